// round 1
// baseline (speedup 1.0000x reference)
#include <cuda_runtime.h>
#include <cuda_bf16.h>
#include <math.h>

// ----------------------------------------------------------------------------
// Problem constants
// ----------------------------------------------------------------------------
#define B   32
#define NK  1024      // keys per batch
#define S   16        // slots
#define D   768
#define H   8
#define DH  64
#define HD  (H*DH)    // 512
#define INNER 3072    // 4*D ... GLU inner
#define N_STEPS 4
static __device__ __constant__ float kSCALE = 0.036084391824351615f;  // 768^-0.5

// ----------------------------------------------------------------------------
// Scratch (device globals; no allocation allowed)
// ----------------------------------------------------------------------------
__device__ float g_xn   [B*NK*D];      // 96 MB
__device__ float g_k    [B*NK*D];      // 96 MB
__device__ float g_v    [B*NK*D];      // 96 MB
__device__ float g_slots[B*S*D];
__device__ float g_qn   [B*S*D];
__device__ float g_q    [B*S*D];
__device__ float g_attn [B*S*NK];      // 2 MB
__device__ float g_sums [B*S];
__device__ float g_upd  [B*S*D];
__device__ float g_h    [B*S*D];
__device__ float g_a    [B*S*D];
__device__ float g_qa   [B*S*HD];
__device__ float g_ka   [B*S*HD];
__device__ float g_va   [B*S*HD];
__device__ float g_oa   [B*S*HD];
__device__ float g_f    [B*S*D];
__device__ float g_ug   [B*S*2*INNER]; // 12 MB
__device__ float g_in   [B*S*INNER];

// ----------------------------------------------------------------------------
// LayerNorm over D=768 (one block per row, 256 threads, 3 elems/thread)
// optional second input added before normalization
// ----------------------------------------------------------------------------
__global__ __launch_bounds__(256)
void ln_kernel(const float* __restrict__ in, const float* __restrict__ add,
               float* __restrict__ out,
               const float* __restrict__ gamma, const float* __restrict__ beta)
{
    int row = blockIdx.x;
    int tid = threadIdx.x;
    const float* x = in + row * D;
    float v0 = x[tid], v1 = x[tid + 256], v2 = x[tid + 512];
    if (add) {
        const float* a = add + row * D;
        v0 += a[tid]; v1 += a[tid + 256]; v2 += a[tid + 512];
    }
    float s = v0 + v1 + v2;
    float q = v0 * v0 + v1 * v1 + v2 * v2;
    __shared__ float sa[8], sb[8];
    #pragma unroll
    for (int o = 16; o > 0; o >>= 1) {
        s += __shfl_down_sync(0xffffffffu, s, o);
        q += __shfl_down_sync(0xffffffffu, q, o);
    }
    int w = tid >> 5, l = tid & 31;
    if (l == 0) { sa[w] = s; sb[w] = q; }
    __syncthreads();
    if (tid == 0) {
        float ts = 0.f, tq = 0.f;
        #pragma unroll
        for (int k = 0; k < 8; k++) { ts += sa[k]; tq += sb[k]; }
        sa[0] = ts; sb[0] = tq;
    }
    __syncthreads();
    float mean = sa[0] * (1.0f / D);
    float var  = sb[0] * (1.0f / D) - mean * mean;
    float r = rsqrtf(var + 1e-5f);
    float* o = out + row * D;
    o[tid]       = (v0 - mean) * r * gamma[tid]       + beta[tid];
    o[tid + 256] = (v1 - mean) * r * gamma[tid + 256] + beta[tid + 256];
    o[tid + 512] = (v2 - mean) * r * gamma[tid + 512] + beta[tid + 512];
}

// ----------------------------------------------------------------------------
// slots init: mu + exp(log_sigma) * noise
// ----------------------------------------------------------------------------
__global__ void init_slots_kernel(const float* __restrict__ noise,
                                  const float* __restrict__ mu,
                                  const float* __restrict__ ls,
                                  float* __restrict__ slots)
{
    int t = blockIdx.x * blockDim.x + threadIdx.x;
    if (t >= B * S * D) return;
    int d = t % D;
    slots[t] = mu[d] + expf(ls[d]) * noise[t];
}

// ----------------------------------------------------------------------------
// Tiled SGEMM: C[M,N] = A[M,K] @ B[K,N] (+ Res). 128x128x8 tile, 256 thr, 8x8.
// All dims must be multiples of (128,128,8). Holds for every GEMM here.
// ----------------------------------------------------------------------------
template <bool HAS_RES>
__global__ __launch_bounds__(256)
void gemm128(const float* __restrict__ A, const float* __restrict__ Bm,
             const float* __restrict__ Res, float* __restrict__ C,
             int M, int N, int K)
{
    __shared__ __align__(16) float As[8][128];
    __shared__ __align__(16) float Bs[8][128];
    int tid  = threadIdx.x;
    int row0 = blockIdx.y * 128, col0 = blockIdx.x * 128;
    int tx = tid & 15, ty = tid >> 4;
    int a_row = tid >> 1, a_kc = (tid & 1) * 4;
    int b_kr  = tid >> 5, b_col = (tid & 31) * 4;
    const float* Ap = A  + (size_t)(row0 + a_row) * K + a_kc;
    const float* Bp = Bm + (size_t)b_kr * N + col0 + b_col;
    float acc[8][8];
    #pragma unroll
    for (int i = 0; i < 8; i++)
        #pragma unroll
        for (int j = 0; j < 8; j++) acc[i][j] = 0.f;

    for (int k0 = 0; k0 < K; k0 += 8) {
        float4 av = *(const float4*)(Ap + k0);
        As[a_kc + 0][a_row] = av.x;
        As[a_kc + 1][a_row] = av.y;
        As[a_kc + 2][a_row] = av.z;
        As[a_kc + 3][a_row] = av.w;
        *(float4*)&Bs[b_kr][b_col] = *(const float4*)(Bp + (size_t)k0 * N);
        __syncthreads();
        #pragma unroll
        for (int kk = 0; kk < 8; kk++) {
            float4 a0 = *(const float4*)&As[kk][ty * 8];
            float4 a1 = *(const float4*)&As[kk][ty * 8 + 4];
            float4 b0 = *(const float4*)&Bs[kk][tx * 8];
            float4 b1 = *(const float4*)&Bs[kk][tx * 8 + 4];
            float ra[8] = {a0.x, a0.y, a0.z, a0.w, a1.x, a1.y, a1.z, a1.w};
            float rb[8] = {b0.x, b0.y, b0.z, b0.w, b1.x, b1.y, b1.z, b1.w};
            #pragma unroll
            for (int i = 0; i < 8; i++)
                #pragma unroll
                for (int j = 0; j < 8; j++)
                    acc[i][j] += ra[i] * rb[j];
        }
        __syncthreads();
    }
    #pragma unroll
    for (int i = 0; i < 8; i++) {
        size_t base = (size_t)(row0 + ty * 8 + i) * N + col0 + tx * 8;
        #pragma unroll
        for (int j = 0; j < 8; j += 4) {
            float4 v = make_float4(acc[i][j], acc[i][j+1], acc[i][j+2], acc[i][j+3]);
            if (HAS_RES) {
                float4 r = *(const float4*)(Res + base + j);
                v.x += r.x; v.y += r.y; v.z += r.z; v.w += r.w;
            }
            *(float4*)(C + base + j) = v;
        }
    }
}

// ----------------------------------------------------------------------------
// dots[b,i,j] = SCALE * dot(q[b,i,:], k[b,j,:])   (16 x 1024 per batch)
// block = (j-tile of 64, b); 256 threads; K tiled by 64
// ----------------------------------------------------------------------------
__global__ __launch_bounds__(256)
void dots_kernel(const float* __restrict__ Q, const float* __restrict__ Kb,
                 float* __restrict__ dots)
{
    int b  = blockIdx.y;
    int j0 = blockIdx.x * 64;
    __shared__ __align__(16) float qs[16][64];
    __shared__ float ks[64][65];
    int tid = threadIdx.x;
    int tx = tid & 63, ty = tid >> 6;
    float acc[4] = {0.f, 0.f, 0.f, 0.f};
    const float* Qb = Q  + (size_t)b * S * D;
    const float* Kp = Kb + ((size_t)b * NK + j0) * D;
    for (int k0 = 0; k0 < D; k0 += 64) {
        {
            int i = tid >> 4, kc = (tid & 15) * 4;
            *(float4*)&qs[i][kc] = *(const float4*)&Qb[(size_t)i * D + k0 + kc];
        }
        #pragma unroll
        for (int p = 0; p < 4; p++) {
            int e = tid + p * 256;
            int jj = e >> 4, kc = (e & 15) * 4;
            float4 v = *(const float4*)&Kp[(size_t)jj * D + k0 + kc];
            ks[jj][kc + 0] = v.x; ks[jj][kc + 1] = v.y;
            ks[jj][kc + 2] = v.z; ks[jj][kc + 3] = v.w;
        }
        __syncthreads();
        #pragma unroll
        for (int kk = 0; kk < 64; kk++) {
            float kv = ks[tx][kk];
            acc[0] += qs[ty     ][kk] * kv;
            acc[1] += qs[ty +  4][kk] * kv;
            acc[2] += qs[ty +  8][kk] * kv;
            acc[3] += qs[ty + 12][kk] * kv;
        }
        __syncthreads();
    }
    #pragma unroll
    for (int r = 0; r < 4; r++)
        dots[((size_t)b * S + ty + r * 4) * NK + j0 + tx] = acc[r] * kSCALE;
}

// softmax over the 16-slot axis for each (b, j); store softmax + EPS
__global__ void softmax_i_kernel(float* __restrict__ attn)
{
    int t = blockIdx.x * blockDim.x + threadIdx.x;  // 32768
    if (t >= B * NK) return;
    int b = t >> 10, j = t & (NK - 1);
    float* p = attn + (size_t)b * S * NK + j;
    float vals[S];
    float m = -1e30f;
    #pragma unroll
    for (int i = 0; i < S; i++) { vals[i] = p[(size_t)i * NK]; m = fmaxf(m, vals[i]); }
    float s = 0.f;
    #pragma unroll
    for (int i = 0; i < S; i++) { vals[i] = expf(vals[i] - m); s += vals[i]; }
    float inv = 1.f / s;
    #pragma unroll
    for (int i = 0; i < S; i++) p[(size_t)i * NK] = vals[i] * inv + 1e-8f;
}

// per-(b,i) sum over j
__global__ __launch_bounds__(256)
void rowsum_kernel(const float* __restrict__ attn, float* __restrict__ sums)
{
    int row = blockIdx.x;            // 512 rows
    const float* p = attn + (size_t)row * NK;
    int tid = threadIdx.x;
    float s = p[tid] + p[tid + 256] + p[tid + 512] + p[tid + 768];
    __shared__ float sa[8];
    #pragma unroll
    for (int o = 16; o > 0; o >>= 1) s += __shfl_down_sync(0xffffffffu, s, o);
    int w = tid >> 5, l = tid & 31;
    if (l == 0) sa[w] = s;
    __syncthreads();
    if (tid == 0) {
        float ts = 0.f;
        #pragma unroll
        for (int k = 0; k < 8; k++) ts += sa[k];
        sums[row] = ts;
    }
}

__global__ void renorm_kernel(float* __restrict__ attn, const float* __restrict__ sums)
{
    int t = blockIdx.x * blockDim.x + threadIdx.x;  // 524288
    if (t >= B * S * NK) return;
    attn[t] = attn[t] / sums[t >> 10];
}

// updates[b,i,n] = sum_j attn[b,i,j] * v[b,j,n]
__global__ __launch_bounds__(256)
void updates_kernel(const float* __restrict__ attn, const float* __restrict__ V,
                    float* __restrict__ upd)
{
    int b  = blockIdx.y;
    int n0 = blockIdx.x * 64;       // 12 tiles over D
    __shared__ __align__(16) float as_[16][64];
    __shared__ __align__(16) float vs[64][64];
    int tid = threadIdx.x;
    int tx = tid & 63, ty = tid >> 6;
    float acc[4] = {0.f, 0.f, 0.f, 0.f};
    for (int j0 = 0; j0 < NK; j0 += 64) {
        {
            int i = tid >> 4, jc = (tid & 15) * 4;
            *(float4*)&as_[i][jc] =
                *(const float4*)&attn[((size_t)b * S + i) * NK + j0 + jc];
        }
        #pragma unroll
        for (int p = 0; p < 4; p++) {
            int e = tid + p * 256;
            int jj = e >> 4, nc = (e & 15) * 4;
            *(float4*)&vs[jj][nc] =
                *(const float4*)&V[((size_t)b * NK + j0 + jj) * D + n0 + nc];
        }
        __syncthreads();
        #pragma unroll
        for (int jj = 0; jj < 64; jj++) {
            float vv = vs[jj][tx];
            acc[0] += as_[ty     ][jj] * vv;
            acc[1] += as_[ty +  4][jj] * vv;
            acc[2] += as_[ty +  8][jj] * vv;
            acc[3] += as_[ty + 12][jj] * vv;
        }
        __syncthreads();
    }
    #pragma unroll
    for (int r = 0; r < 4; r++)
        upd[((size_t)b * S + ty + r * 4) * D + n0 + tx] = acc[r];
}

// ----------------------------------------------------------------------------
// Encoder self-attention over 16 tokens, one block per (b,h)
// ----------------------------------------------------------------------------
__global__ __launch_bounds__(256)
void enc_attn_kernel(const float* __restrict__ Qa, const float* __restrict__ Ka,
                     const float* __restrict__ Va, float* __restrict__ Oa)
{
    int b = blockIdx.x >> 3, h = blockIdx.x & 7;
    __shared__ float qs[16][65], ks[16][65], vs[16][65];
    __shared__ float p[16][17];
    int tid = threadIdx.x;
    int i = tid >> 4, jj = tid & 15;
    {
        int r = tid >> 4, c = (tid & 15) * 4;
        size_t base = ((size_t)b * S + r) * HD + h * DH + c;
        float4 v;
        v = *(const float4*)&Qa[base];
        qs[r][c] = v.x; qs[r][c+1] = v.y; qs[r][c+2] = v.z; qs[r][c+3] = v.w;
        v = *(const float4*)&Ka[base];
        ks[r][c] = v.x; ks[r][c+1] = v.y; ks[r][c+2] = v.z; ks[r][c+3] = v.w;
        v = *(const float4*)&Va[base];
        vs[r][c] = v.x; vs[r][c+1] = v.y; vs[r][c+2] = v.z; vs[r][c+3] = v.w;
    }
    __syncthreads();
    float s = 0.f;
    #pragma unroll
    for (int d = 0; d < DH; d++) s += qs[i][d] * ks[jj][d];
    s *= 0.125f;                      // DH^-0.5
    p[i][jj] = s;
    __syncthreads();
    float m = -1e30f;
    #pragma unroll
    for (int t2 = 0; t2 < 16; t2++) m = fmaxf(m, p[i][t2]);
    __syncthreads();
    float e = expf(s - m);
    p[i][jj] = e;
    __syncthreads();
    float sum = 0.f;
    #pragma unroll
    for (int t2 = 0; t2 < 16; t2++) sum += p[i][t2];
    __syncthreads();
    p[i][jj] = e / sum;
    __syncthreads();
    // o[i][d]: 4 d's per thread
    int io = tid >> 4, dbase = (tid & 15) * 4;
    float o0 = 0.f, o1 = 0.f, o2 = 0.f, o3 = 0.f;
    #pragma unroll
    for (int t2 = 0; t2 < 16; t2++) {
        float pp = p[io][t2];
        o0 += pp * vs[t2][dbase + 0];
        o1 += pp * vs[t2][dbase + 1];
        o2 += pp * vs[t2][dbase + 2];
        o3 += pp * vs[t2][dbase + 3];
    }
    float4 ov = make_float4(o0, o1, o2, o3);
    *(float4*)&Oa[((size_t)b * S + io) * HD + h * DH + dbase] = ov;
}

// GLU: inner[r,c] = u * silu(g), u = ug[r,c], g = ug[r, c+INNER]
__global__ void glu_kernel(const float* __restrict__ ug, float* __restrict__ inner)
{
    int t = blockIdx.x * blockDim.x + threadIdx.x;  // 512*3072
    if (t >= B * S * INNER) return;
    int r = t / INNER, c = t - r * INNER;
    float u = ug[(size_t)r * 2 * INNER + c];
    float g = ug[(size_t)r * 2 * INNER + INNER + c];
    inner[t] = u * (g / (1.f + expf(-g)));
}

// attn_map[b, j, i] = attn[b, i, j]
__global__ void write_attn_kernel(const float* __restrict__ attn, float* __restrict__ out)
{
    int t = blockIdx.x * blockDim.x + threadIdx.x;  // 524288
    if (t >= B * NK * S) return;
    int i = t & 15, j = (t >> 4) & (NK - 1), b = t >> 14;
    out[t] = attn[((size_t)b * S + i) * NK + j];
}

// ----------------------------------------------------------------------------
// Host orchestration
// ----------------------------------------------------------------------------
extern "C" void kernel_launch(void* const* d_in, const int* in_sizes, int n_in,
                              void* d_out, int out_size)
{
    const float* x       = (const float*)d_in[0];
    const float* noise   = (const float*)d_in[1];
    const float* init_mu = (const float*)d_in[2];
    const float* init_ls = (const float*)d_in[3];
    const float* Wk      = (const float*)d_in[4];
    const float* Wv      = (const float*)d_in[5];
    const float* Wq      = (const float*)d_in[6];
    const float* ni_g    = (const float*)d_in[7];
    const float* ni_b    = (const float*)d_in[8];
    const float* ns_g    = (const float*)d_in[9];
    const float* ns_b    = (const float*)d_in[10];
    const float* nica_g  = (const float*)d_in[11];
    const float* nica_b  = (const float*)d_in[12];
    const float* ln1_g   = (const float*)d_in[13];
    const float* ln1_b   = (const float*)d_in[14];
    const float* Wq_a    = (const float*)d_in[15];
    const float* Wk_a    = (const float*)d_in[16];
    const float* Wv_a    = (const float*)d_in[17];
    const float* Wo_a    = (const float*)d_in[18];
    const float* ln2_g   = (const float*)d_in[19];
    const float* ln2_b   = (const float*)d_in[20];
    const float* W1      = (const float*)d_in[21];
    const float* W2      = (const float*)d_in[22];
    const float* lnf_g   = (const float*)d_in[23];
    const float* lnf_b   = (const float*)d_in[24];

    float *xn, *kb, *vb, *slots, *qn, *qb, *attn, *sums, *upd;
    float *hb, *ab, *qa, *ka, *va, *oa, *fb, *ug, *innerb;
    cudaGetSymbolAddress((void**)&xn,    g_xn);
    cudaGetSymbolAddress((void**)&kb,    g_k);
    cudaGetSymbolAddress((void**)&vb,    g_v);
    cudaGetSymbolAddress((void**)&slots, g_slots);
    cudaGetSymbolAddress((void**)&qn,    g_qn);
    cudaGetSymbolAddress((void**)&qb,    g_q);
    cudaGetSymbolAddress((void**)&attn,  g_attn);
    cudaGetSymbolAddress((void**)&sums,  g_sums);
    cudaGetSymbolAddress((void**)&upd,   g_upd);
    cudaGetSymbolAddress((void**)&hb,    g_h);
    cudaGetSymbolAddress((void**)&ab,    g_a);
    cudaGetSymbolAddress((void**)&qa,    g_qa);
    cudaGetSymbolAddress((void**)&ka,    g_ka);
    cudaGetSymbolAddress((void**)&va,    g_va);
    cudaGetSymbolAddress((void**)&oa,    g_oa);
    cudaGetSymbolAddress((void**)&fb,    g_f);
    cudaGetSymbolAddress((void**)&ug,    g_ug);
    cudaGetSymbolAddress((void**)&innerb,g_in);

    // ---- precompute ----
    ln_kernel<<<B * NK, 256>>>(x, nullptr, xn, ni_g, ni_b);
    gemm128<false><<<dim3(D / 128, (B * NK) / 128), 256>>>(xn, Wk, nullptr, kb, B * NK, D, D);
    gemm128<false><<<dim3(D / 128, (B * NK) / 128), 256>>>(xn, Wv, nullptr, vb, B * NK, D, D);
    init_slots_kernel<<<(B * S * D + 255) / 256, 256>>>(noise, init_mu, init_ls, slots);

    // ---- 4 slot-attention steps ----
    for (int it = 0; it < N_STEPS; it++) {
        ln_kernel<<<B * S, 256>>>(slots, nullptr, qn, ns_g, ns_b);
        gemm128<false><<<dim3(D / 128, (B * S) / 128), 256>>>(qn, Wq, nullptr, qb, B * S, D, D);
        dots_kernel<<<dim3(NK / 64, B), 256>>>(qb, kb, attn);
        softmax_i_kernel<<<(B * NK + 255) / 256, 256>>>(attn);
        rowsum_kernel<<<B * S, 256>>>(attn, sums);
        renorm_kernel<<<(B * S * NK + 255) / 256, 256>>>(attn, sums);
        updates_kernel<<<dim3(D / 64, B), 256>>>(attn, vb, upd);
        ln_kernel<<<B * S, 256>>>(slots, upd, hb, nica_g, nica_b);

        // encoder
        ln_kernel<<<B * S, 256>>>(hb, nullptr, ab, ln1_g, ln1_b);
        gemm128<false><<<dim3(HD / 128, (B * S) / 128), 256>>>(ab, Wq_a, nullptr, qa, B * S, HD, D);
        gemm128<false><<<dim3(HD / 128, (B * S) / 128), 256>>>(ab, Wk_a, nullptr, ka, B * S, HD, D);
        gemm128<false><<<dim3(HD / 128, (B * S) / 128), 256>>>(ab, Wv_a, nullptr, va, B * S, HD, D);
        enc_attn_kernel<<<B * H, 256>>>(qa, ka, va, oa);
        gemm128<true><<<dim3(D / 128, (B * S) / 128), 256>>>(oa, Wo_a, hb, hb, B * S, D, HD);
        ln_kernel<<<B * S, 256>>>(hb, nullptr, fb, ln2_g, ln2_b);
        gemm128<false><<<dim3((2 * INNER) / 128, (B * S) / 128), 256>>>(fb, W1, nullptr, ug, B * S, 2 * INNER, D);
        glu_kernel<<<(B * S * INNER + 255) / 256, 256>>>(ug, innerb);
        gemm128<true><<<dim3(D / 128, (B * S) / 128), 256>>>(innerb, W2, hb, hb, B * S, D, INNER);
        ln_kernel<<<B * S, 256>>>(hb, nullptr, slots, lnf_g, lnf_b);
    }

    // ---- outputs: slots [32,16,768], then attn_map [32,1024,16] ----
    float* out = (float*)d_out;
    cudaMemcpyAsync(out, slots, (size_t)B * S * D * sizeof(float),
                    cudaMemcpyDeviceToDevice);
    write_attn_kernel<<<(B * NK * S + 255) / 256, 256>>>(attn, out + (size_t)B * S * D);
}

// round 2
// speedup vs baseline: 1.9575x; 1.9575x over previous
#include <cuda_runtime.h>
#include <cuda_bf16.h>
#include <math.h>

// ----------------------------------------------------------------------------
// Problem constants
// ----------------------------------------------------------------------------
#define B   32
#define NK  1024
#define S   16
#define D   768
#define H   8
#define DH  64
#define HD  (H*DH)    // 512
#define INNER 3072
#define N_STEPS 4
static __device__ __constant__ float kSCALE = 0.036084391824351615f;  // 768^-0.5

// ----------------------------------------------------------------------------
// Scratch (device globals; no allocation allowed)
// ----------------------------------------------------------------------------
__device__ float g_xn   [B*NK*D];
__device__ float g_k    [B*NK*D];
__device__ float g_v    [B*NK*D];
__device__ float g_slots[B*S*D];
__device__ float g_qn   [B*S*D];
__device__ float g_q    [B*S*D];
__device__ float g_attn [B*S*NK];
__device__ float g_upd  [B*S*D];
__device__ float g_h    [B*S*D];
__device__ float g_a    [B*S*D];
__device__ float g_qa   [B*S*HD];
__device__ float g_ka   [B*S*HD];
__device__ float g_va   [B*S*HD];
__device__ float g_oa   [B*S*HD];
__device__ float g_f    [B*S*D];
__device__ float g_ug   [B*S*2*INNER];
__device__ float g_in   [B*S*INNER];
__device__ float g_part [8*512*768];   // split-K partials (max 8 x 512 x 768)

// ----------------------------------------------------------------------------
// FFMA2 helpers (packed fp32x2 — 2x fp32 FMA throughput; ptxas never emits
// this from C++, only via explicit PTX)
// ----------------------------------------------------------------------------
__device__ __forceinline__ void ffma2(unsigned long long &d,
                                      unsigned long long a,
                                      unsigned long long b) {
    asm("fma.rn.f32x2 %0, %1, %2, %0;" : "+l"(d) : "l"(a), "l"(b));
}
__device__ __forceinline__ unsigned long long pack2(float x) {
    unsigned long long r;
    asm("mov.b64 %0, {%1, %1};" : "=l"(r) : "f"(x));
    return r;
}
__device__ __forceinline__ float lo32(unsigned long long v) {
    return __uint_as_float((unsigned)(v & 0xffffffffull));
}
__device__ __forceinline__ float hi32(unsigned long long v) {
    return __uint_as_float((unsigned)(v >> 32));
}

// ----------------------------------------------------------------------------
// LayerNorm over D=768 (one block per row; optional add-before-norm)
// ----------------------------------------------------------------------------
__global__ __launch_bounds__(256)
void ln_kernel(const float* __restrict__ in, const float* __restrict__ add,
               float* __restrict__ out,
               const float* __restrict__ gamma, const float* __restrict__ beta)
{
    int row = blockIdx.x;
    int tid = threadIdx.x;
    const float* x = in + row * D;
    float v0 = x[tid], v1 = x[tid + 256], v2 = x[tid + 512];
    if (add) {
        const float* a = add + row * D;
        v0 += a[tid]; v1 += a[tid + 256]; v2 += a[tid + 512];
    }
    float s = v0 + v1 + v2;
    float q = v0 * v0 + v1 * v1 + v2 * v2;
    __shared__ float sa[8], sb[8];
    #pragma unroll
    for (int o = 16; o > 0; o >>= 1) {
        s += __shfl_down_sync(0xffffffffu, s, o);
        q += __shfl_down_sync(0xffffffffu, q, o);
    }
    int w = tid >> 5, l = tid & 31;
    if (l == 0) { sa[w] = s; sb[w] = q; }
    __syncthreads();
    if (tid == 0) {
        float ts = 0.f, tq = 0.f;
        #pragma unroll
        for (int k = 0; k < 8; k++) { ts += sa[k]; tq += sb[k]; }
        sa[0] = ts; sb[0] = tq;
    }
    __syncthreads();
    float mean = sa[0] * (1.0f / D);
    float var  = sb[0] * (1.0f / D) - mean * mean;
    float r = rsqrtf(var + 1e-5f);
    float* o = out + row * D;
    o[tid]       = (v0 - mean) * r * gamma[tid]       + beta[tid];
    o[tid + 256] = (v1 - mean) * r * gamma[tid + 256] + beta[tid + 256];
    o[tid + 512] = (v2 - mean) * r * gamma[tid + 512] + beta[tid + 512];
}

__global__ void init_slots_kernel(const float* __restrict__ noise,
                                  const float* __restrict__ mu,
                                  const float* __restrict__ ls,
                                  float* __restrict__ slots)
{
    int t = blockIdx.x * blockDim.x + threadIdx.x;
    if (t >= B * S * D) return;
    int d = t % D;
    slots[t] = mu[d] + expf(ls[d]) * noise[t];
}

// ----------------------------------------------------------------------------
// Tiled SGEMM, FFMA2 inner loop, double-buffered smem, split-K via gridDim.z.
// Cout: if gridDim.z>1, per-split partial buffers at z*M*N; else final C.
// M,N multiples of 128; K/gridDim.z multiple of 8.
// ----------------------------------------------------------------------------
template <bool HAS_RES>
__global__ __launch_bounds__(256)
void gemm128(const float* __restrict__ A, const float* __restrict__ Bm,
             const float* __restrict__ Res, float* __restrict__ Cout,
             int M, int N, int K)
{
    __shared__ __align__(16) float As[2][8][128];
    __shared__ __align__(16) float Bs[2][8][128];
    int tid  = threadIdx.x;
    int row0 = blockIdx.y * 128, col0 = blockIdx.x * 128;
    int kb   = K / gridDim.z;
    int kbeg = blockIdx.z * kb;
    float* C = Cout + (size_t)blockIdx.z * M * N;

    int tx = tid & 15, ty = tid >> 4;
    int a_row = tid >> 1, a_kc = (tid & 1) * 4;
    int b_kr  = tid >> 5, b_col = (tid & 31) * 4;
    const float* Ap = A  + (size_t)(row0 + a_row) * K + kbeg + a_kc;
    const float* Bp = Bm + (size_t)(kbeg + b_kr) * N + col0 + b_col;

    unsigned long long acc[8][4];
    #pragma unroll
    for (int i = 0; i < 8; i++)
        #pragma unroll
        for (int p = 0; p < 4; p++) acc[i][p] = 0ull;

    float4 av = *(const float4*)Ap;
    float4 bv = *(const float4*)Bp;
    int buf = 0;
    for (int k0 = 0; k0 < kb; k0 += 8) {
        As[buf][a_kc + 0][a_row] = av.x;
        As[buf][a_kc + 1][a_row] = av.y;
        As[buf][a_kc + 2][a_row] = av.z;
        As[buf][a_kc + 3][a_row] = av.w;
        *(float4*)&Bs[buf][b_kr][b_col] = bv;
        __syncthreads();
        if (k0 + 8 < kb) {
            av = *(const float4*)(Ap + k0 + 8);
            bv = *(const float4*)(Bp + (size_t)(k0 + 8) * N);
        }
        #pragma unroll
        for (int kk = 0; kk < 8; kk++) {
            float4 a0 = *(const float4*)&As[buf][kk][ty * 8];
            float4 a1 = *(const float4*)&As[buf][kk][ty * 8 + 4];
            const unsigned long long* bp =
                (const unsigned long long*)&Bs[buf][kk][tx * 8];
            unsigned long long b0 = bp[0], b1 = bp[1], b2 = bp[2], b3 = bp[3];
            unsigned long long pa[8] = {
                pack2(a0.x), pack2(a0.y), pack2(a0.z), pack2(a0.w),
                pack2(a1.x), pack2(a1.y), pack2(a1.z), pack2(a1.w)};
            #pragma unroll
            for (int i = 0; i < 8; i++) {
                ffma2(acc[i][0], pa[i], b0);
                ffma2(acc[i][1], pa[i], b1);
                ffma2(acc[i][2], pa[i], b2);
                ffma2(acc[i][3], pa[i], b3);
            }
        }
        buf ^= 1;
    }

    #pragma unroll
    for (int i = 0; i < 8; i++) {
        size_t base = (size_t)(row0 + ty * 8 + i) * N + col0 + tx * 8;
        float4 v0 = make_float4(lo32(acc[i][0]), hi32(acc[i][0]),
                                lo32(acc[i][1]), hi32(acc[i][1]));
        float4 v1 = make_float4(lo32(acc[i][2]), hi32(acc[i][2]),
                                lo32(acc[i][3]), hi32(acc[i][3]));
        if (HAS_RES) {
            float4 r0 = *(const float4*)(Res + base);
            float4 r1 = *(const float4*)(Res + base + 4);
            v0.x += r0.x; v0.y += r0.y; v0.z += r0.z; v0.w += r0.w;
            v1.x += r1.x; v1.y += r1.y; v1.z += r1.z; v1.w += r1.w;
        }
        *(float4*)(C + base)     = v0;
        *(float4*)(C + base + 4) = v1;
    }
}

// reduce split-K partials (+ optional residual)
template <bool HAS_RES>
__global__ void reduce_split(const float* __restrict__ part,
                             const float* __restrict__ Res,
                             float* __restrict__ C, int MN, int nsplit)
{
    int t = blockIdx.x * blockDim.x + threadIdx.x;
    if (t * 4 >= MN) return;
    float4 s = ((const float4*)part)[t];
    for (int sp = 1; sp < nsplit; sp++) {
        float4 v = ((const float4*)(part + (size_t)sp * MN))[t];
        s.x += v.x; s.y += v.y; s.z += v.z; s.w += v.w;
    }
    if (HAS_RES) {
        float4 r = ((const float4*)Res)[t];
        s.x += r.x; s.y += r.y; s.z += r.z; s.w += r.w;
    }
    ((float4*)C)[t] = s;
}

// ----------------------------------------------------------------------------
// dots + softmax over the slot axis, fused.
// block = (j-tile of 64, b); thread (tx=j in tile, ty covers 4 slots)
// ----------------------------------------------------------------------------
__global__ __launch_bounds__(256)
void dots_softmax_kernel(const float* __restrict__ Q, const float* __restrict__ Kb,
                         float* __restrict__ attn)
{
    int b  = blockIdx.y;
    int j0 = blockIdx.x * 64;
    __shared__ __align__(16) float qs[16][64];
    __shared__ float ks[64][65];
    __shared__ float red[4][64];
    int tid = threadIdx.x;
    int tx = tid & 63, ty = tid >> 6;
    float acc[4] = {0.f, 0.f, 0.f, 0.f};
    const float* Qb = Q  + (size_t)b * S * D;
    const float* Kp = Kb + ((size_t)b * NK + j0) * D;
    for (int k0 = 0; k0 < D; k0 += 64) {
        {
            int i = tid >> 4, kc = (tid & 15) * 4;
            *(float4*)&qs[i][kc] = *(const float4*)&Qb[(size_t)i * D + k0 + kc];
        }
        #pragma unroll
        for (int p = 0; p < 4; p++) {
            int e = tid + p * 256;
            int jj = e >> 4, kc = (e & 15) * 4;
            float4 v = *(const float4*)&Kp[(size_t)jj * D + k0 + kc];
            ks[jj][kc + 0] = v.x; ks[jj][kc + 1] = v.y;
            ks[jj][kc + 2] = v.z; ks[jj][kc + 3] = v.w;
        }
        __syncthreads();
        #pragma unroll
        for (int kk = 0; kk < 64; kk++) {
            float kv = ks[tx][kk];
            acc[0] += qs[ty     ][kk] * kv;
            acc[1] += qs[ty +  4][kk] * kv;
            acc[2] += qs[ty +  8][kk] * kv;
            acc[3] += qs[ty + 12][kk] * kv;
        }
        __syncthreads();
    }
    #pragma unroll
    for (int r = 0; r < 4; r++) acc[r] *= kSCALE;
    // softmax over the 16 slots of column tx (4 threads x 4 values)
    float m = fmaxf(fmaxf(acc[0], acc[1]), fmaxf(acc[2], acc[3]));
    red[ty][tx] = m;
    __syncthreads();
    float M = fmaxf(fmaxf(red[0][tx], red[1][tx]), fmaxf(red[2][tx], red[3][tx]));
    __syncthreads();
    float e[4]; float s = 0.f;
    #pragma unroll
    for (int r = 0; r < 4; r++) { e[r] = expf(acc[r] - M); s += e[r]; }
    red[ty][tx] = s;
    __syncthreads();
    float Ssum = red[0][tx] + red[1][tx] + red[2][tx] + red[3][tx];
    float inv = 1.f / Ssum;
    #pragma unroll
    for (int r = 0; r < 4; r++)
        attn[((size_t)b * S + ty + r * 4) * NK + j0 + tx] = e[r] * inv + 1e-8f;
}

// sum over keys per (b,i) row and renormalize, in place
__global__ __launch_bounds__(256)
void rowsum_renorm_kernel(float* __restrict__ attn)
{
    int row = blockIdx.x;            // B*S rows of NK
    float4* p = (float4*)(attn + (size_t)row * NK);
    int tid = threadIdx.x;
    float4 v = p[tid];
    float s = v.x + v.y + v.z + v.w;
    __shared__ float sa[8];
    #pragma unroll
    for (int o = 16; o > 0; o >>= 1) s += __shfl_down_sync(0xffffffffu, s, o);
    int w = tid >> 5, l = tid & 31;
    if (l == 0) sa[w] = s;
    __syncthreads();
    if (tid == 0) {
        float ts = 0.f;
        #pragma unroll
        for (int k = 0; k < 8; k++) ts += sa[k];
        sa[0] = ts;
    }
    __syncthreads();
    float inv = 1.f / sa[0];
    v.x *= inv; v.y *= inv; v.z *= inv; v.w *= inv;
    p[tid] = v;
}

// updates[b,i,n] = sum_j attn[b,i,j] * v[b,j,n]
__global__ __launch_bounds__(256)
void updates_kernel(const float* __restrict__ attn, const float* __restrict__ V,
                    float* __restrict__ upd)
{
    int b  = blockIdx.y;
    int n0 = blockIdx.x * 64;
    __shared__ __align__(16) float as_[16][64];
    __shared__ __align__(16) float vs[64][64];
    int tid = threadIdx.x;
    int tx = tid & 63, ty = tid >> 6;
    float acc[4] = {0.f, 0.f, 0.f, 0.f};
    for (int j0 = 0; j0 < NK; j0 += 64) {
        {
            int i = tid >> 4, jc = (tid & 15) * 4;
            *(float4*)&as_[i][jc] =
                *(const float4*)&attn[((size_t)b * S + i) * NK + j0 + jc];
        }
        #pragma unroll
        for (int p = 0; p < 4; p++) {
            int e = tid + p * 256;
            int jj = e >> 4, nc = (e & 15) * 4;
            *(float4*)&vs[jj][nc] =
                *(const float4*)&V[((size_t)b * NK + j0 + jj) * D + n0 + nc];
        }
        __syncthreads();
        #pragma unroll
        for (int jj = 0; jj < 64; jj++) {
            float vv = vs[jj][tx];
            acc[0] += as_[ty     ][jj] * vv;
            acc[1] += as_[ty +  4][jj] * vv;
            acc[2] += as_[ty +  8][jj] * vv;
            acc[3] += as_[ty + 12][jj] * vv;
        }
        __syncthreads();
    }
    #pragma unroll
    for (int r = 0; r < 4; r++)
        upd[((size_t)b * S + ty + r * 4) * D + n0 + tx] = acc[r];
}

// ----------------------------------------------------------------------------
// Encoder self-attention over 16 tokens, one block per (b,h)
// ----------------------------------------------------------------------------
__global__ __launch_bounds__(256)
void enc_attn_kernel(const float* __restrict__ Qa, const float* __restrict__ Ka,
                     const float* __restrict__ Va, float* __restrict__ Oa)
{
    int b = blockIdx.x >> 3, h = blockIdx.x & 7;
    __shared__ float qs[16][65], ks[16][65], vs[16][65];
    __shared__ float p[16][17];
    int tid = threadIdx.x;
    int i = tid >> 4, jj = tid & 15;
    {
        int r = tid >> 4, c = (tid & 15) * 4;
        size_t base = ((size_t)b * S + r) * HD + h * DH + c;
        float4 v;
        v = *(const float4*)&Qa[base];
        qs[r][c] = v.x; qs[r][c+1] = v.y; qs[r][c+2] = v.z; qs[r][c+3] = v.w;
        v = *(const float4*)&Ka[base];
        ks[r][c] = v.x; ks[r][c+1] = v.y; ks[r][c+2] = v.z; ks[r][c+3] = v.w;
        v = *(const float4*)&Va[base];
        vs[r][c] = v.x; vs[r][c+1] = v.y; vs[r][c+2] = v.z; vs[r][c+3] = v.w;
    }
    __syncthreads();
    float s = 0.f;
    #pragma unroll
    for (int d = 0; d < DH; d++) s += qs[i][d] * ks[jj][d];
    s *= 0.125f;
    p[i][jj] = s;
    __syncthreads();
    float m = -1e30f;
    #pragma unroll
    for (int t2 = 0; t2 < 16; t2++) m = fmaxf(m, p[i][t2]);
    __syncthreads();
    float e = expf(s - m);
    p[i][jj] = e;
    __syncthreads();
    float sum = 0.f;
    #pragma unroll
    for (int t2 = 0; t2 < 16; t2++) sum += p[i][t2];
    __syncthreads();
    p[i][jj] = e / sum;
    __syncthreads();
    int io = tid >> 4, dbase = (tid & 15) * 4;
    float o0 = 0.f, o1 = 0.f, o2 = 0.f, o3 = 0.f;
    #pragma unroll
    for (int t2 = 0; t2 < 16; t2++) {
        float pp = p[io][t2];
        o0 += pp * vs[t2][dbase + 0];
        o1 += pp * vs[t2][dbase + 1];
        o2 += pp * vs[t2][dbase + 2];
        o3 += pp * vs[t2][dbase + 3];
    }
    float4 ov = make_float4(o0, o1, o2, o3);
    *(float4*)&Oa[((size_t)b * S + io) * HD + h * DH + dbase] = ov;
}

__global__ void glu_kernel(const float* __restrict__ ug, float* __restrict__ inner)
{
    int t = blockIdx.x * blockDim.x + threadIdx.x;
    if (t >= B * S * INNER) return;
    int r = t / INNER, c = t - r * INNER;
    float u = ug[(size_t)r * 2 * INNER + c];
    float g = ug[(size_t)r * 2 * INNER + INNER + c];
    inner[t] = u * (g / (1.f + expf(-g)));
}

__global__ void write_attn_kernel(const float* __restrict__ attn, float* __restrict__ out)
{
    int t = blockIdx.x * blockDim.x + threadIdx.x;
    if (t >= B * NK * S) return;
    int i = t & 15, j = (t >> 4) & (NK - 1), b = t >> 14;
    out[t] = attn[((size_t)b * S + i) * NK + j];
}

// ----------------------------------------------------------------------------
// Host orchestration
// ----------------------------------------------------------------------------
extern "C" void kernel_launch(void* const* d_in, const int* in_sizes, int n_in,
                              void* d_out, int out_size)
{
    const float* x       = (const float*)d_in[0];
    const float* noise   = (const float*)d_in[1];
    const float* init_mu = (const float*)d_in[2];
    const float* init_ls = (const float*)d_in[3];
    const float* Wk      = (const float*)d_in[4];
    const float* Wv      = (const float*)d_in[5];
    const float* Wq      = (const float*)d_in[6];
    const float* ni_g    = (const float*)d_in[7];
    const float* ni_b    = (const float*)d_in[8];
    const float* ns_g    = (const float*)d_in[9];
    const float* ns_b    = (const float*)d_in[10];
    const float* nica_g  = (const float*)d_in[11];
    const float* nica_b  = (const float*)d_in[12];
    const float* ln1_g   = (const float*)d_in[13];
    const float* ln1_b   = (const float*)d_in[14];
    const float* Wq_a    = (const float*)d_in[15];
    const float* Wk_a    = (const float*)d_in[16];
    const float* Wv_a    = (const float*)d_in[17];
    const float* Wo_a    = (const float*)d_in[18];
    const float* ln2_g   = (const float*)d_in[19];
    const float* ln2_b   = (const float*)d_in[20];
    const float* W1      = (const float*)d_in[21];
    const float* W2      = (const float*)d_in[22];
    const float* lnf_g   = (const float*)d_in[23];
    const float* lnf_b   = (const float*)d_in[24];

    float *xn, *kb, *vb, *slots, *qn, *qb, *attn, *upd;
    float *hb, *ab, *qa, *ka, *va, *oa, *fb, *ug, *innerb, *part;
    cudaGetSymbolAddress((void**)&xn,    g_xn);
    cudaGetSymbolAddress((void**)&kb,    g_k);
    cudaGetSymbolAddress((void**)&vb,    g_v);
    cudaGetSymbolAddress((void**)&slots, g_slots);
    cudaGetSymbolAddress((void**)&qn,    g_qn);
    cudaGetSymbolAddress((void**)&qb,    g_q);
    cudaGetSymbolAddress((void**)&attn,  g_attn);
    cudaGetSymbolAddress((void**)&upd,   g_upd);
    cudaGetSymbolAddress((void**)&hb,    g_h);
    cudaGetSymbolAddress((void**)&ab,    g_a);
    cudaGetSymbolAddress((void**)&qa,    g_qa);
    cudaGetSymbolAddress((void**)&ka,    g_ka);
    cudaGetSymbolAddress((void**)&va,    g_va);
    cudaGetSymbolAddress((void**)&oa,    g_oa);
    cudaGetSymbolAddress((void**)&fb,    g_f);
    cudaGetSymbolAddress((void**)&ug,    g_ug);
    cudaGetSymbolAddress((void**)&innerb,g_in);
    cudaGetSymbolAddress((void**)&part,  g_part);

    const int MS = B * S;            // 512

    // ---- precompute ----
    ln_kernel<<<B * NK, 256>>>(x, nullptr, xn, ni_g, ni_b);
    gemm128<false><<<dim3(D / 128, (B * NK) / 128, 1), 256>>>(xn, Wk, nullptr, kb, B * NK, D, D);
    gemm128<false><<<dim3(D / 128, (B * NK) / 128, 1), 256>>>(xn, Wv, nullptr, vb, B * NK, D, D);
    init_slots_kernel<<<(MS * D + 255) / 256, 256>>>(noise, init_mu, init_ls, slots);

    // ---- 4 slot-attention steps ----
    for (int it = 0; it < N_STEPS; it++) {
        ln_kernel<<<MS, 256>>>(slots, nullptr, qn, ns_g, ns_b);
        // q = qn @ Wq  (split-K 8)
        gemm128<false><<<dim3(D / 128, MS / 128, 8), 256>>>(qn, Wq, nullptr, part, MS, D, D);
        reduce_split<false><<<(MS * D / 4 + 255) / 256, 256>>>(part, nullptr, qb, MS * D, 8);

        dots_softmax_kernel<<<dim3(NK / 64, B), 256>>>(qb, kb, attn);
        rowsum_renorm_kernel<<<MS, 256>>>(attn);
        updates_kernel<<<dim3(D / 64, B), 256>>>(attn, vb, upd);
        ln_kernel<<<MS, 256>>>(slots, upd, hb, nica_g, nica_b);

        // encoder
        ln_kernel<<<MS, 256>>>(hb, nullptr, ab, ln1_g, ln1_b);
        gemm128<false><<<dim3(HD / 128, MS / 128, 8), 256>>>(ab, Wq_a, nullptr, part, MS, HD, D);
        reduce_split<false><<<(MS * HD / 4 + 255) / 256, 256>>>(part, nullptr, qa, MS * HD, 8);
        gemm128<false><<<dim3(HD / 128, MS / 128, 8), 256>>>(ab, Wk_a, nullptr, part, MS, HD, D);
        reduce_split<false><<<(MS * HD / 4 + 255) / 256, 256>>>(part, nullptr, ka, MS * HD, 8);
        gemm128<false><<<dim3(HD / 128, MS / 128, 8), 256>>>(ab, Wv_a, nullptr, part, MS, HD, D);
        reduce_split<false><<<(MS * HD / 4 + 255) / 256, 256>>>(part, nullptr, va, MS * HD, 8);
        enc_attn_kernel<<<B * H, 256>>>(qa, ka, va, oa);
        // h += oa @ Wo  (split-K 8, residual in reduce)
        gemm128<false><<<dim3(D / 128, MS / 128, 8), 256>>>(oa, Wo_a, nullptr, part, MS, D, HD);
        reduce_split<true><<<(MS * D / 4 + 255) / 256, 256>>>(part, hb, hb, MS * D, 8);
        ln_kernel<<<MS, 256>>>(hb, nullptr, fb, ln2_g, ln2_b);
        // ug = f @ W1 (192 blocks already; no split)
        gemm128<false><<<dim3((2 * INNER) / 128, MS / 128, 1), 256>>>(fb, W1, nullptr, ug, MS, 2 * INNER, D);
        glu_kernel<<<(MS * INNER + 255) / 256, 256>>>(ug, innerb);
        // h += inner @ W2 (split-K 8)
        gemm128<false><<<dim3(D / 128, MS / 128, 8), 256>>>(innerb, W2, nullptr, part, MS, D, INNER);
        reduce_split<true><<<(MS * D / 4 + 255) / 256, 256>>>(part, hb, hb, MS * D, 8);
        ln_kernel<<<MS, 256>>>(hb, nullptr, slots, lnf_g, lnf_b);
    }

    // ---- outputs: slots [32,16,768], then attn_map [32,1024,16] ----
    float* out = (float*)d_out;
    cudaMemcpyAsync(out, slots, (size_t)MS * D * sizeof(float),
                    cudaMemcpyDeviceToDevice);
    write_attn_kernel<<<(B * NK * S + 255) / 256, 256>>>(attn, out + (size_t)MS * D);
}

// round 4
// speedup vs baseline: 3.1380x; 1.6031x over previous
#include <cuda_runtime.h>
#include <cuda_fp16.h>
#include <math.h>
#include <stdint.h>

// ----------------------------------------------------------------------------
// Problem constants
// ----------------------------------------------------------------------------
#define B   32
#define NK  1024
#define S   16
#define D   768
#define H   8
#define DH  64
#define HD  (H*DH)    // 512
#define INNER 3072
#define N_STEPS 4
static __device__ __constant__ float kSCALE = 0.036084391824351615f;  // 768^-0.5

// ----------------------------------------------------------------------------
// Scratch (device globals; no allocation allowed)
// ----------------------------------------------------------------------------
__device__ __half g_xnh[B*NK*D];            // LN(x) hi
__device__ __half g_xnl[B*NK*D];            // LN(x) lo
__device__ __half g_wkh[D*D],  g_wkl[D*D];  // Wk^T hi/lo  [n][k]
__device__ __half g_wvh[D*D],  g_wvl[D*D];  // Wv^T hi/lo
__device__ __half g_w1h[2*INNER*D], g_w1l[2*INNER*D];  // W1^T hi/lo [6144][768]
__device__ __half g_fbh[B*S*D], g_fbl[B*S*D];          // ln2 out hi/lo
__device__ float g_k    [B*NK*D];
__device__ float g_v    [B*NK*D];
__device__ float g_slots[B*S*D];
__device__ float g_qn   [B*S*D];
__device__ float g_q    [B*S*D];
__device__ float g_attn [B*S*NK];
__device__ float g_upd  [B*S*D];
__device__ float g_h    [B*S*D];
__device__ float g_a    [B*S*D];
__device__ float g_qa   [B*S*HD];
__device__ float g_ka   [B*S*HD];
__device__ float g_va   [B*S*HD];
__device__ float g_oa   [B*S*HD];
__device__ float g_ug   [B*S*2*INNER];
__device__ float g_in   [B*S*INNER];
__device__ float g_part [8*512*768];

// ----------------------------------------------------------------------------
// FFMA2 helpers (packed fp32x2)
// ----------------------------------------------------------------------------
__device__ __forceinline__ void ffma2(unsigned long long &d,
                                      unsigned long long a,
                                      unsigned long long b) {
    asm("fma.rn.f32x2 %0, %1, %2, %0;" : "+l"(d) : "l"(a), "l"(b));
}
__device__ __forceinline__ unsigned long long pack2(float x) {
    unsigned long long r;
    asm("mov.b64 %0, {%1, %1};" : "=l"(r) : "f"(x));
    return r;
}
__device__ __forceinline__ float lo32(unsigned long long v) {
    return __uint_as_float((unsigned)(v & 0xffffffffull));
}
__device__ __forceinline__ float hi32(unsigned long long v) {
    return __uint_as_float((unsigned)(v >> 32));
}

// ----------------------------------------------------------------------------
// HMMA helpers (baseline PTX — works on plain compute_103 target)
// ----------------------------------------------------------------------------
__device__ __forceinline__ uint32_t smem_u32(const void* p) {
    uint32_t a;
    asm("{ .reg .u64 t; cvta.to.shared.u64 t, %1; cvt.u32.u64 %0, t; }"
        : "=r"(a) : "l"(p));
    return a;
}
#define LDSM_X4(r0, r1, r2, r3, addr) \
    asm volatile("ldmatrix.sync.aligned.m8n8.x4.shared.b16 {%0,%1,%2,%3}, [%4];" \
                 : "=r"(r0), "=r"(r1), "=r"(r2), "=r"(r3) : "r"(addr))
#define LDSM_X2(r0, r1, addr) \
    asm volatile("ldmatrix.sync.aligned.m8n8.x2.shared.b16 {%0,%1}, [%2];" \
                 : "=r"(r0), "=r"(r1) : "r"(addr))
#define MMA16816(c, a, b) \
    asm volatile("mma.sync.aligned.m16n8k16.row.col.f32.f16.f16.f32 " \
                 "{%0,%1,%2,%3}, {%4,%5,%6,%7}, {%8,%9}, {%0,%1,%2,%3};" \
                 : "+f"((c)[0]), "+f"((c)[1]), "+f"((c)[2]), "+f"((c)[3]) \
                 : "r"((a)[0]), "r"((a)[1]), "r"((a)[2]), "r"((a)[3]), \
                   "r"((b)[0]), "r"((b)[1]))

// ----------------------------------------------------------------------------
// fp16 hi/lo HMMA GEMM: C[M,N] = A[M,K] @ Bt^T, Bt given as [N][K] (K-major).
// 128x128 CTA tile, BK=32, 8 warps (2x4), warp tile 64x32 of m16n8k16 frags.
// C = Ah*Bh + Ah*Bl + Al*Bh  (fp32 accum; error ~2^-22)
// ----------------------------------------------------------------------------
#define PITCH 40   // halves per smem row (80 B) — conflict-free ldmatrix
__global__ __launch_bounds__(256)
void hgemm_hilo(const __half* __restrict__ Ah, const __half* __restrict__ Al,
                const __half* __restrict__ Bth, const __half* __restrict__ Btl,
                float* __restrict__ C, int M, int N, int K)
{
    __shared__ __align__(16) __half sAh[128 * PITCH], sAl[128 * PITCH];
    __shared__ __align__(16) __half sBh[128 * PITCH], sBl[128 * PITCH];
    int tid = threadIdx.x;
    int lane = tid & 31, wid = tid >> 5;
    int wm = wid >> 2, wn = wid & 3;       // warp grid 2 (m) x 4 (n)
    int row0 = blockIdx.y * 128, col0 = blockIdx.x * 128;

    uint32_t bAh = smem_u32(sAh), bAl = smem_u32(sAl);
    uint32_t bBh = smem_u32(sBh), bBl = smem_u32(sBl);

    float acc[4][4][4];
    #pragma unroll
    for (int mf = 0; mf < 4; mf++)
        #pragma unroll
        for (int nf = 0; nf < 4; nf++)
            #pragma unroll
            for (int e = 0; e < 4; e++) acc[mf][nf][e] = 0.f;

    int laneAr = lane & 15, laneAk = (lane & 16) ? 8 : 0;
    int laneBr = lane & 7,  laneBk = (lane & 8)  ? 8 : 0;

    for (int kc = 0; kc < K; kc += 32) {
        #pragma unroll
        for (int i = 0; i < 2; i++) {
            int idx = tid + i * 256;       // 0..511
            int row = idx >> 2, seg = idx & 3;
            size_t ga = (size_t)(row0 + row) * K + kc + seg * 8;
            size_t gb = (size_t)(col0 + row) * K + kc + seg * 8;
            int so = row * PITCH + seg * 8;
            *(uint4*)(sAh + so) = *(const uint4*)(Ah + ga);
            *(uint4*)(sAl + so) = *(const uint4*)(Al + ga);
            *(uint4*)(sBh + so) = *(const uint4*)(Bth + gb);
            *(uint4*)(sBl + so) = *(const uint4*)(Btl + gb);
        }
        __syncthreads();
        #pragma unroll
        for (int ks = 0; ks < 32; ks += 16) {
            uint32_t bh[4][2], bl[4][2];
            #pragma unroll
            for (int nf = 0; nf < 4; nf++) {
                uint32_t off = (uint32_t)((wn * 32 + nf * 8 + laneBr) * PITCH
                                          + ks + laneBk) * 2;
                LDSM_X2(bh[nf][0], bh[nf][1], bBh + off);
                LDSM_X2(bl[nf][0], bl[nf][1], bBl + off);
            }
            #pragma unroll
            for (int mf = 0; mf < 4; mf++) {
                uint32_t off = (uint32_t)((wm * 64 + mf * 16 + laneAr) * PITCH
                                          + ks + laneAk) * 2;
                uint32_t ah[4], al[4];
                LDSM_X4(ah[0], ah[1], ah[2], ah[3], bAh + off);
                LDSM_X4(al[0], al[1], al[2], al[3], bAl + off);
                #pragma unroll
                for (int nf = 0; nf < 4; nf++) {
                    MMA16816(acc[mf][nf], ah, bh[nf]);
                    MMA16816(acc[mf][nf], ah, bl[nf]);
                    MMA16816(acc[mf][nf], al, bh[nf]);
                }
            }
        }
        __syncthreads();
    }
    #pragma unroll
    for (int mf = 0; mf < 4; mf++) {
        int r = row0 + wm * 64 + mf * 16 + (lane >> 2);
        #pragma unroll
        for (int nf = 0; nf < 4; nf++) {
            int c = col0 + wn * 32 + nf * 8 + (lane & 3) * 2;
            *(float2*)(C + (size_t)r * N + c) =
                make_float2(acc[mf][nf][0], acc[mf][nf][1]);
            *(float2*)(C + (size_t)(r + 8) * N + c) =
                make_float2(acc[mf][nf][2], acc[mf][nf][3]);
        }
    }
}

// ----------------------------------------------------------------------------
// LN over D=768 emitting fp16 hi/lo
// ----------------------------------------------------------------------------
__global__ __launch_bounds__(256)
void ln_split_kernel(const float* __restrict__ in,
                     __half* __restrict__ oh, __half* __restrict__ ol,
                     const float* __restrict__ gamma, const float* __restrict__ beta)
{
    int row = blockIdx.x;
    int tid = threadIdx.x;
    const float* x = in + (size_t)row * D;
    float v0 = x[tid], v1 = x[tid + 256], v2 = x[tid + 512];
    float s = v0 + v1 + v2;
    float q = v0 * v0 + v1 * v1 + v2 * v2;
    __shared__ float sa[8], sb2[8];
    #pragma unroll
    for (int o = 16; o > 0; o >>= 1) {
        s += __shfl_down_sync(0xffffffffu, s, o);
        q += __shfl_down_sync(0xffffffffu, q, o);
    }
    int w = tid >> 5, l = tid & 31;
    if (l == 0) { sa[w] = s; sb2[w] = q; }
    __syncthreads();
    if (tid == 0) {
        float ts = 0.f, tq = 0.f;
        #pragma unroll
        for (int k = 0; k < 8; k++) { ts += sa[k]; tq += sb2[k]; }
        sa[0] = ts; sb2[0] = tq;
    }
    __syncthreads();
    float mean = sa[0] * (1.0f / D);
    float var  = sb2[0] * (1.0f / D) - mean * mean;
    float r = rsqrtf(var + 1e-5f);
    #pragma unroll
    for (int e = 0; e < 3; e++) {
        int idx = tid + e * 256;
        float val = (e == 0 ? v0 : (e == 1 ? v1 : v2));
        float y = (val - mean) * r * gamma[idx] + beta[idx];
        __half hb = __float2half_rn(y);
        __half lb = __float2half_rn(y - __half2float(hb));
        oh[(size_t)row * D + idx] = hb;
        ol[(size_t)row * D + idx] = lb;
    }
}

// transpose + fp16 hi/lo split: W[768, Ncols] -> T[n][k], T stride = 768
__global__ __launch_bounds__(256)
void wsplit_kernel(const float* __restrict__ W,
                   __half* __restrict__ Th, __half* __restrict__ Tl, int Ncols)
{
    __shared__ float tile[32][33];
    int n0 = blockIdx.x * 32, k0 = blockIdx.y * 32;
    int t = threadIdx.x;
    int tx = t & 31, ty = t >> 5;
    #pragma unroll
    for (int i = 0; i < 4; i++)
        tile[ty + i * 8][tx] = W[(size_t)(k0 + ty + i * 8) * Ncols + n0 + tx];
    __syncthreads();
    #pragma unroll
    for (int i = 0; i < 4; i++) {
        int n = n0 + ty + i * 8;
        float v = tile[tx][ty + i * 8];
        __half hb = __float2half_rn(v);
        __half lb = __float2half_rn(v - __half2float(hb));
        Th[(size_t)n * D + k0 + tx] = hb;
        Tl[(size_t)n * D + k0 + tx] = lb;
    }
}

// ----------------------------------------------------------------------------
// LayerNorm over D=768 (fp32 out; optional add-before-norm)
// ----------------------------------------------------------------------------
__global__ __launch_bounds__(256)
void ln_kernel(const float* __restrict__ in, const float* __restrict__ add,
               float* __restrict__ out,
               const float* __restrict__ gamma, const float* __restrict__ beta)
{
    int row = blockIdx.x;
    int tid = threadIdx.x;
    const float* x = in + (size_t)row * D;
    float v0 = x[tid], v1 = x[tid + 256], v2 = x[tid + 512];
    if (add) {
        const float* a = add + (size_t)row * D;
        v0 += a[tid]; v1 += a[tid + 256]; v2 += a[tid + 512];
    }
    float s = v0 + v1 + v2;
    float q = v0 * v0 + v1 * v1 + v2 * v2;
    __shared__ float sa[8], sb2[8];
    #pragma unroll
    for (int o = 16; o > 0; o >>= 1) {
        s += __shfl_down_sync(0xffffffffu, s, o);
        q += __shfl_down_sync(0xffffffffu, q, o);
    }
    int w = tid >> 5, l = tid & 31;
    if (l == 0) { sa[w] = s; sb2[w] = q; }
    __syncthreads();
    if (tid == 0) {
        float ts = 0.f, tq = 0.f;
        #pragma unroll
        for (int k = 0; k < 8; k++) { ts += sa[k]; tq += sb2[k]; }
        sa[0] = ts; sb2[0] = tq;
    }
    __syncthreads();
    float mean = sa[0] * (1.0f / D);
    float var  = sb2[0] * (1.0f / D) - mean * mean;
    float r = rsqrtf(var + 1e-5f);
    float* o = out + (size_t)row * D;
    o[tid]       = (v0 - mean) * r * gamma[tid]       + beta[tid];
    o[tid + 256] = (v1 - mean) * r * gamma[tid + 256] + beta[tid + 256];
    o[tid + 512] = (v2 - mean) * r * gamma[tid + 512] + beta[tid + 512];
}

__global__ void init_slots_kernel(const float* __restrict__ noise,
                                  const float* __restrict__ mu,
                                  const float* __restrict__ ls,
                                  float* __restrict__ slots)
{
    int t = blockIdx.x * blockDim.x + threadIdx.x;
    if (t >= B * S * D) return;
    int d = t % D;
    slots[t] = mu[d] + expf(ls[d]) * noise[t];
}

// ----------------------------------------------------------------------------
// FFMA2 SGEMM (split-K via gridDim.z) — remaining small GEMMs
// ----------------------------------------------------------------------------
template <bool HAS_RES>
__global__ __launch_bounds__(256)
void gemm128(const float* __restrict__ A, const float* __restrict__ Bm,
             const float* __restrict__ Res, float* __restrict__ Cout,
             int M, int N, int K)
{
    __shared__ __align__(16) float As[2][8][128];
    __shared__ __align__(16) float Bs[2][8][128];
    int tid  = threadIdx.x;
    int row0 = blockIdx.y * 128, col0 = blockIdx.x * 128;
    int kb   = K / gridDim.z;
    int kbeg = blockIdx.z * kb;
    float* C = Cout + (size_t)blockIdx.z * M * N;

    int tx = tid & 15, ty = tid >> 4;
    int a_row = tid >> 1, a_kc = (tid & 1) * 4;
    int b_kr  = tid >> 5, b_col = (tid & 31) * 4;
    const float* Ap = A  + (size_t)(row0 + a_row) * K + kbeg + a_kc;
    const float* Bp = Bm + (size_t)(kbeg + b_kr) * N + col0 + b_col;

    unsigned long long acc[8][4];
    #pragma unroll
    for (int i = 0; i < 8; i++)
        #pragma unroll
        for (int p = 0; p < 4; p++) acc[i][p] = 0ull;

    float4 av = *(const float4*)Ap;
    float4 bv = *(const float4*)Bp;
    int buf = 0;
    for (int k0 = 0; k0 < kb; k0 += 8) {
        As[buf][a_kc + 0][a_row] = av.x;
        As[buf][a_kc + 1][a_row] = av.y;
        As[buf][a_kc + 2][a_row] = av.z;
        As[buf][a_kc + 3][a_row] = av.w;
        *(float4*)&Bs[buf][b_kr][b_col] = bv;
        __syncthreads();
        if (k0 + 8 < kb) {
            av = *(const float4*)(Ap + k0 + 8);
            bv = *(const float4*)(Bp + (size_t)(k0 + 8) * N);
        }
        #pragma unroll
        for (int kk = 0; kk < 8; kk++) {
            float4 a0 = *(const float4*)&As[buf][kk][ty * 8];
            float4 a1 = *(const float4*)&As[buf][kk][ty * 8 + 4];
            const unsigned long long* bp =
                (const unsigned long long*)&Bs[buf][kk][tx * 8];
            unsigned long long b0 = bp[0], b1 = bp[1], b2 = bp[2], b3 = bp[3];
            unsigned long long pa[8] = {
                pack2(a0.x), pack2(a0.y), pack2(a0.z), pack2(a0.w),
                pack2(a1.x), pack2(a1.y), pack2(a1.z), pack2(a1.w)};
            #pragma unroll
            for (int i = 0; i < 8; i++) {
                ffma2(acc[i][0], pa[i], b0);
                ffma2(acc[i][1], pa[i], b1);
                ffma2(acc[i][2], pa[i], b2);
                ffma2(acc[i][3], pa[i], b3);
            }
        }
        buf ^= 1;
    }

    #pragma unroll
    for (int i = 0; i < 8; i++) {
        size_t base = (size_t)(row0 + ty * 8 + i) * N + col0 + tx * 8;
        float4 v0 = make_float4(lo32(acc[i][0]), hi32(acc[i][0]),
                                lo32(acc[i][1]), hi32(acc[i][1]));
        float4 v1 = make_float4(lo32(acc[i][2]), hi32(acc[i][2]),
                                lo32(acc[i][3]), hi32(acc[i][3]));
        if (HAS_RES) {
            float4 r0 = *(const float4*)(Res + base);
            float4 r1 = *(const float4*)(Res + base + 4);
            v0.x += r0.x; v0.y += r0.y; v0.z += r0.z; v0.w += r0.w;
            v1.x += r1.x; v1.y += r1.y; v1.z += r1.z; v1.w += r1.w;
        }
        *(float4*)(C + base)     = v0;
        *(float4*)(C + base + 4) = v1;
    }
}

template <bool HAS_RES>
__global__ void reduce_split(const float* __restrict__ part,
                             const float* __restrict__ Res,
                             float* __restrict__ C, int MN, int nsplit)
{
    int t = blockIdx.x * blockDim.x + threadIdx.x;
    if (t * 4 >= MN) return;
    float4 s = ((const float4*)part)[t];
    for (int sp = 1; sp < nsplit; sp++) {
        float4 v = ((const float4*)(part + (size_t)sp * MN))[t];
        s.x += v.x; s.y += v.y; s.z += v.z; s.w += v.w;
    }
    if (HAS_RES) {
        float4 r = ((const float4*)Res)[t];
        s.x += r.x; s.y += r.y; s.z += r.z; s.w += r.w;
    }
    ((float4*)C)[t] = s;
}

// ----------------------------------------------------------------------------
// dots + softmax over the slot axis, fused
// ----------------------------------------------------------------------------
__global__ __launch_bounds__(256)
void dots_softmax_kernel(const float* __restrict__ Q, const float* __restrict__ Kb,
                         float* __restrict__ attn)
{
    int b  = blockIdx.y;
    int j0 = blockIdx.x * 64;
    __shared__ __align__(16) float qs[16][64];
    __shared__ float ks[64][65];
    __shared__ float red[4][64];
    int tid = threadIdx.x;
    int tx = tid & 63, ty = tid >> 6;
    float acc[4] = {0.f, 0.f, 0.f, 0.f};
    const float* Qb = Q  + (size_t)b * S * D;
    const float* Kp = Kb + ((size_t)b * NK + j0) * D;
    for (int k0 = 0; k0 < D; k0 += 64) {
        {
            int i = tid >> 4, kc = (tid & 15) * 4;
            *(float4*)&qs[i][kc] = *(const float4*)&Qb[(size_t)i * D + k0 + kc];
        }
        #pragma unroll
        for (int p = 0; p < 4; p++) {
            int e = tid + p * 256;
            int jj = e >> 4, kc = (e & 15) * 4;
            float4 v = *(const float4*)&Kp[(size_t)jj * D + k0 + kc];
            ks[jj][kc + 0] = v.x; ks[jj][kc + 1] = v.y;
            ks[jj][kc + 2] = v.z; ks[jj][kc + 3] = v.w;
        }
        __syncthreads();
        #pragma unroll
        for (int kk = 0; kk < 64; kk++) {
            float kv = ks[tx][kk];
            acc[0] += qs[ty     ][kk] * kv;
            acc[1] += qs[ty +  4][kk] * kv;
            acc[2] += qs[ty +  8][kk] * kv;
            acc[3] += qs[ty + 12][kk] * kv;
        }
        __syncthreads();
    }
    #pragma unroll
    for (int r = 0; r < 4; r++) acc[r] *= kSCALE;
    float m = fmaxf(fmaxf(acc[0], acc[1]), fmaxf(acc[2], acc[3]));
    red[ty][tx] = m;
    __syncthreads();
    float M = fmaxf(fmaxf(red[0][tx], red[1][tx]), fmaxf(red[2][tx], red[3][tx]));
    __syncthreads();
    float e[4]; float s = 0.f;
    #pragma unroll
    for (int r = 0; r < 4; r++) { e[r] = expf(acc[r] - M); s += e[r]; }
    red[ty][tx] = s;
    __syncthreads();
    float Ssum = red[0][tx] + red[1][tx] + red[2][tx] + red[3][tx];
    float inv = 1.f / Ssum;
    #pragma unroll
    for (int r = 0; r < 4; r++)
        attn[((size_t)b * S + ty + r * 4) * NK + j0 + tx] = e[r] * inv + 1e-8f;
}

__global__ __launch_bounds__(256)
void rowsum_renorm_kernel(float* __restrict__ attn)
{
    int row = blockIdx.x;
    float4* p = (float4*)(attn + (size_t)row * NK);
    int tid = threadIdx.x;
    float4 v = p[tid];
    float s = v.x + v.y + v.z + v.w;
    __shared__ float sa[8];
    #pragma unroll
    for (int o = 16; o > 0; o >>= 1) s += __shfl_down_sync(0xffffffffu, s, o);
    int w = tid >> 5, l = tid & 31;
    if (l == 0) sa[w] = s;
    __syncthreads();
    if (tid == 0) {
        float ts = 0.f;
        #pragma unroll
        for (int k = 0; k < 8; k++) ts += sa[k];
        sa[0] = ts;
    }
    __syncthreads();
    float inv = 1.f / sa[0];
    v.x *= inv; v.y *= inv; v.z *= inv; v.w *= inv;
    p[tid] = v;
}

__global__ __launch_bounds__(256)
void updates_kernel(const float* __restrict__ attn, const float* __restrict__ V,
                    float* __restrict__ upd)
{
    int b  = blockIdx.y;
    int n0 = blockIdx.x * 64;
    __shared__ __align__(16) float as_[16][64];
    __shared__ __align__(16) float vs[64][64];
    int tid = threadIdx.x;
    int tx = tid & 63, ty = tid >> 6;
    float acc[4] = {0.f, 0.f, 0.f, 0.f};
    for (int j0 = 0; j0 < NK; j0 += 64) {
        {
            int i = tid >> 4, jc = (tid & 15) * 4;
            *(float4*)&as_[i][jc] =
                *(const float4*)&attn[((size_t)b * S + i) * NK + j0 + jc];
        }
        #pragma unroll
        for (int p = 0; p < 4; p++) {
            int e = tid + p * 256;
            int jj = e >> 4, nc = (e & 15) * 4;
            *(float4*)&vs[jj][nc] =
                *(const float4*)&V[((size_t)b * NK + j0 + jj) * D + n0 + nc];
        }
        __syncthreads();
        #pragma unroll
        for (int jj = 0; jj < 64; jj++) {
            float vv = vs[jj][tx];
            acc[0] += as_[ty     ][jj] * vv;
            acc[1] += as_[ty +  4][jj] * vv;
            acc[2] += as_[ty +  8][jj] * vv;
            acc[3] += as_[ty + 12][jj] * vv;
        }
        __syncthreads();
    }
    #pragma unroll
    for (int r = 0; r < 4; r++)
        upd[((size_t)b * S + ty + r * 4) * D + n0 + tx] = acc[r];
}

__global__ __launch_bounds__(256)
void enc_attn_kernel(const float* __restrict__ Qa, const float* __restrict__ Ka,
                     const float* __restrict__ Va, float* __restrict__ Oa)
{
    int b = blockIdx.x >> 3, h = blockIdx.x & 7;
    __shared__ float qs[16][65], ks[16][65], vs[16][65];
    __shared__ float p[16][17];
    int tid = threadIdx.x;
    int i = tid >> 4, jj = tid & 15;
    {
        int r = tid >> 4, c = (tid & 15) * 4;
        size_t base = ((size_t)b * S + r) * HD + h * DH + c;
        float4 v;
        v = *(const float4*)&Qa[base];
        qs[r][c] = v.x; qs[r][c+1] = v.y; qs[r][c+2] = v.z; qs[r][c+3] = v.w;
        v = *(const float4*)&Ka[base];
        ks[r][c] = v.x; ks[r][c+1] = v.y; ks[r][c+2] = v.z; ks[r][c+3] = v.w;
        v = *(const float4*)&Va[base];
        vs[r][c] = v.x; vs[r][c+1] = v.y; vs[r][c+2] = v.z; vs[r][c+3] = v.w;
    }
    __syncthreads();
    float s = 0.f;
    #pragma unroll
    for (int d = 0; d < DH; d++) s += qs[i][d] * ks[jj][d];
    s *= 0.125f;
    p[i][jj] = s;
    __syncthreads();
    float m = -1e30f;
    #pragma unroll
    for (int t2 = 0; t2 < 16; t2++) m = fmaxf(m, p[i][t2]);
    __syncthreads();
    float e = expf(s - m);
    p[i][jj] = e;
    __syncthreads();
    float sum = 0.f;
    #pragma unroll
    for (int t2 = 0; t2 < 16; t2++) sum += p[i][t2];
    __syncthreads();
    p[i][jj] = e / sum;
    __syncthreads();
    int io = tid >> 4, dbase = (tid & 15) * 4;
    float o0 = 0.f, o1 = 0.f, o2 = 0.f, o3 = 0.f;
    #pragma unroll
    for (int t2 = 0; t2 < 16; t2++) {
        float pp = p[io][t2];
        o0 += pp * vs[t2][dbase + 0];
        o1 += pp * vs[t2][dbase + 1];
        o2 += pp * vs[t2][dbase + 2];
        o3 += pp * vs[t2][dbase + 3];
    }
    float4 ov = make_float4(o0, o1, o2, o3);
    *(float4*)&Oa[((size_t)b * S + io) * HD + h * DH + dbase] = ov;
}

__global__ void glu_kernel(const float* __restrict__ ug, float* __restrict__ inner)
{
    int t = blockIdx.x * blockDim.x + threadIdx.x;
    if (t >= B * S * INNER) return;
    int r = t / INNER, c = t - r * INNER;
    float u = ug[(size_t)r * 2 * INNER + c];
    float g = ug[(size_t)r * 2 * INNER + INNER + c];
    inner[t] = u * (g / (1.f + expf(-g)));
}

__global__ void write_attn_kernel(const float* __restrict__ attn, float* __restrict__ out)
{
    int t = blockIdx.x * blockDim.x + threadIdx.x;
    if (t >= B * NK * S) return;
    int i = t & 15, j = (t >> 4) & (NK - 1), b = t >> 14;
    out[t] = attn[((size_t)b * S + i) * NK + j];
}

// ----------------------------------------------------------------------------
// Host orchestration
// ----------------------------------------------------------------------------
extern "C" void kernel_launch(void* const* d_in, const int* in_sizes, int n_in,
                              void* d_out, int out_size)
{
    const float* x       = (const float*)d_in[0];
    const float* noise   = (const float*)d_in[1];
    const float* init_mu = (const float*)d_in[2];
    const float* init_ls = (const float*)d_in[3];
    const float* Wk      = (const float*)d_in[4];
    const float* Wv      = (const float*)d_in[5];
    const float* Wq      = (const float*)d_in[6];
    const float* ni_g    = (const float*)d_in[7];
    const float* ni_b    = (const float*)d_in[8];
    const float* ns_g    = (const float*)d_in[9];
    const float* ns_b    = (const float*)d_in[10];
    const float* nica_g  = (const float*)d_in[11];
    const float* nica_b  = (const float*)d_in[12];
    const float* ln1_g   = (const float*)d_in[13];
    const float* ln1_b   = (const float*)d_in[14];
    const float* Wq_a    = (const float*)d_in[15];
    const float* Wk_a    = (const float*)d_in[16];
    const float* Wv_a    = (const float*)d_in[17];
    const float* Wo_a    = (const float*)d_in[18];
    const float* ln2_g   = (const float*)d_in[19];
    const float* ln2_b   = (const float*)d_in[20];
    const float* W1      = (const float*)d_in[21];
    const float* W2      = (const float*)d_in[22];
    const float* lnf_g   = (const float*)d_in[23];
    const float* lnf_b   = (const float*)d_in[24];

    __half *xnh, *xnl, *wkh, *wkl, *wvh, *wvl, *w1h, *w1l, *fbh, *fbl;
    float *kb, *vb, *slots, *qn, *qb, *attn, *upd;
    float *hb, *ab, *qa, *ka, *va, *oa, *ug, *innerb, *part;
    cudaGetSymbolAddress((void**)&xnh,   g_xnh);
    cudaGetSymbolAddress((void**)&xnl,   g_xnl);
    cudaGetSymbolAddress((void**)&wkh,   g_wkh);
    cudaGetSymbolAddress((void**)&wkl,   g_wkl);
    cudaGetSymbolAddress((void**)&wvh,   g_wvh);
    cudaGetSymbolAddress((void**)&wvl,   g_wvl);
    cudaGetSymbolAddress((void**)&w1h,   g_w1h);
    cudaGetSymbolAddress((void**)&w1l,   g_w1l);
    cudaGetSymbolAddress((void**)&fbh,   g_fbh);
    cudaGetSymbolAddress((void**)&fbl,   g_fbl);
    cudaGetSymbolAddress((void**)&kb,    g_k);
    cudaGetSymbolAddress((void**)&vb,    g_v);
    cudaGetSymbolAddress((void**)&slots, g_slots);
    cudaGetSymbolAddress((void**)&qn,    g_qn);
    cudaGetSymbolAddress((void**)&qb,    g_q);
    cudaGetSymbolAddress((void**)&attn,  g_attn);
    cudaGetSymbolAddress((void**)&upd,   g_upd);
    cudaGetSymbolAddress((void**)&hb,    g_h);
    cudaGetSymbolAddress((void**)&ab,    g_a);
    cudaGetSymbolAddress((void**)&qa,    g_qa);
    cudaGetSymbolAddress((void**)&ka,    g_ka);
    cudaGetSymbolAddress((void**)&va,    g_va);
    cudaGetSymbolAddress((void**)&oa,    g_oa);
    cudaGetSymbolAddress((void**)&ug,    g_ug);
    cudaGetSymbolAddress((void**)&innerb,g_in);
    cudaGetSymbolAddress((void**)&part,  g_part);

    const int MS = B * S;            // 512

    // ---- precompute: LN(x) -> fp16 hi/lo; W^T hi/lo; HMMA projections ----
    ln_split_kernel<<<B * NK, 256>>>(x, xnh, xnl, ni_g, ni_b);
    wsplit_kernel<<<dim3(D / 32, D / 32), 256>>>(Wk, wkh, wkl, D);
    wsplit_kernel<<<dim3(D / 32, D / 32), 256>>>(Wv, wvh, wvl, D);
    wsplit_kernel<<<dim3((2 * INNER) / 32, D / 32), 256>>>(W1, w1h, w1l, 2 * INNER);
    hgemm_hilo<<<dim3(D / 128, (B * NK) / 128), 256>>>(xnh, xnl, wkh, wkl, kb,
                                                       B * NK, D, D);
    hgemm_hilo<<<dim3(D / 128, (B * NK) / 128), 256>>>(xnh, xnl, wvh, wvl, vb,
                                                       B * NK, D, D);
    init_slots_kernel<<<(MS * D + 255) / 256, 256>>>(noise, init_mu, init_ls, slots);

    // ---- 4 slot-attention steps ----
    for (int it = 0; it < N_STEPS; it++) {
        ln_kernel<<<MS, 256>>>(slots, nullptr, qn, ns_g, ns_b);
        gemm128<false><<<dim3(D / 128, MS / 128, 8), 256>>>(qn, Wq, nullptr, part, MS, D, D);
        reduce_split<false><<<(MS * D / 4 + 255) / 256, 256>>>(part, nullptr, qb, MS * D, 8);

        dots_softmax_kernel<<<dim3(NK / 64, B), 256>>>(qb, kb, attn);
        rowsum_renorm_kernel<<<MS, 256>>>(attn);
        updates_kernel<<<dim3(D / 64, B), 256>>>(attn, vb, upd);
        ln_kernel<<<MS, 256>>>(slots, upd, hb, nica_g, nica_b);

        // encoder
        ln_kernel<<<MS, 256>>>(hb, nullptr, ab, ln1_g, ln1_b);
        gemm128<false><<<dim3(HD / 128, MS / 128, 8), 256>>>(ab, Wq_a, nullptr, part, MS, HD, D);
        reduce_split<false><<<(MS * HD / 4 + 255) / 256, 256>>>(part, nullptr, qa, MS * HD, 8);
        gemm128<false><<<dim3(HD / 128, MS / 128, 8), 256>>>(ab, Wk_a, nullptr, part, MS, HD, D);
        reduce_split<false><<<(MS * HD / 4 + 255) / 256, 256>>>(part, nullptr, ka, MS * HD, 8);
        gemm128<false><<<dim3(HD / 128, MS / 128, 8), 256>>>(ab, Wv_a, nullptr, part, MS, HD, D);
        reduce_split<false><<<(MS * HD / 4 + 255) / 256, 256>>>(part, nullptr, va, MS * HD, 8);
        enc_attn_kernel<<<B * H, 256>>>(qa, ka, va, oa);
        gemm128<false><<<dim3(D / 128, MS / 128, 8), 256>>>(oa, Wo_a, nullptr, part, MS, D, HD);
        reduce_split<true><<<(MS * D / 4 + 255) / 256, 256>>>(part, hb, hb, MS * D, 8);

        // ff: ln2 -> hi/lo halves -> HMMA W1 -> GLU -> W2 (FFMA2 split-K)
        ln_split_kernel<<<MS, 256>>>(hb, fbh, fbl, ln2_g, ln2_b);
        hgemm_hilo<<<dim3((2 * INNER) / 128, MS / 128), 256>>>(fbh, fbl, w1h, w1l,
                                                               ug, MS, 2 * INNER, D);
        glu_kernel<<<(MS * INNER + 255) / 256, 256>>>(ug, innerb);
        gemm128<false><<<dim3(D / 128, MS / 128, 8), 256>>>(innerb, W2, nullptr, part, MS, D, INNER);
        reduce_split<true><<<(MS * D / 4 + 255) / 256, 256>>>(part, hb, hb, MS * D, 8);
        ln_kernel<<<MS, 256>>>(hb, nullptr, slots, lnf_g, lnf_b);
    }

    // ---- outputs: slots [32,16,768], then attn_map [32,1024,16] ----
    float* out = (float*)d_out;
    cudaMemcpyAsync(out, slots, (size_t)MS * D * sizeof(float),
                    cudaMemcpyDeviceToDevice);
    write_attn_kernel<<<(B * NK * S + 255) / 256, 256>>>(attn, out + (size_t)MS * D);
}

// round 5
// speedup vs baseline: 3.5225x; 1.1225x over previous
#include <cuda_runtime.h>
#include <cuda_fp16.h>
#include <math.h>
#include <stdint.h>

// ----------------------------------------------------------------------------
// Problem constants
// ----------------------------------------------------------------------------
#define B   32
#define NK  1024
#define S   16
#define D   768
#define H   8
#define DH  64
#define HD  (H*DH)    // 512
#define INNER 3072
#define N_STEPS 4
static __device__ __constant__ float kSCALE = 0.036084391824351615f;  // 768^-0.5

// ----------------------------------------------------------------------------
// Scratch (device globals)
// ----------------------------------------------------------------------------
__device__ __half g_xnh[B*NK*D], g_xnl[B*NK*D];
// weight transposes, fp16 hi/lo, K-major [n][k]
__device__ __half g_wkh [D*D],        g_wkl [D*D];
__device__ __half g_wvh [D*D],        g_wvl [D*D];
__device__ __half g_wqh [D*D],        g_wql [D*D];
__device__ __half g_wqah[HD*D],       g_wqal[HD*D];
__device__ __half g_wkah[HD*D],       g_wkal[HD*D];
__device__ __half g_wvah[HD*D],       g_wval[HD*D];
__device__ __half g_woh [D*HD],       g_wol [D*HD];
__device__ __half g_w1h [2*INNER*D],  g_w1l [2*INNER*D];
__device__ __half g_w2h [D*INNER],    g_w2l [D*INNER];
// activations, fp16 hi/lo
__device__ __half g_qnh[B*S*D],   g_qnl[B*S*D];
__device__ __half g_abh[B*S*D],   g_abl[B*S*D];
__device__ __half g_fbh[B*S*D],   g_fbl[B*S*D];
__device__ __half g_innh[B*S*INNER], g_innl[B*S*INNER];
__device__ __half g_oah[B*S*HD],  g_oal[B*S*HD];
// fp32
__device__ float g_k    [B*NK*D];
__device__ float g_v    [B*NK*D];
__device__ float g_slots[B*S*D];
__device__ float g_q    [B*S*D];
__device__ float g_attn [B*S*NK];
__device__ float g_upd  [B*S*D];
__device__ float g_h    [B*S*D];
__device__ float g_qa   [B*S*HD];
__device__ float g_ka   [B*S*HD];
__device__ float g_va   [B*S*HD];
__device__ float g_ug   [B*S*2*INNER];
__device__ float g_part [8*512*768];

// ----------------------------------------------------------------------------
// HMMA helpers (baseline PTX — compiles for plain compute_103)
// ----------------------------------------------------------------------------
__device__ __forceinline__ uint32_t smem_u32(const void* p) {
    uint32_t a;
    asm("{ .reg .u64 t; cvta.to.shared.u64 t, %1; cvt.u32.u64 %0, t; }"
        : "=r"(a) : "l"(p));
    return a;
}
#define LDSM_X4(r0, r1, r2, r3, addr) \
    asm volatile("ldmatrix.sync.aligned.m8n8.x4.shared.b16 {%0,%1,%2,%3}, [%4];" \
                 : "=r"(r0), "=r"(r1), "=r"(r2), "=r"(r3) : "r"(addr))
#define LDSM_X2(r0, r1, addr) \
    asm volatile("ldmatrix.sync.aligned.m8n8.x2.shared.b16 {%0,%1}, [%2];" \
                 : "=r"(r0), "=r"(r1) : "r"(addr))
#define MMA16816(c, a, b) \
    asm volatile("mma.sync.aligned.m16n8k16.row.col.f32.f16.f16.f32 " \
                 "{%0,%1,%2,%3}, {%4,%5,%6,%7}, {%8,%9}, {%0,%1,%2,%3};" \
                 : "+f"((c)[0]), "+f"((c)[1]), "+f"((c)[2]), "+f"((c)[3]) \
                 : "r"((a)[0]), "r"((a)[1]), "r"((a)[2]), "r"((a)[3]), \
                   "r"((b)[0]), "r"((b)[1]))

#define PITCH 40   // halves per smem row (80 B) — conflict-free ldmatrix

// ----------------------------------------------------------------------------
// fp16 hi/lo HMMA GEMM with split-K: C[M,N] = A[M,K] @ Bt^T, Bt = [N][K].
// 128x128 CTA tile, BK=32, 8 warps (2x4). gridDim.z splits K; partial z
// written at C + z*M*N (z==1 -> direct).
// ----------------------------------------------------------------------------
__global__ __launch_bounds__(256)
void hgemm_hilo(const __half* __restrict__ Ah, const __half* __restrict__ Al,
                const __half* __restrict__ Bth, const __half* __restrict__ Btl,
                float* __restrict__ C, int M, int N, int K)
{
    __shared__ __align__(16) __half sAh[128 * PITCH], sAl[128 * PITCH];
    __shared__ __align__(16) __half sBh[128 * PITCH], sBl[128 * PITCH];
    int tid = threadIdx.x;
    int lane = tid & 31, wid = tid >> 5;
    int wm = wid >> 2, wn = wid & 3;
    int row0 = blockIdx.y * 128, col0 = blockIdx.x * 128;
    int kb   = K / gridDim.z;
    int kbeg = blockIdx.z * kb;
    float* Cz = C + (size_t)blockIdx.z * M * N;

    uint32_t bAh = smem_u32(sAh), bAl = smem_u32(sAl);
    uint32_t bBh = smem_u32(sBh), bBl = smem_u32(sBl);

    float acc[4][4][4];
    #pragma unroll
    for (int mf = 0; mf < 4; mf++)
        #pragma unroll
        for (int nf = 0; nf < 4; nf++)
            #pragma unroll
            for (int e = 0; e < 4; e++) acc[mf][nf][e] = 0.f;

    int laneAr = lane & 15, laneAk = (lane & 16) ? 8 : 0;
    int laneBr = lane & 7,  laneBk = (lane & 8)  ? 8 : 0;

    for (int kc = 0; kc < kb; kc += 32) {
        #pragma unroll
        for (int i = 0; i < 2; i++) {
            int idx = tid + i * 256;
            int row = idx >> 2, seg = idx & 3;
            size_t ga = (size_t)(row0 + row) * K + kbeg + kc + seg * 8;
            size_t gb = (size_t)(col0 + row) * K + kbeg + kc + seg * 8;
            int so = row * PITCH + seg * 8;
            *(uint4*)(sAh + so) = *(const uint4*)(Ah + ga);
            *(uint4*)(sAl + so) = *(const uint4*)(Al + ga);
            *(uint4*)(sBh + so) = *(const uint4*)(Bth + gb);
            *(uint4*)(sBl + so) = *(const uint4*)(Btl + gb);
        }
        __syncthreads();
        #pragma unroll
        for (int ks = 0; ks < 32; ks += 16) {
            uint32_t bh[4][2], bl[4][2];
            #pragma unroll
            for (int nf = 0; nf < 4; nf++) {
                uint32_t off = (uint32_t)((wn * 32 + nf * 8 + laneBr) * PITCH
                                          + ks + laneBk) * 2;
                LDSM_X2(bh[nf][0], bh[nf][1], bBh + off);
                LDSM_X2(bl[nf][0], bl[nf][1], bBl + off);
            }
            #pragma unroll
            for (int mf = 0; mf < 4; mf++) {
                uint32_t off = (uint32_t)((wm * 64 + mf * 16 + laneAr) * PITCH
                                          + ks + laneAk) * 2;
                uint32_t ah[4], al[4];
                LDSM_X4(ah[0], ah[1], ah[2], ah[3], bAh + off);
                LDSM_X4(al[0], al[1], al[2], al[3], bAl + off);
                #pragma unroll
                for (int nf = 0; nf < 4; nf++) {
                    MMA16816(acc[mf][nf], ah, bh[nf]);
                    MMA16816(acc[mf][nf], ah, bl[nf]);
                    MMA16816(acc[mf][nf], al, bh[nf]);
                }
            }
        }
        __syncthreads();
    }
    #pragma unroll
    for (int mf = 0; mf < 4; mf++) {
        int r = row0 + wm * 64 + mf * 16 + (lane >> 2);
        #pragma unroll
        for (int nf = 0; nf < 4; nf++) {
            int c = col0 + wn * 32 + nf * 8 + (lane & 3) * 2;
            *(float2*)(Cz + (size_t)r * N + c) =
                make_float2(acc[mf][nf][0], acc[mf][nf][1]);
            *(float2*)(Cz + (size_t)(r + 8) * N + c) =
                make_float2(acc[mf][nf][2], acc[mf][nf][3]);
        }
    }
}

// ----------------------------------------------------------------------------
// Dual-output projection: Ck = A@Wk^T, Cv = A@Wv^T with A staged once.
// Dynamic smem: 6 tiles of 128*PITCH halves.
// ----------------------------------------------------------------------------
__global__ __launch_bounds__(256)
void hgemm_dual(const __half* __restrict__ Ah, const __half* __restrict__ Al,
                const __half* __restrict__ Bkh, const __half* __restrict__ Bkl,
                const __half* __restrict__ Bvh, const __half* __restrict__ Bvl,
                float* __restrict__ Ck, float* __restrict__ Cv,
                int M, int N, int K)
{
    extern __shared__ __align__(16) __half dyn[];
    __half* sAh = dyn;
    __half* sAl = dyn + 1 * 128 * PITCH;
    __half* sKh = dyn + 2 * 128 * PITCH;
    __half* sKl = dyn + 3 * 128 * PITCH;
    __half* sVh = dyn + 4 * 128 * PITCH;
    __half* sVl = dyn + 5 * 128 * PITCH;
    int tid = threadIdx.x;
    int lane = tid & 31, wid = tid >> 5;
    int wm = wid >> 2, wn = wid & 3;
    int row0 = blockIdx.y * 128, col0 = blockIdx.x * 128;

    uint32_t bAh = smem_u32(sAh), bAl = smem_u32(sAl);
    uint32_t bKh = smem_u32(sKh), bKl = smem_u32(sKl);
    uint32_t bVh = smem_u32(sVh), bVl = smem_u32(sVl);

    float accK[4][4][4], accV[4][4][4];
    #pragma unroll
    for (int mf = 0; mf < 4; mf++)
        #pragma unroll
        for (int nf = 0; nf < 4; nf++)
            #pragma unroll
            for (int e = 0; e < 4; e++) { accK[mf][nf][e] = 0.f; accV[mf][nf][e] = 0.f; }

    int laneAr = lane & 15, laneAk = (lane & 16) ? 8 : 0;
    int laneBr = lane & 7,  laneBk = (lane & 8)  ? 8 : 0;

    for (int kc = 0; kc < K; kc += 32) {
        #pragma unroll
        for (int i = 0; i < 2; i++) {
            int idx = tid + i * 256;
            int row = idx >> 2, seg = idx & 3;
            size_t ga = (size_t)(row0 + row) * K + kc + seg * 8;
            size_t gb = (size_t)(col0 + row) * K + kc + seg * 8;
            int so = row * PITCH + seg * 8;
            *(uint4*)(sAh + so) = *(const uint4*)(Ah + ga);
            *(uint4*)(sAl + so) = *(const uint4*)(Al + ga);
            *(uint4*)(sKh + so) = *(const uint4*)(Bkh + gb);
            *(uint4*)(sKl + so) = *(const uint4*)(Bkl + gb);
            *(uint4*)(sVh + so) = *(const uint4*)(Bvh + gb);
            *(uint4*)(sVl + so) = *(const uint4*)(Bvl + gb);
        }
        __syncthreads();
        #pragma unroll
        for (int ks = 0; ks < 32; ks += 16) {
            uint32_t kh[4][2], kl[4][2], vh[4][2], vl[4][2];
            #pragma unroll
            for (int nf = 0; nf < 4; nf++) {
                uint32_t off = (uint32_t)((wn * 32 + nf * 8 + laneBr) * PITCH
                                          + ks + laneBk) * 2;
                LDSM_X2(kh[nf][0], kh[nf][1], bKh + off);
                LDSM_X2(kl[nf][0], kl[nf][1], bKl + off);
                LDSM_X2(vh[nf][0], vh[nf][1], bVh + off);
                LDSM_X2(vl[nf][0], vl[nf][1], bVl + off);
            }
            #pragma unroll
            for (int mf = 0; mf < 4; mf++) {
                uint32_t off = (uint32_t)((wm * 64 + mf * 16 + laneAr) * PITCH
                                          + ks + laneAk) * 2;
                uint32_t ah[4], al[4];
                LDSM_X4(ah[0], ah[1], ah[2], ah[3], bAh + off);
                LDSM_X4(al[0], al[1], al[2], al[3], bAl + off);
                #pragma unroll
                for (int nf = 0; nf < 4; nf++) {
                    MMA16816(accK[mf][nf], ah, kh[nf]);
                    MMA16816(accK[mf][nf], ah, kl[nf]);
                    MMA16816(accK[mf][nf], al, kh[nf]);
                    MMA16816(accV[mf][nf], ah, vh[nf]);
                    MMA16816(accV[mf][nf], ah, vl[nf]);
                    MMA16816(accV[mf][nf], al, vh[nf]);
                }
            }
        }
        __syncthreads();
    }
    #pragma unroll
    for (int mf = 0; mf < 4; mf++) {
        int r = row0 + wm * 64 + mf * 16 + (lane >> 2);
        #pragma unroll
        for (int nf = 0; nf < 4; nf++) {
            int c = col0 + wn * 32 + nf * 8 + (lane & 3) * 2;
            *(float2*)(Ck + (size_t)r * N + c) =
                make_float2(accK[mf][nf][0], accK[mf][nf][1]);
            *(float2*)(Ck + (size_t)(r + 8) * N + c) =
                make_float2(accK[mf][nf][2], accK[mf][nf][3]);
            *(float2*)(Cv + (size_t)r * N + c) =
                make_float2(accV[mf][nf][0], accV[mf][nf][1]);
            *(float2*)(Cv + (size_t)(r + 8) * N + c) =
                make_float2(accV[mf][nf][2], accV[mf][nf][3]);
        }
    }
}

// ----------------------------------------------------------------------------
// LN over D=768 emitting fp16 hi/lo
// ----------------------------------------------------------------------------
__global__ __launch_bounds__(256)
void ln_split_kernel(const float* __restrict__ in,
                     __half* __restrict__ oh, __half* __restrict__ ol,
                     const float* __restrict__ gamma, const float* __restrict__ beta)
{
    int row = blockIdx.x;
    int tid = threadIdx.x;
    const float* x = in + (size_t)row * D;
    float v0 = x[tid], v1 = x[tid + 256], v2 = x[tid + 512];
    float s = v0 + v1 + v2;
    float q = v0 * v0 + v1 * v1 + v2 * v2;
    __shared__ float sa[8], sb2[8];
    #pragma unroll
    for (int o = 16; o > 0; o >>= 1) {
        s += __shfl_down_sync(0xffffffffu, s, o);
        q += __shfl_down_sync(0xffffffffu, q, o);
    }
    int w = tid >> 5, l = tid & 31;
    if (l == 0) { sa[w] = s; sb2[w] = q; }
    __syncthreads();
    if (tid == 0) {
        float ts = 0.f, tq = 0.f;
        #pragma unroll
        for (int k = 0; k < 8; k++) { ts += sa[k]; tq += sb2[k]; }
        sa[0] = ts; sb2[0] = tq;
    }
    __syncthreads();
    float mean = sa[0] * (1.0f / D);
    float var  = sb2[0] * (1.0f / D) - mean * mean;
    float r = rsqrtf(var + 1e-5f);
    #pragma unroll
    for (int e = 0; e < 3; e++) {
        int idx = tid + e * 256;
        float val = (e == 0 ? v0 : (e == 1 ? v1 : v2));
        float y = (val - mean) * r * gamma[idx] + beta[idx];
        __half hb = __float2half_rn(y);
        __half lb = __float2half_rn(y - __half2float(hb));
        oh[(size_t)row * D + idx] = hb;
        ol[(size_t)row * D + idx] = lb;
    }
}

// transpose + fp16 hi/lo split: W[Krows, Ncols] -> T[n][k] (stride Krows)
__global__ __launch_bounds__(256)
void wsplit_kernel(const float* __restrict__ W,
                   __half* __restrict__ Th, __half* __restrict__ Tl,
                   int Krows, int Ncols)
{
    __shared__ float tile[32][33];
    int n0 = blockIdx.x * 32, k0 = blockIdx.y * 32;
    int t = threadIdx.x;
    int tx = t & 31, ty = t >> 5;
    #pragma unroll
    for (int i = 0; i < 4; i++)
        tile[ty + i * 8][tx] = W[(size_t)(k0 + ty + i * 8) * Ncols + n0 + tx];
    __syncthreads();
    #pragma unroll
    for (int i = 0; i < 4; i++) {
        int n = n0 + ty + i * 8;
        float v = tile[tx][ty + i * 8];
        __half hb = __float2half_rn(v);
        __half lb = __float2half_rn(v - __half2float(hb));
        Th[(size_t)n * Krows + k0 + tx] = hb;
        Tl[(size_t)n * Krows + k0 + tx] = lb;
    }
}

// ----------------------------------------------------------------------------
// LayerNorm over D=768 (fp32 out; optional add-before-norm)
// ----------------------------------------------------------------------------
__global__ __launch_bounds__(256)
void ln_kernel(const float* __restrict__ in, const float* __restrict__ add,
               float* __restrict__ out,
               const float* __restrict__ gamma, const float* __restrict__ beta)
{
    int row = blockIdx.x;
    int tid = threadIdx.x;
    const float* x = in + (size_t)row * D;
    float v0 = x[tid], v1 = x[tid + 256], v2 = x[tid + 512];
    if (add) {
        const float* a = add + (size_t)row * D;
        v0 += a[tid]; v1 += a[tid + 256]; v2 += a[tid + 512];
    }
    float s = v0 + v1 + v2;
    float q = v0 * v0 + v1 * v1 + v2 * v2;
    __shared__ float sa[8], sb2[8];
    #pragma unroll
    for (int o = 16; o > 0; o >>= 1) {
        s += __shfl_down_sync(0xffffffffu, s, o);
        q += __shfl_down_sync(0xffffffffu, q, o);
    }
    int w = tid >> 5, l = tid & 31;
    if (l == 0) { sa[w] = s; sb2[w] = q; }
    __syncthreads();
    if (tid == 0) {
        float ts = 0.f, tq = 0.f;
        #pragma unroll
        for (int k = 0; k < 8; k++) { ts += sa[k]; tq += sb2[k]; }
        sa[0] = ts; sb2[0] = tq;
    }
    __syncthreads();
    float mean = sa[0] * (1.0f / D);
    float var  = sb2[0] * (1.0f / D) - mean * mean;
    float r = rsqrtf(var + 1e-5f);
    float* o = out + (size_t)row * D;
    o[tid]       = (v0 - mean) * r * gamma[tid]       + beta[tid];
    o[tid + 256] = (v1 - mean) * r * gamma[tid + 256] + beta[tid + 256];
    o[tid + 512] = (v2 - mean) * r * gamma[tid + 512] + beta[tid + 512];
}

__global__ void init_slots_kernel(const float* __restrict__ noise,
                                  const float* __restrict__ mu,
                                  const float* __restrict__ ls,
                                  float* __restrict__ slots)
{
    int t = blockIdx.x * blockDim.x + threadIdx.x;
    if (t >= B * S * D) return;
    int d = t % D;
    slots[t] = mu[d] + expf(ls[d]) * noise[t];
}

// reduce split-K partials (+ optional residual)
template <bool HAS_RES>
__global__ void reduce_split(const float* __restrict__ part,
                             const float* __restrict__ Res,
                             float* __restrict__ C, int MN, int nsplit)
{
    int t = blockIdx.x * blockDim.x + threadIdx.x;
    if (t * 4 >= MN) return;
    float4 s = ((const float4*)part)[t];
    for (int sp = 1; sp < nsplit; sp++) {
        float4 v = ((const float4*)(part + (size_t)sp * MN))[t];
        s.x += v.x; s.y += v.y; s.z += v.z; s.w += v.w;
    }
    if (HAS_RES) {
        float4 r = ((const float4*)Res)[t];
        s.x += r.x; s.y += r.y; s.z += r.z; s.w += r.w;
    }
    ((float4*)C)[t] = s;
}

// ----------------------------------------------------------------------------
// dots + softmax over the slot axis, fused
// ----------------------------------------------------------------------------
__global__ __launch_bounds__(256)
void dots_softmax_kernel(const float* __restrict__ Q, const float* __restrict__ Kb,
                         float* __restrict__ attn)
{
    int b  = blockIdx.y;
    int j0 = blockIdx.x * 64;
    __shared__ __align__(16) float qs[16][64];
    __shared__ float ks[64][65];
    __shared__ float red[4][64];
    int tid = threadIdx.x;
    int tx = tid & 63, ty = tid >> 6;
    float acc[4] = {0.f, 0.f, 0.f, 0.f};
    const float* Qb = Q  + (size_t)b * S * D;
    const float* Kp = Kb + ((size_t)b * NK + j0) * D;
    for (int k0 = 0; k0 < D; k0 += 64) {
        {
            int i = tid >> 4, kc = (tid & 15) * 4;
            *(float4*)&qs[i][kc] = *(const float4*)&Qb[(size_t)i * D + k0 + kc];
        }
        #pragma unroll
        for (int p = 0; p < 4; p++) {
            int e = tid + p * 256;
            int jj = e >> 4, kc = (e & 15) * 4;
            float4 v = *(const float4*)&Kp[(size_t)jj * D + k0 + kc];
            ks[jj][kc + 0] = v.x; ks[jj][kc + 1] = v.y;
            ks[jj][kc + 2] = v.z; ks[jj][kc + 3] = v.w;
        }
        __syncthreads();
        #pragma unroll
        for (int kk = 0; kk < 64; kk++) {
            float kv = ks[tx][kk];
            acc[0] += qs[ty     ][kk] * kv;
            acc[1] += qs[ty +  4][kk] * kv;
            acc[2] += qs[ty +  8][kk] * kv;
            acc[3] += qs[ty + 12][kk] * kv;
        }
        __syncthreads();
    }
    #pragma unroll
    for (int r = 0; r < 4; r++) acc[r] *= kSCALE;
    float m = fmaxf(fmaxf(acc[0], acc[1]), fmaxf(acc[2], acc[3]));
    red[ty][tx] = m;
    __syncthreads();
    float M = fmaxf(fmaxf(red[0][tx], red[1][tx]), fmaxf(red[2][tx], red[3][tx]));
    __syncthreads();
    float e[4]; float s = 0.f;
    #pragma unroll
    for (int r = 0; r < 4; r++) { e[r] = expf(acc[r] - M); s += e[r]; }
    red[ty][tx] = s;
    __syncthreads();
    float Ssum = red[0][tx] + red[1][tx] + red[2][tx] + red[3][tx];
    float inv = 1.f / Ssum;
    #pragma unroll
    for (int r = 0; r < 4; r++)
        attn[((size_t)b * S + ty + r * 4) * NK + j0 + tx] = e[r] * inv + 1e-8f;
}

__global__ __launch_bounds__(256)
void rowsum_renorm_kernel(float* __restrict__ attn)
{
    int row = blockIdx.x;
    float4* p = (float4*)(attn + (size_t)row * NK);
    int tid = threadIdx.x;
    float4 v = p[tid];
    float s = v.x + v.y + v.z + v.w;
    __shared__ float sa[8];
    #pragma unroll
    for (int o = 16; o > 0; o >>= 1) s += __shfl_down_sync(0xffffffffu, s, o);
    int w = tid >> 5, l = tid & 31;
    if (l == 0) sa[w] = s;
    __syncthreads();
    if (tid == 0) {
        float ts = 0.f;
        #pragma unroll
        for (int k = 0; k < 8; k++) ts += sa[k];
        sa[0] = ts;
    }
    __syncthreads();
    float inv = 1.f / sa[0];
    v.x *= inv; v.y *= inv; v.z *= inv; v.w *= inv;
    p[tid] = v;
}

__global__ __launch_bounds__(256)
void updates_kernel(const float* __restrict__ attn, const float* __restrict__ V,
                    float* __restrict__ upd)
{
    int b  = blockIdx.y;
    int n0 = blockIdx.x * 64;
    __shared__ __align__(16) float as_[16][64];
    __shared__ __align__(16) float vs[64][64];
    int tid = threadIdx.x;
    int tx = tid & 63, ty = tid >> 6;
    float acc[4] = {0.f, 0.f, 0.f, 0.f};
    for (int j0 = 0; j0 < NK; j0 += 64) {
        {
            int i = tid >> 4, jc = (tid & 15) * 4;
            *(float4*)&as_[i][jc] =
                *(const float4*)&attn[((size_t)b * S + i) * NK + j0 + jc];
        }
        #pragma unroll
        for (int p = 0; p < 4; p++) {
            int e = tid + p * 256;
            int jj = e >> 4, nc = (e & 15) * 4;
            *(float4*)&vs[jj][nc] =
                *(const float4*)&V[((size_t)b * NK + j0 + jj) * D + n0 + nc];
        }
        __syncthreads();
        #pragma unroll
        for (int jj = 0; jj < 64; jj++) {
            float vv = vs[jj][tx];
            acc[0] += as_[ty     ][jj] * vv;
            acc[1] += as_[ty +  4][jj] * vv;
            acc[2] += as_[ty +  8][jj] * vv;
            acc[3] += as_[ty + 12][jj] * vv;
        }
        __syncthreads();
    }
    #pragma unroll
    for (int r = 0; r < 4; r++)
        upd[((size_t)b * S + ty + r * 4) * D + n0 + tx] = acc[r];
}

// encoder self-attention over 16 tokens; emits fp16 hi/lo for the Wo GEMM
__global__ __launch_bounds__(256)
void enc_attn_kernel(const float* __restrict__ Qa, const float* __restrict__ Ka,
                     const float* __restrict__ Va,
                     __half* __restrict__ Oh, __half* __restrict__ Ol)
{
    int b = blockIdx.x >> 3, h = blockIdx.x & 7;
    __shared__ float qs[16][65], ks[16][65], vs[16][65];
    __shared__ float p[16][17];
    int tid = threadIdx.x;
    int i = tid >> 4, jj = tid & 15;
    {
        int r = tid >> 4, c = (tid & 15) * 4;
        size_t base = ((size_t)b * S + r) * HD + h * DH + c;
        float4 v;
        v = *(const float4*)&Qa[base];
        qs[r][c] = v.x; qs[r][c+1] = v.y; qs[r][c+2] = v.z; qs[r][c+3] = v.w;
        v = *(const float4*)&Ka[base];
        ks[r][c] = v.x; ks[r][c+1] = v.y; ks[r][c+2] = v.z; ks[r][c+3] = v.w;
        v = *(const float4*)&Va[base];
        vs[r][c] = v.x; vs[r][c+1] = v.y; vs[r][c+2] = v.z; vs[r][c+3] = v.w;
    }
    __syncthreads();
    float s = 0.f;
    #pragma unroll
    for (int d = 0; d < DH; d++) s += qs[i][d] * ks[jj][d];
    s *= 0.125f;
    p[i][jj] = s;
    __syncthreads();
    float m = -1e30f;
    #pragma unroll
    for (int t2 = 0; t2 < 16; t2++) m = fmaxf(m, p[i][t2]);
    __syncthreads();
    float e = expf(s - m);
    p[i][jj] = e;
    __syncthreads();
    float sum = 0.f;
    #pragma unroll
    for (int t2 = 0; t2 < 16; t2++) sum += p[i][t2];
    __syncthreads();
    p[i][jj] = e / sum;
    __syncthreads();
    int io = tid >> 4, dbase = (tid & 15) * 4;
    float o[4] = {0.f, 0.f, 0.f, 0.f};
    #pragma unroll
    for (int t2 = 0; t2 < 16; t2++) {
        float pp = p[io][t2];
        o[0] += pp * vs[t2][dbase + 0];
        o[1] += pp * vs[t2][dbase + 1];
        o[2] += pp * vs[t2][dbase + 2];
        o[3] += pp * vs[t2][dbase + 3];
    }
    size_t base = ((size_t)b * S + io) * HD + h * DH + dbase;
    #pragma unroll
    for (int c = 0; c < 4; c++) {
        __half hb = __float2half_rn(o[c]);
        Oh[base + c] = hb;
        Ol[base + c] = __float2half_rn(o[c] - __half2float(hb));
    }
}

// GLU emitting fp16 hi/lo for the W2 GEMM
__global__ void glu_kernel(const float* __restrict__ ug,
                           __half* __restrict__ ih, __half* __restrict__ il)
{
    int t = blockIdx.x * blockDim.x + threadIdx.x;
    if (t >= B * S * INNER) return;
    int r = t / INNER, c = t - r * INNER;
    float u = ug[(size_t)r * 2 * INNER + c];
    float g = ug[(size_t)r * 2 * INNER + INNER + c];
    float v = u * (g / (1.f + expf(-g)));
    __half hb = __float2half_rn(v);
    ih[t] = hb;
    il[t] = __float2half_rn(v - __half2float(hb));
}

__global__ void write_attn_kernel(const float* __restrict__ attn, float* __restrict__ out)
{
    int t = blockIdx.x * blockDim.x + threadIdx.x;
    if (t >= B * NK * S) return;
    int i = t & 15, j = (t >> 4) & (NK - 1), b = t >> 14;
    out[t] = attn[((size_t)b * S + i) * NK + j];
}

// ----------------------------------------------------------------------------
// Host orchestration
// ----------------------------------------------------------------------------
extern "C" void kernel_launch(void* const* d_in, const int* in_sizes, int n_in,
                              void* d_out, int out_size)
{
    const float* x       = (const float*)d_in[0];
    const float* noise   = (const float*)d_in[1];
    const float* init_mu = (const float*)d_in[2];
    const float* init_ls = (const float*)d_in[3];
    const float* Wk      = (const float*)d_in[4];
    const float* Wv      = (const float*)d_in[5];
    const float* Wq      = (const float*)d_in[6];
    const float* ni_g    = (const float*)d_in[7];
    const float* ni_b    = (const float*)d_in[8];
    const float* ns_g    = (const float*)d_in[9];
    const float* ns_b    = (const float*)d_in[10];
    const float* nica_g  = (const float*)d_in[11];
    const float* nica_b  = (const float*)d_in[12];
    const float* ln1_g   = (const float*)d_in[13];
    const float* ln1_b   = (const float*)d_in[14];
    const float* Wq_a    = (const float*)d_in[15];
    const float* Wk_a    = (const float*)d_in[16];
    const float* Wv_a    = (const float*)d_in[17];
    const float* Wo_a    = (const float*)d_in[18];
    const float* ln2_g   = (const float*)d_in[19];
    const float* ln2_b   = (const float*)d_in[20];
    const float* W1      = (const float*)d_in[21];
    const float* W2      = (const float*)d_in[22];
    const float* lnf_g   = (const float*)d_in[23];
    const float* lnf_b   = (const float*)d_in[24];

    __half *xnh, *xnl, *wkh, *wkl, *wvh, *wvl, *wqh, *wql;
    __half *wqah, *wqal, *wkah, *wkal, *wvah, *wval, *woh, *wol;
    __half *w1h, *w1l, *w2h, *w2l;
    __half *qnh, *qnl, *abh, *abl, *fbh, *fbl, *innh, *innl, *oah, *oal;
    float *kb, *vb, *slots, *qb, *attn, *upd, *hb, *qa, *ka, *va, *ug, *part;
    cudaGetSymbolAddress((void**)&xnh,  g_xnh);  cudaGetSymbolAddress((void**)&xnl,  g_xnl);
    cudaGetSymbolAddress((void**)&wkh,  g_wkh);  cudaGetSymbolAddress((void**)&wkl,  g_wkl);
    cudaGetSymbolAddress((void**)&wvh,  g_wvh);  cudaGetSymbolAddress((void**)&wvl,  g_wvl);
    cudaGetSymbolAddress((void**)&wqh,  g_wqh);  cudaGetSymbolAddress((void**)&wql,  g_wql);
    cudaGetSymbolAddress((void**)&wqah, g_wqah); cudaGetSymbolAddress((void**)&wqal, g_wqal);
    cudaGetSymbolAddress((void**)&wkah, g_wkah); cudaGetSymbolAddress((void**)&wkal, g_wkal);
    cudaGetSymbolAddress((void**)&wvah, g_wvah); cudaGetSymbolAddress((void**)&wval, g_wval);
    cudaGetSymbolAddress((void**)&woh,  g_woh);  cudaGetSymbolAddress((void**)&wol,  g_wol);
    cudaGetSymbolAddress((void**)&w1h,  g_w1h);  cudaGetSymbolAddress((void**)&w1l,  g_w1l);
    cudaGetSymbolAddress((void**)&w2h,  g_w2h);  cudaGetSymbolAddress((void**)&w2l,  g_w2l);
    cudaGetSymbolAddress((void**)&qnh,  g_qnh);  cudaGetSymbolAddress((void**)&qnl,  g_qnl);
    cudaGetSymbolAddress((void**)&abh,  g_abh);  cudaGetSymbolAddress((void**)&abl,  g_abl);
    cudaGetSymbolAddress((void**)&fbh,  g_fbh);  cudaGetSymbolAddress((void**)&fbl,  g_fbl);
    cudaGetSymbolAddress((void**)&innh, g_innh); cudaGetSymbolAddress((void**)&innl, g_innl);
    cudaGetSymbolAddress((void**)&oah,  g_oah);  cudaGetSymbolAddress((void**)&oal,  g_oal);
    cudaGetSymbolAddress((void**)&kb,   g_k);
    cudaGetSymbolAddress((void**)&vb,   g_v);
    cudaGetSymbolAddress((void**)&slots,g_slots);
    cudaGetSymbolAddress((void**)&qb,   g_q);
    cudaGetSymbolAddress((void**)&attn, g_attn);
    cudaGetSymbolAddress((void**)&upd,  g_upd);
    cudaGetSymbolAddress((void**)&hb,   g_h);
    cudaGetSymbolAddress((void**)&qa,   g_qa);
    cudaGetSymbolAddress((void**)&ka,   g_ka);
    cudaGetSymbolAddress((void**)&va,   g_va);
    cudaGetSymbolAddress((void**)&ug,   g_ug);
    cudaGetSymbolAddress((void**)&part, g_part);

    const int DUAL_SMEM = 6 * 128 * PITCH * (int)sizeof(__half);  // 61440
    cudaFuncSetAttribute(hgemm_dual, cudaFuncAttributeMaxDynamicSharedMemorySize,
                         DUAL_SMEM);

    const int MS = B * S;            // 512

    // ---- precompute ----
    ln_split_kernel<<<B * NK, 256>>>(x, xnh, xnl, ni_g, ni_b);
    wsplit_kernel<<<dim3(D / 32, D / 32), 256>>>(Wk, wkh, wkl, D, D);
    wsplit_kernel<<<dim3(D / 32, D / 32), 256>>>(Wv, wvh, wvl, D, D);
    wsplit_kernel<<<dim3(D / 32, D / 32), 256>>>(Wq, wqh, wql, D, D);
    wsplit_kernel<<<dim3(HD / 32, D / 32), 256>>>(Wq_a, wqah, wqal, D, HD);
    wsplit_kernel<<<dim3(HD / 32, D / 32), 256>>>(Wk_a, wkah, wkal, D, HD);
    wsplit_kernel<<<dim3(HD / 32, D / 32), 256>>>(Wv_a, wvah, wval, D, HD);
    wsplit_kernel<<<dim3(D / 32, HD / 32), 256>>>(Wo_a, woh, wol, HD, D);
    wsplit_kernel<<<dim3((2 * INNER) / 32, D / 32), 256>>>(W1, w1h, w1l, D, 2 * INNER);
    wsplit_kernel<<<dim3(D / 32, INNER / 32), 256>>>(W2, w2h, w2l, INNER, D);
    hgemm_dual<<<dim3(D / 128, (B * NK) / 128), 256, DUAL_SMEM>>>(
        xnh, xnl, wkh, wkl, wvh, wvl, kb, vb, B * NK, D, D);
    init_slots_kernel<<<(MS * D + 255) / 256, 256>>>(noise, init_mu, init_ls, slots);

    // ---- 4 slot-attention steps ----
    for (int it = 0; it < N_STEPS; it++) {
        // q = LN(slots) @ Wq   (HMMA, split-K 4)
        ln_split_kernel<<<MS, 256>>>(slots, qnh, qnl, ns_g, ns_b);
        hgemm_hilo<<<dim3(D / 128, MS / 128, 4), 256>>>(qnh, qnl, wqh, wql,
                                                        part, MS, D, D);
        reduce_split<false><<<(MS * D / 4 + 255) / 256, 256>>>(part, nullptr, qb, MS * D, 4);

        dots_softmax_kernel<<<dim3(NK / 64, B), 256>>>(qb, kb, attn);
        rowsum_renorm_kernel<<<MS, 256>>>(attn);
        updates_kernel<<<dim3(D / 64, B), 256>>>(attn, vb, upd);
        ln_kernel<<<MS, 256>>>(slots, upd, hb, nica_g, nica_b);

        // encoder attention
        ln_split_kernel<<<MS, 256>>>(hb, abh, abl, ln1_g, ln1_b);
        hgemm_hilo<<<dim3(HD / 128, MS / 128, 4), 256>>>(abh, abl, wqah, wqal,
                                                         part, MS, HD, D);
        reduce_split<false><<<(MS * HD / 4 + 255) / 256, 256>>>(part, nullptr, qa, MS * HD, 4);
        hgemm_hilo<<<dim3(HD / 128, MS / 128, 4), 256>>>(abh, abl, wkah, wkal,
                                                         part, MS, HD, D);
        reduce_split<false><<<(MS * HD / 4 + 255) / 256, 256>>>(part, nullptr, ka, MS * HD, 4);
        hgemm_hilo<<<dim3(HD / 128, MS / 128, 4), 256>>>(abh, abl, wvah, wval,
                                                         part, MS, HD, D);
        reduce_split<false><<<(MS * HD / 4 + 255) / 256, 256>>>(part, nullptr, va, MS * HD, 4);
        enc_attn_kernel<<<B * H, 256>>>(qa, ka, va, oah, oal);
        hgemm_hilo<<<dim3(D / 128, MS / 128, 4), 256>>>(oah, oal, woh, wol,
                                                        part, MS, D, HD);
        reduce_split<true><<<(MS * D / 4 + 255) / 256, 256>>>(part, hb, hb, MS * D, 4);

        // GLU feed-forward
        ln_split_kernel<<<MS, 256>>>(hb, fbh, fbl, ln2_g, ln2_b);
        hgemm_hilo<<<dim3((2 * INNER) / 128, MS / 128, 1), 256>>>(fbh, fbl, w1h, w1l,
                                                                  ug, MS, 2 * INNER, D);
        glu_kernel<<<(MS * INNER + 255) / 256, 256>>>(ug, innh, innl);
        hgemm_hilo<<<dim3(D / 128, MS / 128, 8), 256>>>(innh, innl, w2h, w2l,
                                                        part, MS, D, INNER);
        reduce_split<true><<<(MS * D / 4 + 255) / 256, 256>>>(part, hb, hb, MS * D, 8);
        ln_kernel<<<MS, 256>>>(hb, nullptr, slots, lnf_g, lnf_b);
    }

    // ---- outputs: slots [32,16,768], then attn_map [32,1024,16] ----
    float* out = (float*)d_out;
    cudaMemcpyAsync(out, slots, (size_t)MS * D * sizeof(float),
                    cudaMemcpyDeviceToDevice);
    write_attn_kernel<<<(B * NK * S + 255) / 256, 256>>>(attn, out + (size_t)MS * D);
}

// round 6
// speedup vs baseline: 3.9989x; 1.1352x over previous
#include <cuda_runtime.h>
#include <cuda_fp16.h>
#include <math.h>
#include <stdint.h>

// ----------------------------------------------------------------------------
// Problem constants
// ----------------------------------------------------------------------------
#define B   32
#define NK  1024
#define S   16
#define D   768
#define H   8
#define DH  64
#define HD  (H*DH)    // 512
#define QKV3 (3*HD)   // 1536
#define INNER 3072
#define N_STEPS 4
static __device__ __constant__ float kSCALE = 0.036084391824351615f;  // 768^-0.5

// ----------------------------------------------------------------------------
// Scratch (device globals)
// ----------------------------------------------------------------------------
__device__ __half g_xnh[B*NK*D], g_xnl[B*NK*D];
__device__ __half g_wkh [D*D],        g_wkl [D*D];
__device__ __half g_wvh [D*D],        g_wvl [D*D];
__device__ __half g_wqh [D*D],        g_wql [D*D];
__device__ __half g_wqkh[QKV3*D],     g_wqkl[QKV3*D];   // [Wq_a;Wk_a;Wv_a]^T
__device__ __half g_woh [D*HD],       g_wol [D*HD];
__device__ __half g_w1h [2*INNER*D],  g_w1l [2*INNER*D];
__device__ __half g_w2h [D*INNER],    g_w2l [D*INNER];
__device__ __half g_qnh[B*S*D],   g_qnl[B*S*D];
__device__ __half g_abh[B*S*D],   g_abl[B*S*D];
__device__ __half g_fbh[B*S*D],   g_fbl[B*S*D];
__device__ __half g_innh[B*S*INNER], g_innl[B*S*INNER];
__device__ __half g_oah[B*S*HD],  g_oal[B*S*HD];
__device__ float g_k    [B*NK*D];
__device__ float g_v    [B*NK*D];
__device__ float g_slots[B*S*D];
__device__ float g_q    [B*S*D];
__device__ float g_attn [B*S*NK];
__device__ float g_sums [B*S];
__device__ float g_upd  [B*S*D];
__device__ float g_h    [B*S*D];
__device__ float g_qkv  [B*S*QKV3];
__device__ float g_part [4*512*1536];

// ----------------------------------------------------------------------------
// HMMA / cp.async helpers (baseline PTX — compiles for plain compute_103)
// ----------------------------------------------------------------------------
__device__ __forceinline__ uint32_t smem_u32(const void* p) {
    uint32_t a;
    asm("{ .reg .u64 t; cvta.to.shared.u64 t, %1; cvt.u32.u64 %0, t; }"
        : "=r"(a) : "l"(p));
    return a;
}
#define LDSM_X4(r0, r1, r2, r3, addr) \
    asm volatile("ldmatrix.sync.aligned.m8n8.x4.shared.b16 {%0,%1,%2,%3}, [%4];" \
                 : "=r"(r0), "=r"(r1), "=r"(r2), "=r"(r3) : "r"(addr))
#define LDSM_X2(r0, r1, addr) \
    asm volatile("ldmatrix.sync.aligned.m8n8.x2.shared.b16 {%0,%1}, [%2];" \
                 : "=r"(r0), "=r"(r1) : "r"(addr))
#define MMA16816(c, a, b) \
    asm volatile("mma.sync.aligned.m16n8k16.row.col.f32.f16.f16.f32 " \
                 "{%0,%1,%2,%3}, {%4,%5,%6,%7}, {%8,%9}, {%0,%1,%2,%3};" \
                 : "+f"((c)[0]), "+f"((c)[1]), "+f"((c)[2]), "+f"((c)[3]) \
                 : "r"((a)[0]), "r"((a)[1]), "r"((a)[2]), "r"((a)[3]), \
                   "r"((b)[0]), "r"((b)[1]))
#define CP_ASYNC16(dst_u32, src_ptr) \
    asm volatile("cp.async.ca.shared.global [%0], [%1], 16;" \
                 :: "r"(dst_u32), "l"(src_ptr))
#define CP_COMMIT() asm volatile("cp.async.commit_group;" ::: "memory")
#define CP_WAIT(n)  asm volatile("cp.async.wait_group %0;" :: "n"(n) : "memory")

#define PITCH 40            // halves per smem row (80 B) — conflict-free ldmatrix
#define TILEH (128 * PITCH) // halves per tile

// ----------------------------------------------------------------------------
// fp16 hi/lo HMMA GEMM, split-K, 2-stage cp.async double buffer.
// C[M,N] = A[M,K] @ Bt^T (Bt = [N][K]); partial z at C + z*M*N.
// ----------------------------------------------------------------------------
__global__ __launch_bounds__(256)
void hgemm_hilo(const __half* __restrict__ Ah, const __half* __restrict__ Al,
                const __half* __restrict__ Bth, const __half* __restrict__ Btl,
                float* __restrict__ C, int M, int N, int K)
{
    extern __shared__ __align__(16) __half dyn[];
    int tid = threadIdx.x;
    int lane = tid & 31, wid = tid >> 5;
    int wm = wid >> 2, wn = wid & 3;
    int row0 = blockIdx.y * 128, col0 = blockIdx.x * 128;
    int kb   = K / gridDim.z;
    int kbeg = blockIdx.z * kb;
    float* Cz = C + (size_t)blockIdx.z * M * N;
    int nchunk = kb / 32;

    uint32_t base = smem_u32(dyn);
    // stage s tiles: Ah, Al, Bh, Bl
    int r_ld = tid >> 2, seg = tid & 3;   // each thread: 2 rows (r_ld, r_ld+64)... no: idx scheme below

    float acc[4][4][4];
    #pragma unroll
    for (int mf = 0; mf < 4; mf++)
        #pragma unroll
        for (int nf = 0; nf < 4; nf++)
            #pragma unroll
            for (int e = 0; e < 4; e++) acc[mf][nf][e] = 0.f;

    int laneAr = lane & 15, laneAk = (lane & 16) ? 8 : 0;
    int laneBr = lane & 7,  laneBk = (lane & 8)  ? 8 : 0;

    // async load of chunk c into stage s
    auto load_stage = [&](int c, int s) {
        uint32_t sb = base + (uint32_t)s * 4 * TILEH * 2;
        #pragma unroll
        for (int i = 0; i < 2; i++) {
            int idx = tid + i * 256;
            int row = idx >> 2, sg = idx & 3;
            size_t ga = (size_t)(row0 + row) * K + kbeg + c * 32 + sg * 8;
            size_t gb = (size_t)(col0 + row) * K + kbeg + c * 32 + sg * 8;
            uint32_t so = (uint32_t)(row * PITCH + sg * 8) * 2;
            CP_ASYNC16(sb + 0 * TILEH * 2 + so, Ah + ga);
            CP_ASYNC16(sb + 1 * TILEH * 2 + so, Al + ga);
            CP_ASYNC16(sb + 2 * TILEH * 2 + so, Bth + gb);
            CP_ASYNC16(sb + 3 * TILEH * 2 + so, Btl + gb);
        }
    };

    load_stage(0, 0);
    CP_COMMIT();
    for (int c = 0; c < nchunk; c++) {
        int s = c & 1;
        if (c + 1 < nchunk) { load_stage(c + 1, s ^ 1); CP_COMMIT(); }
        if (c + 1 < nchunk) { CP_WAIT(1); } else { CP_WAIT(0); }
        __syncthreads();
        uint32_t bAh = base + (uint32_t)s * 4 * TILEH * 2;
        uint32_t bAl = bAh + TILEH * 2;
        uint32_t bBh = bAl + TILEH * 2;
        uint32_t bBl = bBh + TILEH * 2;
        #pragma unroll
        for (int ks = 0; ks < 32; ks += 16) {
            uint32_t bh[4][2], bl[4][2];
            #pragma unroll
            for (int nf = 0; nf < 4; nf++) {
                uint32_t off = (uint32_t)((wn * 32 + nf * 8 + laneBr) * PITCH
                                          + ks + laneBk) * 2;
                LDSM_X2(bh[nf][0], bh[nf][1], bBh + off);
                LDSM_X2(bl[nf][0], bl[nf][1], bBl + off);
            }
            #pragma unroll
            for (int mf = 0; mf < 4; mf++) {
                uint32_t off = (uint32_t)((wm * 64 + mf * 16 + laneAr) * PITCH
                                          + ks + laneAk) * 2;
                uint32_t ah[4], al[4];
                LDSM_X4(ah[0], ah[1], ah[2], ah[3], bAh + off);
                LDSM_X4(al[0], al[1], al[2], al[3], bAl + off);
                #pragma unroll
                for (int nf = 0; nf < 4; nf++) {
                    MMA16816(acc[mf][nf], ah, bh[nf]);
                    MMA16816(acc[mf][nf], ah, bl[nf]);
                    MMA16816(acc[mf][nf], al, bh[nf]);
                }
            }
        }
        __syncthreads();
    }
    #pragma unroll
    for (int mf = 0; mf < 4; mf++) {
        int r = row0 + wm * 64 + mf * 16 + (lane >> 2);
        #pragma unroll
        for (int nf = 0; nf < 4; nf++) {
            int c = col0 + wn * 32 + nf * 8 + (lane & 3) * 2;
            *(float2*)(Cz + (size_t)r * N + c) =
                make_float2(acc[mf][nf][0], acc[mf][nf][1]);
            *(float2*)(Cz + (size_t)(r + 8) * N + c) =
                make_float2(acc[mf][nf][2], acc[mf][nf][3]);
        }
    }
}
#define HG_SMEM (2 * 4 * TILEH * 2)   // 81920 bytes

// ----------------------------------------------------------------------------
// Dual-output projection (precompute): Ck = A@Wk^T, Cv = A@Wv^T, A staged once.
// ----------------------------------------------------------------------------
__global__ __launch_bounds__(256)
void hgemm_dual(const __half* __restrict__ Ah, const __half* __restrict__ Al,
                const __half* __restrict__ Bkh, const __half* __restrict__ Bkl,
                const __half* __restrict__ Bvh, const __half* __restrict__ Bvl,
                float* __restrict__ Ck, float* __restrict__ Cv,
                int M, int N, int K)
{
    extern __shared__ __align__(16) __half dyn[];
    __half* sAh = dyn;
    __half* sAl = dyn + 1 * TILEH;
    __half* sKh = dyn + 2 * TILEH;
    __half* sKl = dyn + 3 * TILEH;
    __half* sVh = dyn + 4 * TILEH;
    __half* sVl = dyn + 5 * TILEH;
    int tid = threadIdx.x;
    int lane = tid & 31, wid = tid >> 5;
    int wm = wid >> 2, wn = wid & 3;
    int row0 = blockIdx.y * 128, col0 = blockIdx.x * 128;

    uint32_t bAh = smem_u32(sAh), bAl = smem_u32(sAl);
    uint32_t bKh = smem_u32(sKh), bKl = smem_u32(sKl);
    uint32_t bVh = smem_u32(sVh), bVl = smem_u32(sVl);

    float accK[4][4][4], accV[4][4][4];
    #pragma unroll
    for (int mf = 0; mf < 4; mf++)
        #pragma unroll
        for (int nf = 0; nf < 4; nf++)
            #pragma unroll
            for (int e = 0; e < 4; e++) { accK[mf][nf][e] = 0.f; accV[mf][nf][e] = 0.f; }

    int laneAr = lane & 15, laneAk = (lane & 16) ? 8 : 0;
    int laneBr = lane & 7,  laneBk = (lane & 8)  ? 8 : 0;

    for (int kc = 0; kc < K; kc += 32) {
        #pragma unroll
        for (int i = 0; i < 2; i++) {
            int idx = tid + i * 256;
            int row = idx >> 2, seg = idx & 3;
            size_t ga = (size_t)(row0 + row) * K + kc + seg * 8;
            size_t gb = (size_t)(col0 + row) * K + kc + seg * 8;
            uint32_t so = (uint32_t)(row * PITCH + seg * 8) * 2;
            CP_ASYNC16(bAh + so, Ah + ga);
            CP_ASYNC16(bAl + so, Al + ga);
            CP_ASYNC16(bKh + so, Bkh + gb);
            CP_ASYNC16(bKl + so, Bkl + gb);
            CP_ASYNC16(bVh + so, Bvh + gb);
            CP_ASYNC16(bVl + so, Bvl + gb);
        }
        CP_COMMIT();
        CP_WAIT(0);
        __syncthreads();
        #pragma unroll
        for (int ks = 0; ks < 32; ks += 16) {
            uint32_t kh[4][2], kl[4][2], vh[4][2], vl[4][2];
            #pragma unroll
            for (int nf = 0; nf < 4; nf++) {
                uint32_t off = (uint32_t)((wn * 32 + nf * 8 + laneBr) * PITCH
                                          + ks + laneBk) * 2;
                LDSM_X2(kh[nf][0], kh[nf][1], bKh + off);
                LDSM_X2(kl[nf][0], kl[nf][1], bKl + off);
                LDSM_X2(vh[nf][0], vh[nf][1], bVh + off);
                LDSM_X2(vl[nf][0], vl[nf][1], bVl + off);
            }
            #pragma unroll
            for (int mf = 0; mf < 4; mf++) {
                uint32_t off = (uint32_t)((wm * 64 + mf * 16 + laneAr) * PITCH
                                          + ks + laneAk) * 2;
                uint32_t ah[4], al[4];
                LDSM_X4(ah[0], ah[1], ah[2], ah[3], bAh + off);
                LDSM_X4(al[0], al[1], al[2], al[3], bAl + off);
                #pragma unroll
                for (int nf = 0; nf < 4; nf++) {
                    MMA16816(accK[mf][nf], ah, kh[nf]);
                    MMA16816(accK[mf][nf], ah, kl[nf]);
                    MMA16816(accK[mf][nf], al, kh[nf]);
                    MMA16816(accV[mf][nf], ah, vh[nf]);
                    MMA16816(accV[mf][nf], ah, vl[nf]);
                    MMA16816(accV[mf][nf], al, vh[nf]);
                }
            }
        }
        __syncthreads();
    }
    #pragma unroll
    for (int mf = 0; mf < 4; mf++) {
        int r = row0 + wm * 64 + mf * 16 + (lane >> 2);
        #pragma unroll
        for (int nf = 0; nf < 4; nf++) {
            int c = col0 + wn * 32 + nf * 8 + (lane & 3) * 2;
            *(float2*)(Ck + (size_t)r * N + c) =
                make_float2(accK[mf][nf][0], accK[mf][nf][1]);
            *(float2*)(Ck + (size_t)(r + 8) * N + c) =
                make_float2(accK[mf][nf][2], accK[mf][nf][3]);
            *(float2*)(Cv + (size_t)r * N + c) =
                make_float2(accV[mf][nf][0], accV[mf][nf][1]);
            *(float2*)(Cv + (size_t)(r + 8) * N + c) =
                make_float2(accV[mf][nf][2], accV[mf][nf][3]);
        }
    }
}
#define DUAL_SMEM (6 * TILEH * 2)   // 61440

// ----------------------------------------------------------------------------
// W1 + GLU fused: u = A@W1u^T, g = A@W1g^T (W1t rows n and n+INNER),
// out = fp16 hi/lo of u*silu(g), written to inn[M, INNER].
// ----------------------------------------------------------------------------
__global__ __launch_bounds__(256)
void hgemm_glu(const __half* __restrict__ Ah, const __half* __restrict__ Al,
               const __half* __restrict__ W1th, const __half* __restrict__ W1tl,
               __half* __restrict__ Ih, __half* __restrict__ Il, int M)
{
    extern __shared__ __align__(16) __half dyn[];
    __half* sAh = dyn;
    __half* sAl = dyn + 1 * TILEH;
    __half* sUh = dyn + 2 * TILEH;
    __half* sUl = dyn + 3 * TILEH;
    __half* sGh = dyn + 4 * TILEH;
    __half* sGl = dyn + 5 * TILEH;
    int tid = threadIdx.x;
    int lane = tid & 31, wid = tid >> 5;
    int wm = wid >> 2, wn = wid & 3;
    int row0 = blockIdx.y * 128, col0 = blockIdx.x * 128;

    uint32_t bAh = smem_u32(sAh), bAl = smem_u32(sAl);
    uint32_t bUh = smem_u32(sUh), bUl = smem_u32(sUl);
    uint32_t bGh = smem_u32(sGh), bGl = smem_u32(sGl);

    float accU[4][4][4], accG[4][4][4];
    #pragma unroll
    for (int mf = 0; mf < 4; mf++)
        #pragma unroll
        for (int nf = 0; nf < 4; nf++)
            #pragma unroll
            for (int e = 0; e < 4; e++) { accU[mf][nf][e] = 0.f; accG[mf][nf][e] = 0.f; }

    int laneAr = lane & 15, laneAk = (lane & 16) ? 8 : 0;
    int laneBr = lane & 7,  laneBk = (lane & 8)  ? 8 : 0;

    for (int kc = 0; kc < D; kc += 32) {
        #pragma unroll
        for (int i = 0; i < 2; i++) {
            int idx = tid + i * 256;
            int row = idx >> 2, seg = idx & 3;
            size_t ga = (size_t)(row0 + row) * D + kc + seg * 8;
            size_t gu = (size_t)(col0 + row) * D + kc + seg * 8;
            size_t gg = (size_t)(col0 + row + INNER) * D + kc + seg * 8;
            uint32_t so = (uint32_t)(row * PITCH + seg * 8) * 2;
            CP_ASYNC16(bAh + so, Ah + ga);
            CP_ASYNC16(bAl + so, Al + ga);
            CP_ASYNC16(bUh + so, W1th + gu);
            CP_ASYNC16(bUl + so, W1tl + gu);
            CP_ASYNC16(bGh + so, W1th + gg);
            CP_ASYNC16(bGl + so, W1tl + gg);
        }
        CP_COMMIT();
        CP_WAIT(0);
        __syncthreads();
        #pragma unroll
        for (int ks = 0; ks < 32; ks += 16) {
            uint32_t uh[4][2], ul[4][2], gh[4][2], gl[4][2];
            #pragma unroll
            for (int nf = 0; nf < 4; nf++) {
                uint32_t off = (uint32_t)((wn * 32 + nf * 8 + laneBr) * PITCH
                                          + ks + laneBk) * 2;
                LDSM_X2(uh[nf][0], uh[nf][1], bUh + off);
                LDSM_X2(ul[nf][0], ul[nf][1], bUl + off);
                LDSM_X2(gh[nf][0], gh[nf][1], bGh + off);
                LDSM_X2(gl[nf][0], gl[nf][1], bGl + off);
            }
            #pragma unroll
            for (int mf = 0; mf < 4; mf++) {
                uint32_t off = (uint32_t)((wm * 64 + mf * 16 + laneAr) * PITCH
                                          + ks + laneAk) * 2;
                uint32_t ah[4], al[4];
                LDSM_X4(ah[0], ah[1], ah[2], ah[3], bAh + off);
                LDSM_X4(al[0], al[1], al[2], al[3], bAl + off);
                #pragma unroll
                for (int nf = 0; nf < 4; nf++) {
                    MMA16816(accU[mf][nf], ah, uh[nf]);
                    MMA16816(accU[mf][nf], ah, ul[nf]);
                    MMA16816(accU[mf][nf], al, uh[nf]);
                    MMA16816(accG[mf][nf], ah, gh[nf]);
                    MMA16816(accG[mf][nf], ah, gl[nf]);
                    MMA16816(accG[mf][nf], al, gh[nf]);
                }
            }
        }
        __syncthreads();
    }
    #pragma unroll
    for (int mf = 0; mf < 4; mf++) {
        int r = row0 + wm * 64 + mf * 16 + (lane >> 2);
        #pragma unroll
        for (int nf = 0; nf < 4; nf++) {
            int c = col0 + wn * 32 + nf * 8 + (lane & 3) * 2;
            #pragma unroll
            for (int half_ = 0; half_ < 2; half_++) {
                int rr = r + half_ * 8;
                float u0 = accU[mf][nf][half_ * 2], u1 = accU[mf][nf][half_ * 2 + 1];
                float gg0 = accG[mf][nf][half_ * 2], gg1 = accG[mf][nf][half_ * 2 + 1];
                float v0 = u0 * (gg0 / (1.f + expf(-gg0)));
                float v1 = u1 * (gg1 / (1.f + expf(-gg1)));
                __half h0 = __float2half_rn(v0), h1 = __float2half_rn(v1);
                __half l0 = __float2half_rn(v0 - __half2float(h0));
                __half l1 = __float2half_rn(v1 - __half2float(h1));
                *(__half2*)(Ih + (size_t)rr * INNER + c) = __halves2half2(h0, h1);
                *(__half2*)(Il + (size_t)rr * INNER + c) = __halves2half2(l0, l1);
            }
        }
    }
}

// ----------------------------------------------------------------------------
// LN over D=768 emitting fp16 hi/lo
// ----------------------------------------------------------------------------
__global__ __launch_bounds__(256)
void ln_split_kernel(const float* __restrict__ in,
                     __half* __restrict__ oh, __half* __restrict__ ol,
                     const float* __restrict__ gamma, const float* __restrict__ beta)
{
    int row = blockIdx.x;
    int tid = threadIdx.x;
    const float* x = in + (size_t)row * D;
    float v0 = x[tid], v1 = x[tid + 256], v2 = x[tid + 512];
    float s = v0 + v1 + v2;
    float q = v0 * v0 + v1 * v1 + v2 * v2;
    __shared__ float sa[8], sb2[8];
    #pragma unroll
    for (int o = 16; o > 0; o >>= 1) {
        s += __shfl_down_sync(0xffffffffu, s, o);
        q += __shfl_down_sync(0xffffffffu, q, o);
    }
    int w = tid >> 5, l = tid & 31;
    if (l == 0) { sa[w] = s; sb2[w] = q; }
    __syncthreads();
    if (tid == 0) {
        float ts = 0.f, tq = 0.f;
        #pragma unroll
        for (int k = 0; k < 8; k++) { ts += sa[k]; tq += sb2[k]; }
        sa[0] = ts; sb2[0] = tq;
    }
    __syncthreads();
    float mean = sa[0] * (1.0f / D);
    float var  = sb2[0] * (1.0f / D) - mean * mean;
    float r = rsqrtf(var + 1e-5f);
    #pragma unroll
    for (int e = 0; e < 3; e++) {
        int idx = tid + e * 256;
        float val = (e == 0 ? v0 : (e == 1 ? v1 : v2));
        float y = (val - mean) * r * gamma[idx] + beta[idx];
        __half hb = __float2half_rn(y);
        __half lb = __float2half_rn(y - __half2float(hb));
        oh[(size_t)row * D + idx] = hb;
        ol[(size_t)row * D + idx] = lb;
    }
}

// transpose + fp16 hi/lo split: W[Krows, Ncols] -> T[(n_off+n)][k], T stride Krows
__global__ __launch_bounds__(256)
void wsplit_kernel(const float* __restrict__ W,
                   __half* __restrict__ Th, __half* __restrict__ Tl,
                   int Krows, int Ncols, int n_off)
{
    __shared__ float tile[32][33];
    int n0 = blockIdx.x * 32, k0 = blockIdx.y * 32;
    int t = threadIdx.x;
    int tx = t & 31, ty = t >> 5;
    #pragma unroll
    for (int i = 0; i < 4; i++)
        tile[ty + i * 8][tx] = W[(size_t)(k0 + ty + i * 8) * Ncols + n0 + tx];
    __syncthreads();
    #pragma unroll
    for (int i = 0; i < 4; i++) {
        int n = n_off + n0 + ty + i * 8;
        float v = tile[tx][ty + i * 8];
        __half hb = __float2half_rn(v);
        __half lb = __float2half_rn(v - __half2float(hb));
        Th[(size_t)n * Krows + k0 + tx] = hb;
        Tl[(size_t)n * Krows + k0 + tx] = lb;
    }
}

// ----------------------------------------------------------------------------
// LayerNorm over D=768 (fp32 out; optional add-before-norm)
// ----------------------------------------------------------------------------
__global__ __launch_bounds__(256)
void ln_kernel(const float* __restrict__ in, const float* __restrict__ add,
               float* __restrict__ out,
               const float* __restrict__ gamma, const float* __restrict__ beta)
{
    int row = blockIdx.x;
    int tid = threadIdx.x;
    const float* x = in + (size_t)row * D;
    float v0 = x[tid], v1 = x[tid + 256], v2 = x[tid + 512];
    if (add) {
        const float* a = add + (size_t)row * D;
        v0 += a[tid]; v1 += a[tid + 256]; v2 += a[tid + 512];
    }
    float s = v0 + v1 + v2;
    float q = v0 * v0 + v1 * v1 + v2 * v2;
    __shared__ float sa[8], sb2[8];
    #pragma unroll
    for (int o = 16; o > 0; o >>= 1) {
        s += __shfl_down_sync(0xffffffffu, s, o);
        q += __shfl_down_sync(0xffffffffu, q, o);
    }
    int w = tid >> 5, l = tid & 31;
    if (l == 0) { sa[w] = s; sb2[w] = q; }
    __syncthreads();
    if (tid == 0) {
        float ts = 0.f, tq = 0.f;
        #pragma unroll
        for (int k = 0; k < 8; k++) { ts += sa[k]; tq += sb2[k]; }
        sa[0] = ts; sb2[0] = tq;
    }
    __syncthreads();
    float mean = sa[0] * (1.0f / D);
    float var  = sb2[0] * (1.0f / D) - mean * mean;
    float r = rsqrtf(var + 1e-5f);
    float* o = out + (size_t)row * D;
    o[tid]       = (v0 - mean) * r * gamma[tid]       + beta[tid];
    o[tid + 256] = (v1 - mean) * r * gamma[tid + 256] + beta[tid + 256];
    o[tid + 512] = (v2 - mean) * r * gamma[tid + 512] + beta[tid + 512];
}

__global__ void init_slots_kernel(const float* __restrict__ noise,
                                  const float* __restrict__ mu,
                                  const float* __restrict__ ls,
                                  float* __restrict__ slots)
{
    int t = blockIdx.x * blockDim.x + threadIdx.x;
    if (t >= B * S * D) return;
    int d = t % D;
    slots[t] = mu[d] + expf(ls[d]) * noise[t];
}

// reduce split-K partials (+ optional residual)
template <bool HAS_RES>
__global__ void reduce_split(const float* __restrict__ part,
                             const float* __restrict__ Res,
                             float* __restrict__ C, int MN, int nsplit)
{
    int t = blockIdx.x * blockDim.x + threadIdx.x;
    if (t * 4 >= MN) return;
    float4 s = ((const float4*)part)[t];
    for (int sp = 1; sp < nsplit; sp++) {
        float4 v = ((const float4*)(part + (size_t)sp * MN))[t];
        s.x += v.x; s.y += v.y; s.z += v.z; s.w += v.w;
    }
    if (HAS_RES) {
        float4 r = ((const float4*)Res)[t];
        s.x += r.x; s.y += r.y; s.z += r.z; s.w += r.w;
    }
    ((float4*)C)[t] = s;
}

// ----------------------------------------------------------------------------
// dots + softmax over the slot axis, fused (attn left key-unnormalized)
// ----------------------------------------------------------------------------
__global__ __launch_bounds__(256)
void dots_softmax_kernel(const float* __restrict__ Q, const float* __restrict__ Kb,
                         float* __restrict__ attn)
{
    int b  = blockIdx.y;
    int j0 = blockIdx.x * 64;
    __shared__ __align__(16) float qs[16][64];
    __shared__ float ks[64][65];
    __shared__ float red[4][64];
    int tid = threadIdx.x;
    int tx = tid & 63, ty = tid >> 6;
    float acc[4] = {0.f, 0.f, 0.f, 0.f};
    const float* Qb = Q  + (size_t)b * S * D;
    const float* Kp = Kb + ((size_t)b * NK + j0) * D;
    for (int k0 = 0; k0 < D; k0 += 64) {
        {
            int i = tid >> 4, kc = (tid & 15) * 4;
            *(float4*)&qs[i][kc] = *(const float4*)&Qb[(size_t)i * D + k0 + kc];
        }
        #pragma unroll
        for (int p = 0; p < 4; p++) {
            int e = tid + p * 256;
            int jj = e >> 4, kc = (e & 15) * 4;
            float4 v = *(const float4*)&Kp[(size_t)jj * D + k0 + kc];
            ks[jj][kc + 0] = v.x; ks[jj][kc + 1] = v.y;
            ks[jj][kc + 2] = v.z; ks[jj][kc + 3] = v.w;
        }
        __syncthreads();
        #pragma unroll
        for (int kk = 0; kk < 64; kk++) {
            float kv = ks[tx][kk];
            acc[0] += qs[ty     ][kk] * kv;
            acc[1] += qs[ty +  4][kk] * kv;
            acc[2] += qs[ty +  8][kk] * kv;
            acc[3] += qs[ty + 12][kk] * kv;
        }
        __syncthreads();
    }
    #pragma unroll
    for (int r = 0; r < 4; r++) acc[r] *= kSCALE;
    float m = fmaxf(fmaxf(acc[0], acc[1]), fmaxf(acc[2], acc[3]));
    red[ty][tx] = m;
    __syncthreads();
    float M = fmaxf(fmaxf(red[0][tx], red[1][tx]), fmaxf(red[2][tx], red[3][tx]));
    __syncthreads();
    float e[4]; float s = 0.f;
    #pragma unroll
    for (int r = 0; r < 4; r++) { e[r] = expf(acc[r] - M); s += e[r]; }
    red[ty][tx] = s;
    __syncthreads();
    float Ssum = red[0][tx] + red[1][tx] + red[2][tx] + red[3][tx];
    float inv = 1.f / Ssum;
    #pragma unroll
    for (int r = 0; r < 4; r++)
        attn[((size_t)b * S + ty + r * 4) * NK + j0 + tx] = e[r] * inv + 1e-8f;
}

// updates[b,i,n] = sum_j attn[b,i,j] * v[b,j,n] / sum_j attn[b,i,j]
__global__ __launch_bounds__(256)
void updates_kernel(const float* __restrict__ attn, const float* __restrict__ V,
                    float* __restrict__ upd)
{
    int b  = blockIdx.y;
    int n0 = blockIdx.x * 64;
    __shared__ __align__(16) float as_[16][64];
    __shared__ __align__(16) float vs[64][64];
    int tid = threadIdx.x;
    int tx = tid & 63, ty = tid >> 6;
    float acc[4] = {0.f, 0.f, 0.f, 0.f};
    float ssum[4] = {0.f, 0.f, 0.f, 0.f};
    for (int j0 = 0; j0 < NK; j0 += 64) {
        {
            int i = tid >> 4, jc = (tid & 15) * 4;
            *(float4*)&as_[i][jc] =
                *(const float4*)&attn[((size_t)b * S + i) * NK + j0 + jc];
        }
        #pragma unroll
        for (int p = 0; p < 4; p++) {
            int e = tid + p * 256;
            int jj = e >> 4, nc = (e & 15) * 4;
            *(float4*)&vs[jj][nc] =
                *(const float4*)&V[((size_t)b * NK + j0 + jj) * D + n0 + nc];
        }
        __syncthreads();
        #pragma unroll
        for (int jj = 0; jj < 64; jj++) {
            float vv = vs[jj][tx];
            float a0 = as_[ty][jj], a1 = as_[ty + 4][jj];
            float a2 = as_[ty + 8][jj], a3 = as_[ty + 12][jj];
            acc[0] += a0 * vv;  ssum[0] += a0;
            acc[1] += a1 * vv;  ssum[1] += a1;
            acc[2] += a2 * vv;  ssum[2] += a2;
            acc[3] += a3 * vv;  ssum[3] += a3;
        }
        __syncthreads();
    }
    #pragma unroll
    for (int r = 0; r < 4; r++)
        upd[((size_t)b * S + ty + r * 4) * D + n0 + tx] = acc[r] / ssum[r];
}

// encoder self-attention; q/k/v packed in one [MS, 1536] buffer
__global__ __launch_bounds__(256)
void enc_attn_kernel(const float* __restrict__ QKV,
                     __half* __restrict__ Oh, __half* __restrict__ Ol)
{
    int b = blockIdx.x >> 3, h = blockIdx.x & 7;
    __shared__ float qs[16][65], ks[16][65], vs[16][65];
    __shared__ float p[16][17];
    int tid = threadIdx.x;
    int i = tid >> 4, jj = tid & 15;
    {
        int r = tid >> 4, c = (tid & 15) * 4;
        size_t base = ((size_t)b * S + r) * QKV3 + h * DH + c;
        float4 v;
        v = *(const float4*)&QKV[base];
        qs[r][c] = v.x; qs[r][c+1] = v.y; qs[r][c+2] = v.z; qs[r][c+3] = v.w;
        v = *(const float4*)&QKV[base + HD];
        ks[r][c] = v.x; ks[r][c+1] = v.y; ks[r][c+2] = v.z; ks[r][c+3] = v.w;
        v = *(const float4*)&QKV[base + 2 * HD];
        vs[r][c] = v.x; vs[r][c+1] = v.y; vs[r][c+2] = v.z; vs[r][c+3] = v.w;
    }
    __syncthreads();
    float s = 0.f;
    #pragma unroll
    for (int d = 0; d < DH; d++) s += qs[i][d] * ks[jj][d];
    s *= 0.125f;
    p[i][jj] = s;
    __syncthreads();
    float m = -1e30f;
    #pragma unroll
    for (int t2 = 0; t2 < 16; t2++) m = fmaxf(m, p[i][t2]);
    __syncthreads();
    float e = expf(s - m);
    p[i][jj] = e;
    __syncthreads();
    float sum = 0.f;
    #pragma unroll
    for (int t2 = 0; t2 < 16; t2++) sum += p[i][t2];
    __syncthreads();
    p[i][jj] = e / sum;
    __syncthreads();
    int io = tid >> 4, dbase = (tid & 15) * 4;
    float o[4] = {0.f, 0.f, 0.f, 0.f};
    #pragma unroll
    for (int t2 = 0; t2 < 16; t2++) {
        float pp = p[io][t2];
        o[0] += pp * vs[t2][dbase + 0];
        o[1] += pp * vs[t2][dbase + 1];
        o[2] += pp * vs[t2][dbase + 2];
        o[3] += pp * vs[t2][dbase + 3];
    }
    size_t base = ((size_t)b * S + io) * HD + h * DH + dbase;
    #pragma unroll
    for (int c = 0; c < 4; c++) {
        __half hb = __float2half_rn(o[c]);
        Oh[base + c] = hb;
        Ol[base + c] = __float2half_rn(o[c] - __half2float(hb));
    }
}

// per-(b,i) key-sum of attn (for the output map only)
__global__ __launch_bounds__(256)
void attn_sums_kernel(const float* __restrict__ attn, float* __restrict__ sums)
{
    int row = blockIdx.x;
    const float4* p = (const float4*)(attn + (size_t)row * NK);
    int tid = threadIdx.x;
    float4 v = p[tid];
    float s = v.x + v.y + v.z + v.w;
    __shared__ float sa[8];
    #pragma unroll
    for (int o = 16; o > 0; o >>= 1) s += __shfl_down_sync(0xffffffffu, s, o);
    int w = tid >> 5, l = tid & 31;
    if (l == 0) sa[w] = s;
    __syncthreads();
    if (tid == 0) {
        float ts = 0.f;
        #pragma unroll
        for (int k = 0; k < 8; k++) ts += sa[k];
        sums[row] = ts;
    }
}

__global__ void write_attn_kernel(const float* __restrict__ attn,
                                  const float* __restrict__ sums,
                                  float* __restrict__ out)
{
    int t = blockIdx.x * blockDim.x + threadIdx.x;
    if (t >= B * NK * S) return;
    int i = t & 15, j = (t >> 4) & (NK - 1), b = t >> 14;
    out[t] = attn[((size_t)b * S + i) * NK + j] / sums[b * S + i];
}

// ----------------------------------------------------------------------------
// Host orchestration
// ----------------------------------------------------------------------------
extern "C" void kernel_launch(void* const* d_in, const int* in_sizes, int n_in,
                              void* d_out, int out_size)
{
    const float* x       = (const float*)d_in[0];
    const float* noise   = (const float*)d_in[1];
    const float* init_mu = (const float*)d_in[2];
    const float* init_ls = (const float*)d_in[3];
    const float* Wk      = (const float*)d_in[4];
    const float* Wv      = (const float*)d_in[5];
    const float* Wq      = (const float*)d_in[6];
    const float* ni_g    = (const float*)d_in[7];
    const float* ni_b    = (const float*)d_in[8];
    const float* ns_g    = (const float*)d_in[9];
    const float* ns_b    = (const float*)d_in[10];
    const float* nica_g  = (const float*)d_in[11];
    const float* nica_b  = (const float*)d_in[12];
    const float* ln1_g   = (const float*)d_in[13];
    const float* ln1_b   = (const float*)d_in[14];
    const float* Wq_a    = (const float*)d_in[15];
    const float* Wk_a    = (const float*)d_in[16];
    const float* Wv_a    = (const float*)d_in[17];
    const float* Wo_a    = (const float*)d_in[18];
    const float* ln2_g   = (const float*)d_in[19];
    const float* ln2_b   = (const float*)d_in[20];
    const float* W1      = (const float*)d_in[21];
    const float* W2      = (const float*)d_in[22];
    const float* lnf_g   = (const float*)d_in[23];
    const float* lnf_b   = (const float*)d_in[24];

    __half *xnh, *xnl, *wkh, *wkl, *wvh, *wvl, *wqh, *wql;
    __half *wqkh, *wqkl, *woh, *wol, *w1h, *w1l, *w2h, *w2l;
    __half *qnh, *qnl, *abh, *abl, *fbh, *fbl, *innh, *innl, *oah, *oal;
    float *kb, *vb, *slots, *qb, *attn, *sums, *upd, *hb, *qkv, *part;
    cudaGetSymbolAddress((void**)&xnh,  g_xnh);  cudaGetSymbolAddress((void**)&xnl,  g_xnl);
    cudaGetSymbolAddress((void**)&wkh,  g_wkh);  cudaGetSymbolAddress((void**)&wkl,  g_wkl);
    cudaGetSymbolAddress((void**)&wvh,  g_wvh);  cudaGetSymbolAddress((void**)&wvl,  g_wvl);
    cudaGetSymbolAddress((void**)&wqh,  g_wqh);  cudaGetSymbolAddress((void**)&wql,  g_wql);
    cudaGetSymbolAddress((void**)&wqkh, g_wqkh); cudaGetSymbolAddress((void**)&wqkl, g_wqkl);
    cudaGetSymbolAddress((void**)&woh,  g_woh);  cudaGetSymbolAddress((void**)&wol,  g_wol);
    cudaGetSymbolAddress((void**)&w1h,  g_w1h);  cudaGetSymbolAddress((void**)&w1l,  g_w1l);
    cudaGetSymbolAddress((void**)&w2h,  g_w2h);  cudaGetSymbolAddress((void**)&w2l,  g_w2l);
    cudaGetSymbolAddress((void**)&qnh,  g_qnh);  cudaGetSymbolAddress((void**)&qnl,  g_qnl);
    cudaGetSymbolAddress((void**)&abh,  g_abh);  cudaGetSymbolAddress((void**)&abl,  g_abl);
    cudaGetSymbolAddress((void**)&fbh,  g_fbh);  cudaGetSymbolAddress((void**)&fbl,  g_fbl);
    cudaGetSymbolAddress((void**)&innh, g_innh); cudaGetSymbolAddress((void**)&innl, g_innl);
    cudaGetSymbolAddress((void**)&oah,  g_oah);  cudaGetSymbolAddress((void**)&oal,  g_oal);
    cudaGetSymbolAddress((void**)&kb,   g_k);
    cudaGetSymbolAddress((void**)&vb,   g_v);
    cudaGetSymbolAddress((void**)&slots,g_slots);
    cudaGetSymbolAddress((void**)&qb,   g_q);
    cudaGetSymbolAddress((void**)&attn, g_attn);
    cudaGetSymbolAddress((void**)&sums, g_sums);
    cudaGetSymbolAddress((void**)&upd,  g_upd);
    cudaGetSymbolAddress((void**)&hb,   g_h);
    cudaGetSymbolAddress((void**)&qkv,  g_qkv);
    cudaGetSymbolAddress((void**)&part, g_part);

    cudaFuncSetAttribute(hgemm_hilo, cudaFuncAttributeMaxDynamicSharedMemorySize, HG_SMEM);
    cudaFuncSetAttribute(hgemm_dual, cudaFuncAttributeMaxDynamicSharedMemorySize, DUAL_SMEM);
    cudaFuncSetAttribute(hgemm_glu,  cudaFuncAttributeMaxDynamicSharedMemorySize, DUAL_SMEM);

    const int MS = B * S;            // 512

    // ---- precompute ----
    ln_split_kernel<<<B * NK, 256>>>(x, xnh, xnl, ni_g, ni_b);
    wsplit_kernel<<<dim3(D / 32, D / 32), 256>>>(Wk, wkh, wkl, D, D, 0);
    wsplit_kernel<<<dim3(D / 32, D / 32), 256>>>(Wv, wvh, wvl, D, D, 0);
    wsplit_kernel<<<dim3(D / 32, D / 32), 256>>>(Wq, wqh, wql, D, D, 0);
    wsplit_kernel<<<dim3(HD / 32, D / 32), 256>>>(Wq_a, wqkh, wqkl, D, HD, 0);
    wsplit_kernel<<<dim3(HD / 32, D / 32), 256>>>(Wk_a, wqkh, wqkl, D, HD, HD);
    wsplit_kernel<<<dim3(HD / 32, D / 32), 256>>>(Wv_a, wqkh, wqkl, D, HD, 2 * HD);
    wsplit_kernel<<<dim3(D / 32, HD / 32), 256>>>(Wo_a, woh, wol, HD, D, 0);
    wsplit_kernel<<<dim3((2 * INNER) / 32, D / 32), 256>>>(W1, w1h, w1l, D, 2 * INNER, 0);
    wsplit_kernel<<<dim3(D / 32, INNER / 32), 256>>>(W2, w2h, w2l, INNER, D, 0);
    hgemm_dual<<<dim3(D / 128, (B * NK) / 128), 256, DUAL_SMEM>>>(
        xnh, xnl, wkh, wkl, wvh, wvl, kb, vb, B * NK, D, D);
    init_slots_kernel<<<(MS * D + 255) / 256, 256>>>(noise, init_mu, init_ls, slots);

    // ---- 4 slot-attention steps ----
    for (int it = 0; it < N_STEPS; it++) {
        ln_split_kernel<<<MS, 256>>>(slots, qnh, qnl, ns_g, ns_b);
        hgemm_hilo<<<dim3(D / 128, MS / 128, 4), 256, HG_SMEM>>>(qnh, qnl, wqh, wql,
                                                                 part, MS, D, D);
        reduce_split<false><<<(MS * D / 4 + 255) / 256, 256>>>(part, nullptr, qb, MS * D, 4);

        dots_softmax_kernel<<<dim3(NK / 64, B), 256>>>(qb, kb, attn);
        updates_kernel<<<dim3(D / 64, B), 256>>>(attn, vb, upd);
        ln_kernel<<<MS, 256>>>(slots, upd, hb, nica_g, nica_b);

        // encoder attention (fused QKV, N=1536)
        ln_split_kernel<<<MS, 256>>>(hb, abh, abl, ln1_g, ln1_b);
        hgemm_hilo<<<dim3(QKV3 / 128, MS / 128, 4), 256, HG_SMEM>>>(abh, abl, wqkh, wqkl,
                                                                    part, MS, QKV3, D);
        reduce_split<false><<<(MS * QKV3 / 4 + 255) / 256, 256>>>(part, nullptr, qkv,
                                                                  MS * QKV3, 4);
        enc_attn_kernel<<<B * H, 256>>>(qkv, oah, oal);
        hgemm_hilo<<<dim3(D / 128, MS / 128, 4), 256, HG_SMEM>>>(oah, oal, woh, wol,
                                                                 part, MS, D, HD);
        reduce_split<true><<<(MS * D / 4 + 255) / 256, 256>>>(part, hb, hb, MS * D, 4);

        // GLU feed-forward (fused W1+GLU, then W2)
        ln_split_kernel<<<MS, 256>>>(hb, fbh, fbl, ln2_g, ln2_b);
        hgemm_glu<<<dim3(INNER / 128, MS / 128), 256, DUAL_SMEM>>>(fbh, fbl, w1h, w1l,
                                                                   innh, innl, MS);
        hgemm_hilo<<<dim3(D / 128, MS / 128, 4), 256, HG_SMEM>>>(innh, innl, w2h, w2l,
                                                                 part, MS, D, INNER);
        reduce_split<true><<<(MS * D / 4 + 255) / 256, 256>>>(part, hb, hb, MS * D, 4);
        ln_kernel<<<MS, 256>>>(hb, nullptr, slots, lnf_g, lnf_b);
    }

    // ---- outputs: slots [32,16,768], then attn_map [32,1024,16] ----
    float* out = (float*)d_out;
    cudaMemcpyAsync(out, slots, (size_t)MS * D * sizeof(float),
                    cudaMemcpyDeviceToDevice);
    attn_sums_kernel<<<MS, 256>>>(attn, sums);
    write_attn_kernel<<<(B * NK * S + 255) / 256, 256>>>(attn, sums,
                                                         out + (size_t)MS * D);
}

// round 7
// speedup vs baseline: 4.3045x; 1.0764x over previous
#include <cuda_runtime.h>
#include <cuda_fp16.h>
#include <math.h>
#include <stdint.h>

// ----------------------------------------------------------------------------
// Problem constants
// ----------------------------------------------------------------------------
#define B   32
#define NK  1024
#define S   16
#define D   768
#define H   8
#define DH  64
#define HD  (H*DH)    // 512
#define QKV3 (3*HD)   // 1536
#define INNER 3072
#define N_STEPS 4
#define MS  (B*S)     // 512
static __device__ __constant__ float kSCALE = 0.036084391824351615f;  // 768^-0.5

// ----------------------------------------------------------------------------
// Scratch (device globals)
// ----------------------------------------------------------------------------
__device__ __half g_xnh[B*NK*D], g_xnl[B*NK*D];
__device__ __half g_wkh [D*D],        g_wkl [D*D];
__device__ __half g_wvh [D*D],        g_wvl [D*D];
__device__ __half g_wqh [D*D],        g_wql [D*D];
__device__ __half g_wqkh[QKV3*D],     g_wqkl[QKV3*D];
__device__ __half g_woh [D*HD],       g_wol [D*HD];
__device__ __half g_w1h [2*INNER*D],  g_w1l [2*INNER*D];
__device__ __half g_w2h [D*INNER],    g_w2l [D*INNER];
__device__ __half g_qnh[MS*D],   g_qnl[MS*D];
__device__ __half g_abh[MS*D],   g_abl[MS*D];
__device__ __half g_fbh[MS*D],   g_fbl[MS*D];
__device__ __half g_innh[MS*INNER], g_innl[MS*INNER];
__device__ __half g_oah[MS*HD],  g_oal[MS*HD];
__device__ float g_k    [B*NK*D];
__device__ float g_v    [B*NK*D];
__device__ float g_slots[MS*D];
__device__ float g_attn [MS*NK];
__device__ float g_sums [MS];
__device__ float g_upd  [MS*D];
__device__ float g_h    [MS*D];
__device__ float g_part [4*MS*QKV3];

// ----------------------------------------------------------------------------
// HMMA / cp.async helpers (baseline PTX — compiles for plain compute_103)
// ----------------------------------------------------------------------------
__device__ __forceinline__ uint32_t smem_u32(const void* p) {
    uint32_t a;
    asm("{ .reg .u64 t; cvta.to.shared.u64 t, %1; cvt.u32.u64 %0, t; }"
        : "=r"(a) : "l"(p));
    return a;
}
#define LDSM_X4(r0, r1, r2, r3, addr) \
    asm volatile("ldmatrix.sync.aligned.m8n8.x4.shared.b16 {%0,%1,%2,%3}, [%4];" \
                 : "=r"(r0), "=r"(r1), "=r"(r2), "=r"(r3) : "r"(addr))
#define LDSM_X2(r0, r1, addr) \
    asm volatile("ldmatrix.sync.aligned.m8n8.x2.shared.b16 {%0,%1}, [%2];" \
                 : "=r"(r0), "=r"(r1) : "r"(addr))
#define MMA16816(c, a, b) \
    asm volatile("mma.sync.aligned.m16n8k16.row.col.f32.f16.f16.f32 " \
                 "{%0,%1,%2,%3}, {%4,%5,%6,%7}, {%8,%9}, {%0,%1,%2,%3};" \
                 : "+f"((c)[0]), "+f"((c)[1]), "+f"((c)[2]), "+f"((c)[3]) \
                 : "r"((a)[0]), "r"((a)[1]), "r"((a)[2]), "r"((a)[3]), \
                   "r"((b)[0]), "r"((b)[1]))
#define CP_ASYNC16(dst_u32, src_ptr) \
    asm volatile("cp.async.ca.shared.global [%0], [%1], 16;" \
                 :: "r"(dst_u32), "l"(src_ptr))
#define CP_COMMIT() asm volatile("cp.async.commit_group;" ::: "memory")
#define CP_WAIT(n)  asm volatile("cp.async.wait_group %0;" :: "n"(n) : "memory")

#define PITCH 40            // halves per smem row (80 B) — conflict-free ldmatrix
#define TILEH (128 * PITCH) // halves per tile
#define TILEB (TILEH * 2)   // bytes per tile

// ----------------------------------------------------------------------------
// fp16 hi/lo HMMA GEMM, split-K, 2-stage cp.async double buffer.
// ----------------------------------------------------------------------------
__global__ __launch_bounds__(256)
void hgemm_hilo(const __half* __restrict__ Ah, const __half* __restrict__ Al,
                const __half* __restrict__ Bth, const __half* __restrict__ Btl,
                float* __restrict__ C, int M, int N, int K)
{
    extern __shared__ __align__(16) __half dyn[];
    int tid = threadIdx.x;
    int lane = tid & 31, wid = tid >> 5;
    int wm = wid >> 2, wn = wid & 3;
    int row0 = blockIdx.y * 128, col0 = blockIdx.x * 128;
    int kb   = K / gridDim.z;
    int kbeg = blockIdx.z * kb;
    float* Cz = C + (size_t)blockIdx.z * M * N;
    int nchunk = kb / 32;

    uint32_t base = smem_u32(dyn);

    float acc[4][4][4];
    #pragma unroll
    for (int mf = 0; mf < 4; mf++)
        #pragma unroll
        for (int nf = 0; nf < 4; nf++)
            #pragma unroll
            for (int e = 0; e < 4; e++) acc[mf][nf][e] = 0.f;

    int laneAr = lane & 15, laneAk = (lane & 16) ? 8 : 0;
    int laneBr = lane & 7,  laneBk = (lane & 8)  ? 8 : 0;

    auto load_stage = [&](int c, int s) {
        uint32_t sb = base + (uint32_t)s * 4 * TILEB;
        #pragma unroll
        for (int i = 0; i < 2; i++) {
            int idx = tid + i * 256;
            int row = idx >> 2, sg = idx & 3;
            size_t ga = (size_t)(row0 + row) * K + kbeg + c * 32 + sg * 8;
            size_t gb = (size_t)(col0 + row) * K + kbeg + c * 32 + sg * 8;
            uint32_t so = (uint32_t)(row * PITCH + sg * 8) * 2;
            CP_ASYNC16(sb + 0 * TILEB + so, Ah + ga);
            CP_ASYNC16(sb + 1 * TILEB + so, Al + ga);
            CP_ASYNC16(sb + 2 * TILEB + so, Bth + gb);
            CP_ASYNC16(sb + 3 * TILEB + so, Btl + gb);
        }
    };

    load_stage(0, 0);
    CP_COMMIT();
    for (int c = 0; c < nchunk; c++) {
        int s = c & 1;
        if (c + 1 < nchunk) { load_stage(c + 1, s ^ 1); CP_COMMIT(); CP_WAIT(1); }
        else                { CP_WAIT(0); }
        __syncthreads();
        uint32_t bAh = base + (uint32_t)s * 4 * TILEB;
        uint32_t bAl = bAh + TILEB;
        uint32_t bBh = bAl + TILEB;
        uint32_t bBl = bBh + TILEB;
        #pragma unroll
        for (int ks = 0; ks < 32; ks += 16) {
            uint32_t bh[4][2], bl[4][2];
            #pragma unroll
            for (int nf = 0; nf < 4; nf++) {
                uint32_t off = (uint32_t)((wn * 32 + nf * 8 + laneBr) * PITCH
                                          + ks + laneBk) * 2;
                LDSM_X2(bh[nf][0], bh[nf][1], bBh + off);
                LDSM_X2(bl[nf][0], bl[nf][1], bBl + off);
            }
            #pragma unroll
            for (int mf = 0; mf < 4; mf++) {
                uint32_t off = (uint32_t)((wm * 64 + mf * 16 + laneAr) * PITCH
                                          + ks + laneAk) * 2;
                uint32_t ah[4], al[4];
                LDSM_X4(ah[0], ah[1], ah[2], ah[3], bAh + off);
                LDSM_X4(al[0], al[1], al[2], al[3], bAl + off);
                #pragma unroll
                for (int nf = 0; nf < 4; nf++) {
                    MMA16816(acc[mf][nf], ah, bh[nf]);
                    MMA16816(acc[mf][nf], ah, bl[nf]);
                    MMA16816(acc[mf][nf], al, bh[nf]);
                }
            }
        }
        __syncthreads();
    }
    #pragma unroll
    for (int mf = 0; mf < 4; mf++) {
        int r = row0 + wm * 64 + mf * 16 + (lane >> 2);
        #pragma unroll
        for (int nf = 0; nf < 4; nf++) {
            int c = col0 + wn * 32 + nf * 8 + (lane & 3) * 2;
            *(float2*)(Cz + (size_t)r * N + c) =
                make_float2(acc[mf][nf][0], acc[mf][nf][1]);
            *(float2*)(Cz + (size_t)(r + 8) * N + c) =
                make_float2(acc[mf][nf][2], acc[mf][nf][3]);
        }
    }
}
#define HG_SMEM (2 * 4 * TILEB)     // 81920

// ----------------------------------------------------------------------------
// Dual-output projection, 2-stage pipelined: Ck = A@Wk^T, Cv = A@Wv^T.
// ----------------------------------------------------------------------------
__global__ __launch_bounds__(256)
void hgemm_dual(const __half* __restrict__ Ah, const __half* __restrict__ Al,
                const __half* __restrict__ Bkh, const __half* __restrict__ Bkl,
                const __half* __restrict__ Bvh, const __half* __restrict__ Bvl,
                float* __restrict__ Ck, float* __restrict__ Cv,
                int M, int N, int K)
{
    extern __shared__ __align__(16) __half dyn[];
    int tid = threadIdx.x;
    int lane = tid & 31, wid = tid >> 5;
    int wm = wid >> 2, wn = wid & 3;
    int row0 = blockIdx.y * 128, col0 = blockIdx.x * 128;
    int nchunk = K / 32;
    uint32_t base = smem_u32(dyn);

    float accK[4][4][4], accV[4][4][4];
    #pragma unroll
    for (int mf = 0; mf < 4; mf++)
        #pragma unroll
        for (int nf = 0; nf < 4; nf++)
            #pragma unroll
            for (int e = 0; e < 4; e++) { accK[mf][nf][e] = 0.f; accV[mf][nf][e] = 0.f; }

    int laneAr = lane & 15, laneAk = (lane & 16) ? 8 : 0;
    int laneBr = lane & 7,  laneBk = (lane & 8)  ? 8 : 0;

    auto load_stage = [&](int c, int s) {
        uint32_t sb = base + (uint32_t)s * 6 * TILEB;
        #pragma unroll
        for (int i = 0; i < 2; i++) {
            int idx = tid + i * 256;
            int row = idx >> 2, sg = idx & 3;
            size_t ga = (size_t)(row0 + row) * K + c * 32 + sg * 8;
            size_t gb = (size_t)(col0 + row) * K + c * 32 + sg * 8;
            uint32_t so = (uint32_t)(row * PITCH + sg * 8) * 2;
            CP_ASYNC16(sb + 0 * TILEB + so, Ah + ga);
            CP_ASYNC16(sb + 1 * TILEB + so, Al + ga);
            CP_ASYNC16(sb + 2 * TILEB + so, Bkh + gb);
            CP_ASYNC16(sb + 3 * TILEB + so, Bkl + gb);
            CP_ASYNC16(sb + 4 * TILEB + so, Bvh + gb);
            CP_ASYNC16(sb + 5 * TILEB + so, Bvl + gb);
        }
    };

    load_stage(0, 0);
    CP_COMMIT();
    for (int c = 0; c < nchunk; c++) {
        int s = c & 1;
        if (c + 1 < nchunk) { load_stage(c + 1, s ^ 1); CP_COMMIT(); CP_WAIT(1); }
        else                { CP_WAIT(0); }
        __syncthreads();
        uint32_t bAh = base + (uint32_t)s * 6 * TILEB;
        uint32_t bAl = bAh + TILEB;
        uint32_t bKh = bAl + TILEB;
        uint32_t bKl = bKh + TILEB;
        uint32_t bVh = bKl + TILEB;
        uint32_t bVl = bVh + TILEB;
        #pragma unroll
        for (int ks = 0; ks < 32; ks += 16) {
            uint32_t kh[4][2], kl[4][2], vh[4][2], vl[4][2];
            #pragma unroll
            for (int nf = 0; nf < 4; nf++) {
                uint32_t off = (uint32_t)((wn * 32 + nf * 8 + laneBr) * PITCH
                                          + ks + laneBk) * 2;
                LDSM_X2(kh[nf][0], kh[nf][1], bKh + off);
                LDSM_X2(kl[nf][0], kl[nf][1], bKl + off);
                LDSM_X2(vh[nf][0], vh[nf][1], bVh + off);
                LDSM_X2(vl[nf][0], vl[nf][1], bVl + off);
            }
            #pragma unroll
            for (int mf = 0; mf < 4; mf++) {
                uint32_t off = (uint32_t)((wm * 64 + mf * 16 + laneAr) * PITCH
                                          + ks + laneAk) * 2;
                uint32_t ah[4], al[4];
                LDSM_X4(ah[0], ah[1], ah[2], ah[3], bAh + off);
                LDSM_X4(al[0], al[1], al[2], al[3], bAl + off);
                #pragma unroll
                for (int nf = 0; nf < 4; nf++) {
                    MMA16816(accK[mf][nf], ah, kh[nf]);
                    MMA16816(accK[mf][nf], ah, kl[nf]);
                    MMA16816(accK[mf][nf], al, kh[nf]);
                    MMA16816(accV[mf][nf], ah, vh[nf]);
                    MMA16816(accV[mf][nf], ah, vl[nf]);
                    MMA16816(accV[mf][nf], al, vh[nf]);
                }
            }
        }
        __syncthreads();
    }
    #pragma unroll
    for (int mf = 0; mf < 4; mf++) {
        int r = row0 + wm * 64 + mf * 16 + (lane >> 2);
        #pragma unroll
        for (int nf = 0; nf < 4; nf++) {
            int c = col0 + wn * 32 + nf * 8 + (lane & 3) * 2;
            *(float2*)(Ck + (size_t)r * N + c) =
                make_float2(accK[mf][nf][0], accK[mf][nf][1]);
            *(float2*)(Ck + (size_t)(r + 8) * N + c) =
                make_float2(accK[mf][nf][2], accK[mf][nf][3]);
            *(float2*)(Cv + (size_t)r * N + c) =
                make_float2(accV[mf][nf][0], accV[mf][nf][1]);
            *(float2*)(Cv + (size_t)(r + 8) * N + c) =
                make_float2(accV[mf][nf][2], accV[mf][nf][3]);
        }
    }
}
#define DUAL2_SMEM (2 * 6 * TILEB)   // 122880

// ----------------------------------------------------------------------------
// W1 + GLU fused, 2-stage pipelined; emits fp16 hi/lo of u*silu(g).
// ----------------------------------------------------------------------------
__global__ __launch_bounds__(256)
void hgemm_glu(const __half* __restrict__ Ah, const __half* __restrict__ Al,
               const __half* __restrict__ W1th, const __half* __restrict__ W1tl,
               __half* __restrict__ Ih, __half* __restrict__ Il, int M)
{
    extern __shared__ __align__(16) __half dyn[];
    int tid = threadIdx.x;
    int lane = tid & 31, wid = tid >> 5;
    int wm = wid >> 2, wn = wid & 3;
    int row0 = blockIdx.y * 128, col0 = blockIdx.x * 128;
    int nchunk = D / 32;
    uint32_t base = smem_u32(dyn);

    float accU[4][4][4], accG[4][4][4];
    #pragma unroll
    for (int mf = 0; mf < 4; mf++)
        #pragma unroll
        for (int nf = 0; nf < 4; nf++)
            #pragma unroll
            for (int e = 0; e < 4; e++) { accU[mf][nf][e] = 0.f; accG[mf][nf][e] = 0.f; }

    int laneAr = lane & 15, laneAk = (lane & 16) ? 8 : 0;
    int laneBr = lane & 7,  laneBk = (lane & 8)  ? 8 : 0;

    auto load_stage = [&](int c, int s) {
        uint32_t sb = base + (uint32_t)s * 6 * TILEB;
        #pragma unroll
        for (int i = 0; i < 2; i++) {
            int idx = tid + i * 256;
            int row = idx >> 2, sg = idx & 3;
            size_t ga = (size_t)(row0 + row) * D + c * 32 + sg * 8;
            size_t gu = (size_t)(col0 + row) * D + c * 32 + sg * 8;
            size_t gg = (size_t)(col0 + row + INNER) * D + c * 32 + sg * 8;
            uint32_t so = (uint32_t)(row * PITCH + sg * 8) * 2;
            CP_ASYNC16(sb + 0 * TILEB + so, Ah + ga);
            CP_ASYNC16(sb + 1 * TILEB + so, Al + ga);
            CP_ASYNC16(sb + 2 * TILEB + so, W1th + gu);
            CP_ASYNC16(sb + 3 * TILEB + so, W1tl + gu);
            CP_ASYNC16(sb + 4 * TILEB + so, W1th + gg);
            CP_ASYNC16(sb + 5 * TILEB + so, W1tl + gg);
        }
    };

    load_stage(0, 0);
    CP_COMMIT();
    for (int c = 0; c < nchunk; c++) {
        int s = c & 1;
        if (c + 1 < nchunk) { load_stage(c + 1, s ^ 1); CP_COMMIT(); CP_WAIT(1); }
        else                { CP_WAIT(0); }
        __syncthreads();
        uint32_t bAh = base + (uint32_t)s * 6 * TILEB;
        uint32_t bAl = bAh + TILEB;
        uint32_t bUh = bAl + TILEB;
        uint32_t bUl = bUh + TILEB;
        uint32_t bGh = bUl + TILEB;
        uint32_t bGl = bGh + TILEB;
        #pragma unroll
        for (int ks = 0; ks < 32; ks += 16) {
            uint32_t uh[4][2], ul[4][2], gh[4][2], gl[4][2];
            #pragma unroll
            for (int nf = 0; nf < 4; nf++) {
                uint32_t off = (uint32_t)((wn * 32 + nf * 8 + laneBr) * PITCH
                                          + ks + laneBk) * 2;
                LDSM_X2(uh[nf][0], uh[nf][1], bUh + off);
                LDSM_X2(ul[nf][0], ul[nf][1], bUl + off);
                LDSM_X2(gh[nf][0], gh[nf][1], bGh + off);
                LDSM_X2(gl[nf][0], gl[nf][1], bGl + off);
            }
            #pragma unroll
            for (int mf = 0; mf < 4; mf++) {
                uint32_t off = (uint32_t)((wm * 64 + mf * 16 + laneAr) * PITCH
                                          + ks + laneAk) * 2;
                uint32_t ah[4], al[4];
                LDSM_X4(ah[0], ah[1], ah[2], ah[3], bAh + off);
                LDSM_X4(al[0], al[1], al[2], al[3], bAl + off);
                #pragma unroll
                for (int nf = 0; nf < 4; nf++) {
                    MMA16816(accU[mf][nf], ah, uh[nf]);
                    MMA16816(accU[mf][nf], ah, ul[nf]);
                    MMA16816(accU[mf][nf], al, uh[nf]);
                    MMA16816(accG[mf][nf], ah, gh[nf]);
                    MMA16816(accG[mf][nf], ah, gl[nf]);
                    MMA16816(accG[mf][nf], al, gh[nf]);
                }
            }
        }
        __syncthreads();
    }
    #pragma unroll
    for (int mf = 0; mf < 4; mf++) {
        int r = row0 + wm * 64 + mf * 16 + (lane >> 2);
        #pragma unroll
        for (int nf = 0; nf < 4; nf++) {
            int c = col0 + wn * 32 + nf * 8 + (lane & 3) * 2;
            #pragma unroll
            for (int half_ = 0; half_ < 2; half_++) {
                int rr = r + half_ * 8;
                float u0 = accU[mf][nf][half_ * 2], u1 = accU[mf][nf][half_ * 2 + 1];
                float gg0 = accG[mf][nf][half_ * 2], gg1 = accG[mf][nf][half_ * 2 + 1];
                float v0 = u0 * (gg0 / (1.f + expf(-gg0)));
                float v1 = u1 * (gg1 / (1.f + expf(-gg1)));
                __half h0 = __float2half_rn(v0), h1 = __float2half_rn(v1);
                __half l0 = __float2half_rn(v0 - __half2float(h0));
                __half l1 = __float2half_rn(v1 - __half2float(h1));
                *(__half2*)(Ih + (size_t)rr * INNER + c) = __halves2half2(h0, h1);
                *(__half2*)(Il + (size_t)rr * INNER + c) = __halves2half2(l0, l1);
            }
        }
    }
}

// ----------------------------------------------------------------------------
// LN reduction helper (256 threads over D=768)
// ----------------------------------------------------------------------------
__device__ __forceinline__ void ln_stats(float v0, float v1, float v2,
                                         float* sa, float* sb2,
                                         float& mean, float& rinv)
{
    float s = v0 + v1 + v2;
    float q = v0 * v0 + v1 * v1 + v2 * v2;
    int tid = threadIdx.x;
    #pragma unroll
    for (int o = 16; o > 0; o >>= 1) {
        s += __shfl_down_sync(0xffffffffu, s, o);
        q += __shfl_down_sync(0xffffffffu, q, o);
    }
    int w = tid >> 5, l = tid & 31;
    if (l == 0) { sa[w] = s; sb2[w] = q; }
    __syncthreads();
    if (tid == 0) {
        float ts = 0.f, tq = 0.f;
        #pragma unroll
        for (int k = 0; k < 8; k++) { ts += sa[k]; tq += sb2[k]; }
        sa[0] = ts; sb2[0] = tq;
    }
    __syncthreads();
    mean = sa[0] * (1.0f / D);
    float var = sb2[0] * (1.0f / D) - mean * mean;
    rinv = rsqrtf(var + 1e-5f);
    __syncthreads();
}

// LN(x) -> fp16 hi/lo
__global__ __launch_bounds__(256)
void ln_split_kernel(const float* __restrict__ in,
                     __half* __restrict__ oh, __half* __restrict__ ol,
                     const float* __restrict__ gamma, const float* __restrict__ beta)
{
    int row = blockIdx.x, tid = threadIdx.x;
    const float* x = in + (size_t)row * D;
    float v[3] = {x[tid], x[tid + 256], x[tid + 512]};
    __shared__ float sa[8], sb2[8];
    float mean, r;
    ln_stats(v[0], v[1], v[2], sa, sb2, mean, r);
    #pragma unroll
    for (int e = 0; e < 3; e++) {
        int idx = tid + e * 256;
        float y = (v[e] - mean) * r * gamma[idx] + beta[idx];
        __half hb = __float2half_rn(y);
        oh[(size_t)row * D + idx] = hb;
        ol[(size_t)row * D + idx] = __float2half_rn(y - __half2float(hb));
    }
}

// h = LN_a(slots + upd) -> hb(fp32);  LN_b(h) -> oh/ol(hi/lo)
__global__ __launch_bounds__(256)
void ln_dual_kernel(const float* __restrict__ slots, const float* __restrict__ upd,
                    float* __restrict__ hb,
                    const float* __restrict__ g1, const float* __restrict__ b1,
                    const float* __restrict__ g2, const float* __restrict__ b2,
                    __half* __restrict__ oh, __half* __restrict__ ol)
{
    int row = blockIdx.x, tid = threadIdx.x;
    const float* xs = slots + (size_t)row * D;
    const float* xu = upd + (size_t)row * D;
    float v[3];
    #pragma unroll
    for (int e = 0; e < 3; e++) v[e] = xs[tid + e * 256] + xu[tid + e * 256];
    __shared__ float sa[8], sb2[8];
    float mean, r;
    ln_stats(v[0], v[1], v[2], sa, sb2, mean, r);
    float y[3];
    #pragma unroll
    for (int e = 0; e < 3; e++) {
        int idx = tid + e * 256;
        y[e] = (v[e] - mean) * r * g1[idx] + b1[idx];
        hb[(size_t)row * D + idx] = y[e];
    }
    float mean2, r2;
    ln_stats(y[0], y[1], y[2], sa, sb2, mean2, r2);
    #pragma unroll
    for (int e = 0; e < 3; e++) {
        int idx = tid + e * 256;
        float z = (y[e] - mean2) * r2 * g2[idx] + b2[idx];
        __half hh = __float2half_rn(z);
        oh[(size_t)row * D + idx] = hh;
        ol[(size_t)row * D + idx] = __float2half_rn(z - __half2float(hh));
    }
}

// h = res + sum_{sp<4} part[sp]; res <- h; LN(h) -> oh/ol
__global__ __launch_bounds__(256)
void ln_split_red_kernel(const float* __restrict__ part, float* __restrict__ res,
                         const float* __restrict__ gamma, const float* __restrict__ beta,
                         __half* __restrict__ oh, __half* __restrict__ ol)
{
    int row = blockIdx.x, tid = threadIdx.x;
    float v[3];
    #pragma unroll
    for (int e = 0; e < 3; e++) {
        int idx = tid + e * 256;
        size_t o = (size_t)row * D + idx;
        float s = res[o];
        #pragma unroll
        for (int sp = 0; sp < 4; sp++) s += part[(size_t)sp * MS * D + o];
        v[e] = s;
        res[o] = s;
    }
    __shared__ float sa[8], sb2[8];
    float mean, r;
    ln_stats(v[0], v[1], v[2], sa, sb2, mean, r);
    #pragma unroll
    for (int e = 0; e < 3; e++) {
        int idx = tid + e * 256;
        float y = (v[e] - mean) * r * gamma[idx] + beta[idx];
        __half hb = __float2half_rn(y);
        oh[(size_t)row * D + idx] = hb;
        ol[(size_t)row * D + idx] = __float2half_rn(y - __half2float(hb));
    }
}

// h = res + sum part; slots = LN_f(h);  LN_s(slots) -> qn hi/lo (for next step)
__global__ __launch_bounds__(256)
void ln_red_dual_kernel(const float* __restrict__ part, const float* __restrict__ res,
                        float* __restrict__ slots,
                        const float* __restrict__ gf, const float* __restrict__ bf,
                        const float* __restrict__ gs, const float* __restrict__ bs,
                        __half* __restrict__ qh, __half* __restrict__ ql)
{
    int row = blockIdx.x, tid = threadIdx.x;
    float v[3];
    #pragma unroll
    for (int e = 0; e < 3; e++) {
        int idx = tid + e * 256;
        size_t o = (size_t)row * D + idx;
        float s = res[o];
        #pragma unroll
        for (int sp = 0; sp < 4; sp++) s += part[(size_t)sp * MS * D + o];
        v[e] = s;
    }
    __shared__ float sa[8], sb2[8];
    float mean, r;
    ln_stats(v[0], v[1], v[2], sa, sb2, mean, r);
    float y[3];
    #pragma unroll
    for (int e = 0; e < 3; e++) {
        int idx = tid + e * 256;
        y[e] = (v[e] - mean) * r * gf[idx] + bf[idx];
        slots[(size_t)row * D + idx] = y[e];
    }
    float mean2, r2;
    ln_stats(y[0], y[1], y[2], sa, sb2, mean2, r2);
    #pragma unroll
    for (int e = 0; e < 3; e++) {
        int idx = tid + e * 256;
        float z = (y[e] - mean2) * r2 * gs[idx] + bs[idx];
        __half hh = __float2half_rn(z);
        qh[(size_t)row * D + idx] = hh;
        ql[(size_t)row * D + idx] = __float2half_rn(z - __half2float(hh));
    }
}

// transpose + fp16 hi/lo split: W[Krows, Ncols] -> T[(n_off+n)][k], stride Krows
__global__ __launch_bounds__(256)
void wsplit_kernel(const float* __restrict__ W,
                   __half* __restrict__ Th, __half* __restrict__ Tl,
                   int Krows, int Ncols, int n_off)
{
    __shared__ float tile[32][33];
    int n0 = blockIdx.x * 32, k0 = blockIdx.y * 32;
    int t = threadIdx.x;
    int tx = t & 31, ty = t >> 5;
    #pragma unroll
    for (int i = 0; i < 4; i++)
        tile[ty + i * 8][tx] = W[(size_t)(k0 + ty + i * 8) * Ncols + n0 + tx];
    __syncthreads();
    #pragma unroll
    for (int i = 0; i < 4; i++) {
        int n = n_off + n0 + ty + i * 8;
        float v = tile[tx][ty + i * 8];
        __half hb = __float2half_rn(v);
        Th[(size_t)n * Krows + k0 + tx] = hb;
        Tl[(size_t)n * Krows + k0 + tx] = __float2half_rn(v - __half2float(hb));
    }
}

__global__ void init_slots_kernel(const float* __restrict__ noise,
                                  const float* __restrict__ mu,
                                  const float* __restrict__ ls,
                                  float* __restrict__ slots)
{
    int t = blockIdx.x * blockDim.x + threadIdx.x;
    if (t >= MS * D) return;
    int d = t % D;
    slots[t] = mu[d] + expf(ls[d]) * noise[t];
}

// ----------------------------------------------------------------------------
// dots + softmax over the slot axis, fused; reads Wq split-K partials directly
// ----------------------------------------------------------------------------
__global__ __launch_bounds__(256)
void dots_softmax_kernel(const float* __restrict__ Qpart, const float* __restrict__ Kb,
                         float* __restrict__ attn)
{
    int b  = blockIdx.y;
    int j0 = blockIdx.x * 64;
    __shared__ __align__(16) float qs[16][64];
    __shared__ float ks[64][65];
    __shared__ float red[4][64];
    int tid = threadIdx.x;
    int tx = tid & 63, ty = tid >> 6;
    float acc[4] = {0.f, 0.f, 0.f, 0.f};
    const float* Kp = Kb + ((size_t)b * NK + j0) * D;
    for (int k0 = 0; k0 < D; k0 += 64) {
        {
            int i = tid >> 4, kc = (tid & 15) * 4;
            size_t o = ((size_t)b * S + i) * D + k0 + kc;
            float4 v = *(const float4*)&Qpart[o];
            #pragma unroll
            for (int sp = 1; sp < 4; sp++) {
                float4 w = *(const float4*)&Qpart[(size_t)sp * MS * D + o];
                v.x += w.x; v.y += w.y; v.z += w.z; v.w += w.w;
            }
            *(float4*)&qs[i][kc] = v;
        }
        #pragma unroll
        for (int p = 0; p < 4; p++) {
            int e = tid + p * 256;
            int jj = e >> 4, kc = (e & 15) * 4;
            float4 v = *(const float4*)&Kp[(size_t)jj * D + k0 + kc];
            ks[jj][kc + 0] = v.x; ks[jj][kc + 1] = v.y;
            ks[jj][kc + 2] = v.z; ks[jj][kc + 3] = v.w;
        }
        __syncthreads();
        #pragma unroll
        for (int kk = 0; kk < 64; kk++) {
            float kv = ks[tx][kk];
            acc[0] += qs[ty     ][kk] * kv;
            acc[1] += qs[ty +  4][kk] * kv;
            acc[2] += qs[ty +  8][kk] * kv;
            acc[3] += qs[ty + 12][kk] * kv;
        }
        __syncthreads();
    }
    #pragma unroll
    for (int r = 0; r < 4; r++) acc[r] *= kSCALE;
    float m = fmaxf(fmaxf(acc[0], acc[1]), fmaxf(acc[2], acc[3]));
    red[ty][tx] = m;
    __syncthreads();
    float M = fmaxf(fmaxf(red[0][tx], red[1][tx]), fmaxf(red[2][tx], red[3][tx]));
    __syncthreads();
    float e[4]; float s = 0.f;
    #pragma unroll
    for (int r = 0; r < 4; r++) { e[r] = expf(acc[r] - M); s += e[r]; }
    red[ty][tx] = s;
    __syncthreads();
    float Ssum = red[0][tx] + red[1][tx] + red[2][tx] + red[3][tx];
    float inv = 1.f / Ssum;
    #pragma unroll
    for (int r = 0; r < 4; r++)
        attn[((size_t)b * S + ty + r * 4) * NK + j0 + tx] = e[r] * inv + 1e-8f;
}

// updates[b,i,n] = (sum_j attn * v) / (sum_j attn)
__global__ __launch_bounds__(256)
void updates_kernel(const float* __restrict__ attn, const float* __restrict__ V,
                    float* __restrict__ upd)
{
    int b  = blockIdx.y;
    int n0 = blockIdx.x * 64;
    __shared__ __align__(16) float as_[16][64];
    __shared__ __align__(16) float vs[64][64];
    int tid = threadIdx.x;
    int tx = tid & 63, ty = tid >> 6;
    float acc[4] = {0.f, 0.f, 0.f, 0.f};
    float ssum[4] = {0.f, 0.f, 0.f, 0.f};
    for (int j0 = 0; j0 < NK; j0 += 64) {
        {
            int i = tid >> 4, jc = (tid & 15) * 4;
            *(float4*)&as_[i][jc] =
                *(const float4*)&attn[((size_t)b * S + i) * NK + j0 + jc];
        }
        #pragma unroll
        for (int p = 0; p < 4; p++) {
            int e = tid + p * 256;
            int jj = e >> 4, nc = (e & 15) * 4;
            *(float4*)&vs[jj][nc] =
                *(const float4*)&V[((size_t)b * NK + j0 + jj) * D + n0 + nc];
        }
        __syncthreads();
        #pragma unroll
        for (int jj = 0; jj < 64; jj++) {
            float vv = vs[jj][tx];
            float a0 = as_[ty][jj], a1 = as_[ty + 4][jj];
            float a2 = as_[ty + 8][jj], a3 = as_[ty + 12][jj];
            acc[0] += a0 * vv;  ssum[0] += a0;
            acc[1] += a1 * vv;  ssum[1] += a1;
            acc[2] += a2 * vv;  ssum[2] += a2;
            acc[3] += a3 * vv;  ssum[3] += a3;
        }
        __syncthreads();
    }
    #pragma unroll
    for (int r = 0; r < 4; r++)
        upd[((size_t)b * S + ty + r * 4) * D + n0 + tx] = acc[r] / ssum[r];
}

// encoder self-attention; reads QKV split-K partials directly
__global__ __launch_bounds__(256)
void enc_attn_kernel(const float* __restrict__ QKVpart,
                     __half* __restrict__ Oh, __half* __restrict__ Ol)
{
    int b = blockIdx.x >> 3, h = blockIdx.x & 7;
    __shared__ float qs[16][65], ks[16][65], vs[16][65];
    __shared__ float p[16][17];
    int tid = threadIdx.x;
    int i = tid >> 4, jj = tid & 15;
    {
        int r = tid >> 4, c = (tid & 15) * 4;
        size_t base = ((size_t)b * S + r) * QKV3 + h * DH + c;
        float4 vq = *(const float4*)&QKVpart[base];
        float4 vk = *(const float4*)&QKVpart[base + HD];
        float4 vv = *(const float4*)&QKVpart[base + 2 * HD];
        #pragma unroll
        for (int sp = 1; sp < 4; sp++) {
            size_t o = (size_t)sp * MS * QKV3 + base;
            float4 w;
            w = *(const float4*)&QKVpart[o];
            vq.x += w.x; vq.y += w.y; vq.z += w.z; vq.w += w.w;
            w = *(const float4*)&QKVpart[o + HD];
            vk.x += w.x; vk.y += w.y; vk.z += w.z; vk.w += w.w;
            w = *(const float4*)&QKVpart[o + 2 * HD];
            vv.x += w.x; vv.y += w.y; vv.z += w.z; vv.w += w.w;
        }
        qs[r][c] = vq.x; qs[r][c+1] = vq.y; qs[r][c+2] = vq.z; qs[r][c+3] = vq.w;
        ks[r][c] = vk.x; ks[r][c+1] = vk.y; ks[r][c+2] = vk.z; ks[r][c+3] = vk.w;
        vs[r][c] = vv.x; vs[r][c+1] = vv.y; vs[r][c+2] = vv.z; vs[r][c+3] = vv.w;
    }
    __syncthreads();
    float s = 0.f;
    #pragma unroll
    for (int d = 0; d < DH; d++) s += qs[i][d] * ks[jj][d];
    s *= 0.125f;
    p[i][jj] = s;
    __syncthreads();
    float m = -1e30f;
    #pragma unroll
    for (int t2 = 0; t2 < 16; t2++) m = fmaxf(m, p[i][t2]);
    __syncthreads();
    float e = expf(s - m);
    p[i][jj] = e;
    __syncthreads();
    float sum = 0.f;
    #pragma unroll
    for (int t2 = 0; t2 < 16; t2++) sum += p[i][t2];
    __syncthreads();
    p[i][jj] = e / sum;
    __syncthreads();
    int io = tid >> 4, dbase = (tid & 15) * 4;
    float o[4] = {0.f, 0.f, 0.f, 0.f};
    #pragma unroll
    for (int t2 = 0; t2 < 16; t2++) {
        float pp = p[io][t2];
        o[0] += pp * vs[t2][dbase + 0];
        o[1] += pp * vs[t2][dbase + 1];
        o[2] += pp * vs[t2][dbase + 2];
        o[3] += pp * vs[t2][dbase + 3];
    }
    size_t base = ((size_t)b * S + io) * HD + h * DH + dbase;
    #pragma unroll
    for (int c = 0; c < 4; c++) {
        __half hb = __float2half_rn(o[c]);
        Oh[base + c] = hb;
        Ol[base + c] = __float2half_rn(o[c] - __half2float(hb));
    }
}

// per-(b,i) key-sum of attn (for the output map only)
__global__ __launch_bounds__(256)
void attn_sums_kernel(const float* __restrict__ attn, float* __restrict__ sums)
{
    int row = blockIdx.x;
    const float4* p = (const float4*)(attn + (size_t)row * NK);
    int tid = threadIdx.x;
    float4 v = p[tid];
    float s = v.x + v.y + v.z + v.w;
    __shared__ float sa[8];
    #pragma unroll
    for (int o = 16; o > 0; o >>= 1) s += __shfl_down_sync(0xffffffffu, s, o);
    int w = tid >> 5, l = tid & 31;
    if (l == 0) sa[w] = s;
    __syncthreads();
    if (tid == 0) {
        float ts = 0.f;
        #pragma unroll
        for (int k = 0; k < 8; k++) ts += sa[k];
        sums[row] = ts;
    }
}

__global__ void write_attn_kernel(const float* __restrict__ attn,
                                  const float* __restrict__ sums,
                                  float* __restrict__ out)
{
    int t = blockIdx.x * blockDim.x + threadIdx.x;
    if (t >= B * NK * S) return;
    int i = t & 15, j = (t >> 4) & (NK - 1), b = t >> 14;
    out[t] = attn[((size_t)b * S + i) * NK + j] / sums[b * S + i];
}

// ----------------------------------------------------------------------------
// Host orchestration
// ----------------------------------------------------------------------------
extern "C" void kernel_launch(void* const* d_in, const int* in_sizes, int n_in,
                              void* d_out, int out_size)
{
    const float* x       = (const float*)d_in[0];
    const float* noise   = (const float*)d_in[1];
    const float* init_mu = (const float*)d_in[2];
    const float* init_ls = (const float*)d_in[3];
    const float* Wk      = (const float*)d_in[4];
    const float* Wv      = (const float*)d_in[5];
    const float* Wq      = (const float*)d_in[6];
    const float* ni_g    = (const float*)d_in[7];
    const float* ni_b    = (const float*)d_in[8];
    const float* ns_g    = (const float*)d_in[9];
    const float* ns_b    = (const float*)d_in[10];
    const float* nica_g  = (const float*)d_in[11];
    const float* nica_b  = (const float*)d_in[12];
    const float* ln1_g   = (const float*)d_in[13];
    const float* ln1_b   = (const float*)d_in[14];
    const float* Wq_a    = (const float*)d_in[15];
    const float* Wk_a    = (const float*)d_in[16];
    const float* Wv_a    = (const float*)d_in[17];
    const float* Wo_a    = (const float*)d_in[18];
    const float* ln2_g   = (const float*)d_in[19];
    const float* ln2_b   = (const float*)d_in[20];
    const float* W1      = (const float*)d_in[21];
    const float* W2      = (const float*)d_in[22];
    const float* lnf_g   = (const float*)d_in[23];
    const float* lnf_b   = (const float*)d_in[24];

    __half *xnh, *xnl, *wkh, *wkl, *wvh, *wvl, *wqh, *wql;
    __half *wqkh, *wqkl, *woh, *wol, *w1h, *w1l, *w2h, *w2l;
    __half *qnh, *qnl, *abh, *abl, *fbh, *fbl, *innh, *innl, *oah, *oal;
    float *kb, *vb, *slots, *attn, *sums, *upd, *hb, *part;
    cudaGetSymbolAddress((void**)&xnh,  g_xnh);  cudaGetSymbolAddress((void**)&xnl,  g_xnl);
    cudaGetSymbolAddress((void**)&wkh,  g_wkh);  cudaGetSymbolAddress((void**)&wkl,  g_wkl);
    cudaGetSymbolAddress((void**)&wvh,  g_wvh);  cudaGetSymbolAddress((void**)&wvl,  g_wvl);
    cudaGetSymbolAddress((void**)&wqh,  g_wqh);  cudaGetSymbolAddress((void**)&wql,  g_wql);
    cudaGetSymbolAddress((void**)&wqkh, g_wqkh); cudaGetSymbolAddress((void**)&wqkl, g_wqkl);
    cudaGetSymbolAddress((void**)&woh,  g_woh);  cudaGetSymbolAddress((void**)&wol,  g_wol);
    cudaGetSymbolAddress((void**)&w1h,  g_w1h);  cudaGetSymbolAddress((void**)&w1l,  g_w1l);
    cudaGetSymbolAddress((void**)&w2h,  g_w2h);  cudaGetSymbolAddress((void**)&w2l,  g_w2l);
    cudaGetSymbolAddress((void**)&qnh,  g_qnh);  cudaGetSymbolAddress((void**)&qnl,  g_qnl);
    cudaGetSymbolAddress((void**)&abh,  g_abh);  cudaGetSymbolAddress((void**)&abl,  g_abl);
    cudaGetSymbolAddress((void**)&fbh,  g_fbh);  cudaGetSymbolAddress((void**)&fbl,  g_fbl);
    cudaGetSymbolAddress((void**)&innh, g_innh); cudaGetSymbolAddress((void**)&innl, g_innl);
    cudaGetSymbolAddress((void**)&oah,  g_oah);  cudaGetSymbolAddress((void**)&oal,  g_oal);
    cudaGetSymbolAddress((void**)&kb,   g_k);
    cudaGetSymbolAddress((void**)&vb,   g_v);
    cudaGetSymbolAddress((void**)&slots,g_slots);
    cudaGetSymbolAddress((void**)&attn, g_attn);
    cudaGetSymbolAddress((void**)&sums, g_sums);
    cudaGetSymbolAddress((void**)&upd,  g_upd);
    cudaGetSymbolAddress((void**)&hb,   g_h);
    cudaGetSymbolAddress((void**)&part, g_part);

    cudaFuncSetAttribute(hgemm_hilo, cudaFuncAttributeMaxDynamicSharedMemorySize, HG_SMEM);
    cudaFuncSetAttribute(hgemm_dual, cudaFuncAttributeMaxDynamicSharedMemorySize, DUAL2_SMEM);
    cudaFuncSetAttribute(hgemm_glu,  cudaFuncAttributeMaxDynamicSharedMemorySize, DUAL2_SMEM);

    // ---- precompute ----
    ln_split_kernel<<<B * NK, 256>>>(x, xnh, xnl, ni_g, ni_b);
    wsplit_kernel<<<dim3(D / 32, D / 32), 256>>>(Wk, wkh, wkl, D, D, 0);
    wsplit_kernel<<<dim3(D / 32, D / 32), 256>>>(Wv, wvh, wvl, D, D, 0);
    wsplit_kernel<<<dim3(D / 32, D / 32), 256>>>(Wq, wqh, wql, D, D, 0);
    wsplit_kernel<<<dim3(HD / 32, D / 32), 256>>>(Wq_a, wqkh, wqkl, D, HD, 0);
    wsplit_kernel<<<dim3(HD / 32, D / 32), 256>>>(Wk_a, wqkh, wqkl, D, HD, HD);
    wsplit_kernel<<<dim3(HD / 32, D / 32), 256>>>(Wv_a, wqkh, wqkl, D, HD, 2 * HD);
    wsplit_kernel<<<dim3(D / 32, HD / 32), 256>>>(Wo_a, woh, wol, HD, D, 0);
    wsplit_kernel<<<dim3((2 * INNER) / 32, D / 32), 256>>>(W1, w1h, w1l, D, 2 * INNER, 0);
    wsplit_kernel<<<dim3(D / 32, INNER / 32), 256>>>(W2, w2h, w2l, INNER, D, 0);
    hgemm_dual<<<dim3(D / 128, (B * NK) / 128), 256, DUAL2_SMEM>>>(
        xnh, xnl, wkh, wkl, wvh, wvl, kb, vb, B * NK, D, D);
    init_slots_kernel<<<(MS * D + 255) / 256, 256>>>(noise, init_mu, init_ls, slots);
    ln_split_kernel<<<MS, 256>>>(slots, qnh, qnl, ns_g, ns_b);

    // ---- 4 slot-attention steps (11 launches each) ----
    for (int it = 0; it < N_STEPS; it++) {
        hgemm_hilo<<<dim3(D / 128, MS / 128, 4), 256, HG_SMEM>>>(qnh, qnl, wqh, wql,
                                                                 part, MS, D, D);
        dots_softmax_kernel<<<dim3(NK / 64, B), 256>>>(part, kb, attn);
        updates_kernel<<<dim3(D / 64, B), 256>>>(attn, vb, upd);
        ln_dual_kernel<<<MS, 256>>>(slots, upd, hb, nica_g, nica_b,
                                    ln1_g, ln1_b, abh, abl);
        hgemm_hilo<<<dim3(QKV3 / 128, MS / 128, 4), 256, HG_SMEM>>>(abh, abl, wqkh, wqkl,
                                                                    part, MS, QKV3, D);
        enc_attn_kernel<<<B * H, 256>>>(part, oah, oal);
        hgemm_hilo<<<dim3(D / 128, MS / 128, 4), 256, HG_SMEM>>>(oah, oal, woh, wol,
                                                                 part, MS, D, HD);
        ln_split_red_kernel<<<MS, 256>>>(part, hb, ln2_g, ln2_b, fbh, fbl);
        hgemm_glu<<<dim3(INNER / 128, MS / 128), 256, DUAL2_SMEM>>>(fbh, fbl, w1h, w1l,
                                                                    innh, innl, MS);
        hgemm_hilo<<<dim3(D / 128, MS / 128, 4), 256, HG_SMEM>>>(innh, innl, w2h, w2l,
                                                                 part, MS, D, INNER);
        ln_red_dual_kernel<<<MS, 256>>>(part, hb, slots, lnf_g, lnf_b,
                                        ns_g, ns_b, qnh, qnl);
    }

    // ---- outputs: slots [32,16,768], then attn_map [32,1024,16] ----
    float* out = (float*)d_out;
    cudaMemcpyAsync(out, slots, (size_t)MS * D * sizeof(float),
                    cudaMemcpyDeviceToDevice);
    attn_sums_kernel<<<MS, 256>>>(attn, sums);
    write_attn_kernel<<<(B * NK * S + 255) / 256, 256>>>(attn, sums,
                                                         out + (size_t)MS * D);
}